// round 8
// baseline (speedup 1.0000x reference)
#include <cuda_runtime.h>
#include <cuda_bf16.h>
#include <cuda_fp16.h>
#include <math.h>
#include <stdint.h>

#define NB 2
#define SEQ 1024
#define NTOK (NB * SEQ)          // 2048
#define DEMB 1024
#define NHEAD 16
#define DH 64
#define DFF 4096
#define NVOCAB 32000
#define NLAYER 6

// -------- scratch (device globals; no allocation allowed) --------
__device__ float g_x [NTOK * DEMB];
__device__ float g_h1[NTOK * DEMB];
__device__ float g_h2[NTOK * DEMB];
__device__ float g_t [NTOK * DEMB];
__device__ float g_q [NTOK * DEMB];
__device__ float g_k [NTOK * DEMB];
__device__ float g_v [NTOK * DEMB];
__device__ float g_ff[NTOK * DFF];
// split-fp16 staging (uint16 = raw fp16 bits)
__device__ uint16_t g_ah [NTOK * DFF];             // A hi (max 2048x4096)
__device__ uint16_t g_al [NTOK * DFF];             // A lo
__device__ uint16_t g_bth[(size_t)NVOCAB * DEMB];  // B^T hi (max 32000x1024)
__device__ uint16_t g_btl[(size_t)NVOCAB * DEMB];  // B^T lo

// ---------------- split-bf16 helper (flash attention only) ----------------
__device__ __forceinline__ void split2(float x0, float x1, uint32_t& hi, uint32_t& lo) {
    uint32_t u0 = __float_as_uint(x0), u1 = __float_as_uint(x1);
    hi = __byte_perm(u0, u1, 0x7632);
    float l0 = x0 - __uint_as_float(u0 & 0xffff0000u);
    float l1 = x1 - __uint_as_float(u1 & 0xffff0000u);
    asm("cvt.rn.bf16x2.f32 %0, %1, %2;" : "=r"(lo) : "f"(l1), "f"(l0));
}

// ---------------- split-fp16 helper: x = hi(fp16 RN) + lo(fp16), |lo|<=2^-11|x| ----------------
__device__ __forceinline__ void split2h(float x0, float x1, uint32_t& hi, uint32_t& lo) {
    __half h0 = __float2half_rn(x0), h1 = __float2half_rn(x1);
    float r0 = x0 - __half2float(h0);
    float r1 = x1 - __half2float(h1);
    __half l0 = __float2half_rn(r0), l1 = __float2half_rn(r1);
    hi = (uint32_t)(*(uint16_t*)&h0) | ((uint32_t)(*(uint16_t*)&h1) << 16);
    lo = (uint32_t)(*(uint16_t*)&l0) | ((uint32_t)(*(uint16_t*)&l1) << 16);
}

// bf16 MMA, fp32 acc (flash attention)
#define MMA(acc, a0, a1, a2, a3, b0, b1)                                        \
    asm("mma.sync.aligned.m16n8k16.row.col.f32.bf16.bf16.f32 "                  \
        "{%0,%1,%2,%3}, {%4,%5,%6,%7}, {%8,%9}, {%0,%1,%2,%3};"                 \
        : "+f"((acc)[0]), "+f"((acc)[1]), "+f"((acc)[2]), "+f"((acc)[3])        \
        : "r"(a0), "r"(a1), "r"(a2), "r"(a3), "r"(b0), "r"(b1))

// fp16 MMA, fp32 acc (hi*hi pass)
#define MMAF(acc, a0, a1, a2, a3, b0, b1)                                       \
    asm("mma.sync.aligned.m16n8k16.row.col.f32.f16.f16.f32 "                    \
        "{%0,%1,%2,%3}, {%4,%5,%6,%7}, {%8,%9}, {%0,%1,%2,%3};"                 \
        : "+f"((acc)[0]), "+f"((acc)[1]), "+f"((acc)[2]), "+f"((acc)[3])        \
        : "r"(a0), "r"(a1), "r"(a2), "r"(a3), "r"(b0), "r"(b1))

// fp16 MMA, fp16 acc (cross passes, 2x rate expected)
#define MMAH(accp, a0, a1, a2, a3, b0, b1)                                      \
    asm("mma.sync.aligned.m16n8k16.row.col.f16.f16.f16.f16 "                    \
        "{%0,%1}, {%2,%3,%4,%5}, {%6,%7}, {%0,%1};"                             \
        : "+r"((accp)[0]), "+r"((accp)[1])                                      \
        : "r"(a0), "r"(a1), "r"(a2), "r"(a3), "r"(b0), "r"(b1))

#define CP_ASYNC16(dst, src) \
    asm volatile("cp.async.cg.shared.global [%0], [%1], 16;" :: "r"(dst), "l"(src))
#define CP_COMMIT() asm volatile("cp.async.commit_group;")
#define CP_WAIT(n)  asm volatile("cp.async.wait_group %0;" :: "n"(n))

__device__ __forceinline__ uint32_t smem_u32(const void* p) {
    uint32_t a;
    asm("{ .reg .u64 t; cvta.to.shared.u64 t, %1; cvt.u32.u64 %0, t; }" : "=r"(a) : "l"(p));
    return a;
}

// ---------------- elementwise fp32 -> split-fp16 (hi/lo) ----------------
__global__ __launch_bounds__(256) void cvt_split(const float* __restrict__ in,
                                                 uint16_t* __restrict__ hi,
                                                 uint16_t* __restrict__ lo) {
    int i4 = (blockIdx.x * 256 + threadIdx.x) * 4;
    float4 v = *(const float4*)(in + i4);
    uint32_t h0, l0, h1, l1;
    split2h(v.x, v.y, h0, l0);
    split2h(v.z, v.w, h1, l1);
    *(uint32_t*)(hi + i4) = h0; *(uint32_t*)(hi + i4 + 2) = h1;
    *(uint32_t*)(lo + i4) = l0; *(uint32_t*)(lo + i4 + 2) = l1;
}

// ---------------- transpose + split: in[K][N] -> hiT/loT [N][K] ----------------
__global__ __launch_bounds__(256) void cvt_trans(const float* __restrict__ in,
                                                 uint16_t* __restrict__ hiT,
                                                 uint16_t* __restrict__ loT,
                                                 int K, int N) {
    __shared__ float t[32][33];
    int n0 = blockIdx.x * 32, k0 = blockIdx.y * 32;
    int tx = threadIdx.x & 31, ty = threadIdx.x >> 5;   // 32x8
#pragma unroll
    for (int i = 0; i < 32; i += 8)
        t[ty + i][tx] = in[(size_t)(k0 + ty + i) * N + n0 + tx];
    __syncthreads();
#pragma unroll
    for (int i = 0; i < 32; i += 8) {
        float x = t[tx][ty + i];                         // k = k0+tx, n = n0+ty+i
        __half h = __float2half_rn(x);
        __half l = __float2half_rn(x - __half2float(h));
        size_t o = (size_t)(n0 + ty + i) * K + k0 + tx;
        hiT[o] = *(uint16_t*)&h;
        loT[o] = *(uint16_t*)&l;
    }
}

// ============ cp.async pipelined split-fp16 HMMA GEMM: C = A@B^T(pre-split) + bias ============
// hi*hi -> fp32 acc; hi*lo + lo*hi -> fp16 acc (2x rate). grid=(M/128,N/128), 2 CTAs/SM.
#define STRIDE 20                         // words per smem row (32 k + pad)
#define TILE_B (128 * STRIDE * 4)         // 10240 bytes per tile
#define BUF_B  (4 * TILE_B)               // Ah,Al,Bh,Bl = 40960 bytes
#define GEMM_SMEM (2 * BUF_B)             // 81920

__global__ __launch_bounds__(256, 2) void gemm_cp(const uint16_t* __restrict__ Ahg,
                                                  const uint16_t* __restrict__ Alg,
                                                  const uint16_t* __restrict__ Bth,
                                                  const uint16_t* __restrict__ Btl,
                                                  const float* __restrict__ bias,
                                                  float* __restrict__ C,
                                                  int N, int K, int relu) {
    extern __shared__ uint32_t sh[];
    uint32_t sb = smem_u32(sh);
    int tid = threadIdx.x, wid = tid >> 5, lane = tid & 31;
    int bm = blockIdx.x * 128, bn = blockIdx.y * 128;
    int wm = (wid >> 2) * 64, wn = (wid & 3) * 32;
    int r = lane >> 2, c = lane & 3;

#define ISSUE(kt, buf)                                                          \
    {                                                                           \
        int k0i = (kt) << 5;                                                    \
        _Pragma("unroll")                                                       \
        for (int p = 0; p < 2; p++) {                                           \
            int idx = tid + p * 256;                                            \
            int row = idx >> 2, q = idx & 3;                                    \
            size_t ao = (size_t)(bm + row) * K + k0i + q * 8;                   \
            size_t bo = (size_t)(bn + row) * K + k0i + q * 8;                   \
            uint32_t d = sb + (buf) * BUF_B + row * (STRIDE * 4) + q * 16;      \
            CP_ASYNC16(d,              Ahg + ao);                               \
            CP_ASYNC16(d + TILE_B,     Alg + ao);                               \
            CP_ASYNC16(d + 2 * TILE_B, Bth + bo);                               \
            CP_ASYNC16(d + 3 * TILE_B, Btl + bo);                               \
        }                                                                       \
        CP_COMMIT();                                                            \
    }

    float accH[4][4][4] = {};
    uint32_t accC[4][4][2];
#pragma unroll
    for (int i = 0; i < 4; i++)
#pragma unroll
        for (int j = 0; j < 4; j++) { accC[i][j][0] = 0u; accC[i][j][1] = 0u; }

    int KT = K >> 5;
    ISSUE(0, 0);
    ISSUE(1, 1);

    for (int kt = 0; kt < KT; kt++) {
        if (kt + 1 < KT) { CP_WAIT(1); } else { CP_WAIT(0); }
        __syncthreads();
        uint32_t* Ah = sh + (kt & 1) * (BUF_B / 4);
        uint32_t* Al = Ah + 2560;
        uint32_t* Bh = Al + 2560;
        uint32_t* Bl = Bh + 2560;
#pragma unroll
        for (int s = 0; s < 2; s++) {
            uint32_t bh[4][2], bl[4][2];
#pragma unroll
            for (int j = 0; j < 4; j++) {
                int o = (wn + 8 * j + r) * STRIDE + s * 8 + c;
                bh[j][0] = Bh[o]; bh[j][1] = Bh[o + 4];
                bl[j][0] = Bl[o]; bl[j][1] = Bl[o + 4];
            }
#pragma unroll
            for (int i = 0; i < 4; i++) {
                int o0 = (wm + 16 * i + r) * STRIDE + s * 8 + c;
                int o1 = o0 + 8 * STRIDE;
                uint32_t ah0 = Ah[o0], ah1 = Ah[o1], ah2 = Ah[o0 + 4], ah3 = Ah[o1 + 4];
                uint32_t al0 = Al[o0], al1 = Al[o1], al2 = Al[o0 + 4], al3 = Al[o1 + 4];
#pragma unroll
                for (int j = 0; j < 4; j++) {
                    MMAF(accH[i][j], ah0, ah1, ah2, ah3, bh[j][0], bh[j][1]);   // hi*hi, fp32 acc
                    MMAH(accC[i][j], ah0, ah1, ah2, ah3, bl[j][0], bl[j][1]);   // hi*lo, fp16 acc
                    MMAH(accC[i][j], al0, al1, al2, al3, bh[j][0], bh[j][1]);   // lo*hi, fp16 acc
                }
            }
        }
        if (kt + 2 < KT) {
            __syncthreads();               // all compute(kt) done before overwriting its buffer
            ISSUE(kt + 2, kt & 1);
        }
    }

#pragma unroll
    for (int i = 0; i < 4; i++) {
#pragma unroll
        for (int j = 0; j < 4; j++) {
            int col = bn + wn + 8 * j + 2 * c;
            int row0 = bm + wm + 16 * i + r;
            float2 c0 = __half22float2(*(__half2*)&accC[i][j][0]);
            float2 c1 = __half22float2(*(__half2*)&accC[i][j][1]);
            float b0 = bias[col], b1 = bias[col + 1];
            float v0 = accH[i][j][0] + c0.x + b0, v1 = accH[i][j][1] + c0.y + b1;
            float v2 = accH[i][j][2] + c1.x + b0, v3 = accH[i][j][3] + c1.y + b1;
            if (relu) {
                v0 = fmaxf(v0, 0.0f); v1 = fmaxf(v1, 0.0f);
                v2 = fmaxf(v2, 0.0f); v3 = fmaxf(v3, 0.0f);
            }
            *(float2*)(C + (size_t)row0 * N + col) = make_float2(v0, v1);
            *(float2*)(C + (size_t)(row0 + 8) * N + col) = make_float2(v2, v3);
        }
    }
}

// ============ fused flash attention (split-bf16 HMMA, online softmax, 1e-19 mask quirk) ============
#define FA_SMEM_WORDS (4608 + 4608 + 4352 + 4352)
#define FA_SMEM_BYTES (FA_SMEM_WORDS * 4)
__global__ __launch_bounds__(256) void flash_attn(const float* __restrict__ Qg,
                                                  const float* __restrict__ Kg,
                                                  const float* __restrict__ Vg,
                                                  float* __restrict__ Og, int causal) {
    extern __shared__ uint32_t sm[];
    uint32_t* Kh = sm;
    uint32_t* Kl = sm + 4608;
    uint32_t* Vh = sm + 9216;
    uint32_t* Vl = sm + 13568;
    int tid = threadIdx.x, wid = tid >> 5, lane = tid & 31;
    int r = lane >> 2, c = lane & 3;
    int b = blockIdx.y >> 4, h = blockIdx.y & 15;
    const float* Qb = Qg + (size_t)b * SEQ * DEMB + h * DH;
    const float* Kb = Kg + (size_t)b * SEQ * DEMB + h * DH;
    const float* Vb = Vg + (size_t)b * SEQ * DEMB + h * DH;
    int q0 = blockIdx.x * 128;
    int grow = q0 + wid * 16 + r;

    uint32_t qh[4][4], ql[4][4];
#pragma unroll
    for (int s = 0; s < 4; s++) {
        const float* q0p = Qb + (size_t)grow * DEMB + s * 16;
        const float* q1p = q0p + 8 * DEMB;
        float2 v0 = *(const float2*)(q0p + 2 * c);
        float2 v1 = *(const float2*)(q1p + 2 * c);
        float2 v2 = *(const float2*)(q0p + 2 * c + 8);
        float2 v3 = *(const float2*)(q1p + 2 * c + 8);
        split2(v0.x, v0.y, qh[s][0], ql[s][0]);
        split2(v1.x, v1.y, qh[s][1], ql[s][1]);
        split2(v2.x, v2.y, qh[s][2], ql[s][2]);
        split2(v3.x, v3.y, qh[s][3], ql[s][3]);
    }

    float oacc[8][4] = {};
    float m0 = -1e30f, m1 = -1e30f, l0 = 0.0f, l1 = 0.0f;

    for (int kt = 0; kt < SEQ / 128; kt++) {
        int k0 = kt * 128;
        __syncthreads();
#pragma unroll
        for (int p = 0; p < 16; p++) {
            int idx = tid + p * 256;
            int row = idx >> 5, kp = idx & 31;
            float2 kv = *(const float2*)(Kb + (size_t)(k0 + row) * DEMB + kp * 2);
            uint32_t hh, ll; split2(kv.x, kv.y, hh, ll);
            Kh[row * 36 + kp] = hh; Kl[row * 36 + kp] = ll;
        }
#pragma unroll
        for (int p = 0; p < 16; p++) {
            int idx = tid + p * 256;
            int d = idx & 63, kp = idx >> 6;
            float x0 = Vb[(size_t)(k0 + kp * 2) * DEMB + d];
            float x1 = Vb[(size_t)(k0 + kp * 2 + 1) * DEMB + d];
            uint32_t hh, ll; split2(x0, x1, hh, ll);
            Vh[d * 68 + kp] = hh; Vl[d * 68 + kp] = ll;
        }
        __syncthreads();

        float sacc[16][4];
#pragma unroll
        for (int j = 0; j < 16; j++) { sacc[j][0] = sacc[j][1] = sacc[j][2] = sacc[j][3] = 0.0f; }
#pragma unroll
        for (int j = 0; j < 16; j++) {
#pragma unroll
            for (int s = 0; s < 4; s++) {
                int o = (8 * j + r) * 36 + 8 * s + c;
                uint32_t kh0 = Kh[o], kh1 = Kh[o + 4];
                uint32_t kl0 = Kl[o], kl1 = Kl[o + 4];
                MMA(sacc[j], qh[s][0], qh[s][1], qh[s][2], qh[s][3], kh0, kh1);
                MMA(sacc[j], qh[s][0], qh[s][1], qh[s][2], qh[s][3], kl0, kl1);
                MMA(sacc[j], ql[s][0], ql[s][1], ql[s][2], ql[s][3], kh0, kh1);
            }
        }
        float tm0 = -1e30f, tm1 = -1e30f;
#pragma unroll
        for (int j = 0; j < 16; j++) {
            int col = k0 + 8 * j + 2 * c;
            float v0 = sacc[j][0] * 0.125f, v1 = sacc[j][1] * 0.125f;
            float v2 = sacc[j][2] * 0.125f, v3 = sacc[j][3] * 0.125f;
            if (causal) {
                if (col     > grow)     v0 = 1e-19f;
                if (col + 1 > grow)     v1 = 1e-19f;
                if (col     > grow + 8) v2 = 1e-19f;
                if (col + 1 > grow + 8) v3 = 1e-19f;
            }
            sacc[j][0] = v0; sacc[j][1] = v1; sacc[j][2] = v2; sacc[j][3] = v3;
            tm0 = fmaxf(tm0, fmaxf(v0, v1));
            tm1 = fmaxf(tm1, fmaxf(v2, v3));
        }
        tm0 = fmaxf(tm0, __shfl_xor_sync(0xffffffffu, tm0, 1));
        tm0 = fmaxf(tm0, __shfl_xor_sync(0xffffffffu, tm0, 2));
        tm1 = fmaxf(tm1, __shfl_xor_sync(0xffffffffu, tm1, 1));
        tm1 = fmaxf(tm1, __shfl_xor_sync(0xffffffffu, tm1, 2));
        float mn0 = fmaxf(m0, tm0), mn1 = fmaxf(m1, tm1);
        float sc0 = __expf(m0 - mn0), sc1 = __expf(m1 - mn1);
        m0 = mn0; m1 = mn1;
        float rs0 = 0.0f, rs1 = 0.0f;
#pragma unroll
        for (int j = 0; j < 16; j++) {
            float p0 = __expf(sacc[j][0] - m0), p1 = __expf(sacc[j][1] - m0);
            float p2 = __expf(sacc[j][2] - m1), p3 = __expf(sacc[j][3] - m1);
            sacc[j][0] = p0; sacc[j][1] = p1; sacc[j][2] = p2; sacc[j][3] = p3;
            rs0 += p0 + p1; rs1 += p2 + p3;
        }
        rs0 += __shfl_xor_sync(0xffffffffu, rs0, 1);
        rs0 += __shfl_xor_sync(0xffffffffu, rs0, 2);
        rs1 += __shfl_xor_sync(0xffffffffu, rs1, 1);
        rs1 += __shfl_xor_sync(0xffffffffu, rs1, 2);
        l0 = l0 * sc0 + rs0; l1 = l1 * sc1 + rs1;
#pragma unroll
        for (int j2 = 0; j2 < 8; j2++) {
            oacc[j2][0] *= sc0; oacc[j2][1] *= sc0;
            oacc[j2][2] *= sc1; oacc[j2][3] *= sc1;
        }
#pragma unroll
        for (int s2 = 0; s2 < 8; s2++) {
            uint32_t a0h, a0l, a1h, a1l, a2h, a2l, a3h, a3l;
            split2(sacc[2 * s2][0],     sacc[2 * s2][1],     a0h, a0l);
            split2(sacc[2 * s2][2],     sacc[2 * s2][3],     a1h, a1l);
            split2(sacc[2 * s2 + 1][0], sacc[2 * s2 + 1][1], a2h, a2l);
            split2(sacc[2 * s2 + 1][2], sacc[2 * s2 + 1][3], a3h, a3l);
#pragma unroll
            for (int j2 = 0; j2 < 8; j2++) {
                int o = (8 * j2 + r) * 68 + 8 * s2 + c;
                uint32_t vh0 = Vh[o], vh1 = Vh[o + 4];
                uint32_t vl0 = Vl[o], vl1 = Vl[o + 4];
                MMA(oacc[j2], a0h, a1h, a2h, a3h, vh0, vh1);
                MMA(oacc[j2], a0h, a1h, a2h, a3h, vl0, vl1);
                MMA(oacc[j2], a0l, a1l, a2l, a3l, vh0, vh1);
            }
        }
    }
    float i0 = 1.0f / l0, i1 = 1.0f / l1;
#pragma unroll
    for (int j2 = 0; j2 < 8; j2++) {
        float* op = Og + (size_t)(b * SEQ + grow) * DEMB + h * DH + 8 * j2 + 2 * c;
        *(float2*)op = make_float2(oacc[j2][0] * i0, oacc[j2][1] * i0);
        *(float2*)(op + 8 * DEMB) = make_float2(oacc[j2][2] * i1, oacc[j2][3] * i1);
    }
}

// ---------------- embedding + positional encoding ----------------
__global__ __launch_bounds__(256) void embed_kernel(const int* __restrict__ ids,
                                                    const float* __restrict__ emb,
                                                    float* __restrict__ X) {
    int t = blockIdx.x;
    int pos = t & (SEQ - 1);
    int id = ids[t];
    int d0 = threadIdx.x * 4;
    float4 e4 = *(const float4*)(emb + (size_t)id * DEMB + d0);
    float ev[4] = {e4.x, e4.y, e4.z, e4.w};
    float ov[4];
#pragma unroll
    for (int j = 0; j < 4; j++) {
        int d = d0 + j;
        float ang = (float)pos * powf(10000.0f, -2.0f * (float)d / (float)DEMB);
        float pe = ((d & 1) == 0) ? sinf(ang) : cosf(ang);
        ov[j] = ev[j] * 32.0f + pe;
    }
    *(float4*)(X + (size_t)t * DEMB + d0) = make_float4(ov[0], ov[1], ov[2], ov[3]);
}

// ---------------- fused q/k/v per-head projection (grid.z selects) ----------------
__global__ __launch_bounds__(256) void proj_head3(
        const float* __restrict__ X0, const float* __restrict__ X1, const float* __restrict__ X2,
        const float* __restrict__ W0, const float* __restrict__ W1, const float* __restrict__ W2,
        float* __restrict__ O0, float* __restrict__ O1, float* __restrict__ O2) {
    const float* X; const float* W; float* O;
    if (blockIdx.z == 0)      { X = X0; W = W0; O = O0; }
    else if (blockIdx.z == 1) { X = X1; W = W1; O = O1; }
    else                      { X = X2; W = W2; O = O2; }
    __shared__ float Xs[64][64];
    __shared__ float Ws[64][64];
    int tid = threadIdx.x;
    int h = blockIdx.y;
    int t0 = blockIdx.x * 64;
#pragma unroll
    for (int r = 0; r < 4; r++) {
        int idx = tid + r * 256;
        int a = idx >> 4;
        int c4 = (idx & 15) << 2;
        float4 xv = *(const float4*)(X + (size_t)(t0 + a) * DEMB + h * DH + c4);
        Xs[c4 + 0][a] = xv.x; Xs[c4 + 1][a] = xv.y; Xs[c4 + 2][a] = xv.z; Xs[c4 + 3][a] = xv.w;
        float4 wv = *(const float4*)(W + a * DH + c4);
        *(float4*)&Ws[a][c4] = wv;
    }
    __syncthreads();
    int tx = tid & 15, ty = tid >> 4;
    float acc[4][4] = {};
#pragma unroll
    for (int d = 0; d < 64; d++) {
        float4 a4 = *(float4*)&Xs[d][ty * 4];
        float4 w4 = *(float4*)&Ws[d][tx * 4];
        float av[4] = {a4.x, a4.y, a4.z, a4.w};
        float wv[4] = {w4.x, w4.y, w4.z, w4.w};
#pragma unroll
        for (int i = 0; i < 4; i++)
#pragma unroll
            for (int j = 0; j < 4; j++) acc[i][j] = fmaf(av[i], wv[j], acc[i][j]);
    }
#pragma unroll
    for (int i = 0; i < 4; i++) {
        float4 o = make_float4(acc[i][0], acc[i][1], acc[i][2], acc[i][3]);
        *(float4*)(O + (size_t)(t0 + ty * 4 + i) * DEMB + h * DH + tx * 4) = o;
    }
}

// ---------------- residual add + layernorm: one warp per row, shuffle-only ----------------
__global__ __launch_bounds__(256) void add_ln(const float* __restrict__ A, const float* __restrict__ B,
                                              const float* __restrict__ g, const float* __restrict__ be,
                                              float* __restrict__ O) {
    int lane = threadIdx.x & 31, wid = threadIdx.x >> 5;
    int row = blockIdx.x * 8 + wid;
    size_t base = (size_t)row * DEMB;
    float4 v[8];
    float s1 = 0.0f, s2 = 0.0f;
#pragma unroll
    for (int p = 0; p < 8; p++) {
        float4 a = ((const float4*)(A + base))[lane + p * 32];
        float4 b = ((const float4*)(B + base))[lane + p * 32];
        float4 t = make_float4(a.x + b.x, a.y + b.y, a.z + b.z, a.w + b.w);
        v[p] = t;
        s1 += t.x + t.y + t.z + t.w;
        s2 += t.x * t.x + t.y * t.y + t.z * t.z + t.w * t.w;
    }
#pragma unroll
    for (int o = 16; o; o >>= 1) {
        s1 += __shfl_xor_sync(0xffffffffu, s1, o);
        s2 += __shfl_xor_sync(0xffffffffu, s2, o);
    }
    float mu = s1 * (1.0f / DEMB);
    float var = s2 * (1.0f / DEMB) - mu * mu;
    float w = rsqrtf(var + 1e-5f);
#pragma unroll
    for (int p = 0; p < 8; p++) {
        float4 gg = ((const float4*)g)[lane + p * 32];
        float4 bb = ((const float4*)be)[lane + p * 32];
        float4 t = v[p];
        float4 o;
        o.x = (t.x - mu) * w * gg.x + bb.x;
        o.y = (t.y - mu) * w * gg.y + bb.y;
        o.z = (t.z - mu) * w * gg.z + bb.z;
        o.w = (t.w - mu) * w * gg.w + bb.w;
        ((float4*)(O + base))[lane + p * 32] = o;
    }
}

// ---------------- host orchestration ----------------
extern "C" void kernel_launch(void* const* d_in, const int* in_sizes, int n_in,
                              void* d_out, int out_size) {
    const int*   ids   = (const int*)  d_in[0];
    const float* enc_k = (const float*)d_in[1];
    const float* enc_v = (const float*)d_in[2];
    const float* emb   = (const float*)d_in[3];
    const float* Wq_m  = (const float*)d_in[4];
    const float* Wk_m  = (const float*)d_in[5];
    const float* Wv_m  = (const float*)d_in[6];
    const float* Wq_c  = (const float*)d_in[7];
    const float* Wk_c  = (const float*)d_in[8];
    const float* Wv_c  = (const float*)d_in[9];
    const float* ln1_g = (const float*)d_in[10];
    const float* ln1_b = (const float*)d_in[11];
    const float* ln2_g = (const float*)d_in[12];
    const float* ln2_b = (const float*)d_in[13];
    const float* ln3_g = (const float*)d_in[14];
    const float* ln3_b = (const float*)d_in[15];
    const float* W1    = (const float*)d_in[16];
    const float* b1    = (const float*)d_in[17];
    const float* W2    = (const float*)d_in[18];
    const float* b2    = (const float*)d_in[19];
    const float* Wout  = (const float*)d_in[20];
    const float* bout  = (const float*)d_in[21];
    float* out = (float*)d_out;

    float *x, *h1, *h2, *t, *q, *k, *v, *ff;
    uint16_t *ah, *al, *bth, *btl;
    cudaGetSymbolAddress((void**)&x,  g_x);
    cudaGetSymbolAddress((void**)&h1, g_h1);
    cudaGetSymbolAddress((void**)&h2, g_h2);
    cudaGetSymbolAddress((void**)&t,  g_t);
    cudaGetSymbolAddress((void**)&q,  g_q);
    cudaGetSymbolAddress((void**)&k,  g_k);
    cudaGetSymbolAddress((void**)&v,  g_v);
    cudaGetSymbolAddress((void**)&ff, g_ff);
    cudaGetSymbolAddress((void**)&ah,  g_ah);
    cudaGetSymbolAddress((void**)&al,  g_al);
    cudaGetSymbolAddress((void**)&bth, g_bth);
    cudaGetSymbolAddress((void**)&btl, g_btl);

    cudaFuncSetAttribute(flash_attn, cudaFuncAttributeMaxDynamicSharedMemorySize, FA_SMEM_BYTES);
    cudaFuncSetAttribute(gemm_cp,   cudaFuncAttributeMaxDynamicSharedMemorySize, GEMM_SMEM);

    dim3 blk(256);
    dim3 projGrid(NTOK / 64, NHEAD, 3);
    dim3 faGrid(SEQ / 128, NB * NHEAD);
    dim3 tblk(256);

    embed_kernel<<<NTOK, blk>>>(ids, emb, x);

    for (int l = 0; l < NLAYER; l++) {
        size_t wOff  = (size_t)l * DH * DH;
        size_t lnOff = (size_t)l * DEMB;
        // --- masked self-attention ---
        proj_head3<<<projGrid, blk>>>(x, x, x, Wq_m + wOff, Wk_m + wOff, Wv_m + wOff, q, k, v);
        flash_attn<<<faGrid, blk, FA_SMEM_BYTES>>>(q, k, v, t, 1);
        add_ln<<<NTOK / 8, blk>>>(t, x, ln1_g + lnOff, ln1_b + lnOff, h1);
        // --- cross-attention ---
        proj_head3<<<projGrid, blk>>>(h1, enc_k, enc_v, Wq_c + wOff, Wk_c + wOff, Wv_c + wOff, q, k, v);
        flash_attn<<<faGrid, blk, FA_SMEM_BYTES>>>(q, k, v, t, 0);
        add_ln<<<NTOK / 8, blk>>>(t, h1, ln2_g + lnOff, ln2_b + lnOff, h2);
        // --- FFN (cp.async split-fp16 HMMA, 2 CTAs/SM) ---
        cvt_split<<<(NTOK * DEMB) / 1024, blk>>>(h2, ah, al);
        cvt_trans<<<dim3(DFF / 32, DEMB / 32), tblk>>>(W1 + (size_t)l * DEMB * DFF, bth, btl, DEMB, DFF);
        gemm_cp<<<dim3(NTOK / 128, DFF / 128), blk, GEMM_SMEM>>>(
            ah, al, bth, btl, b1 + (size_t)l * DFF, ff, DFF, DEMB, 1);
        cvt_split<<<(NTOK * DFF) / 1024, blk>>>(ff, ah, al);
        cvt_trans<<<dim3(DEMB / 32, DFF / 32), tblk>>>(W2 + (size_t)l * DFF * DEMB, bth, btl, DFF, DEMB);
        gemm_cp<<<dim3(NTOK / 128, DEMB / 128), blk, GEMM_SMEM>>>(
            ah, al, bth, btl, b2 + lnOff, t, DEMB, DFF, 0);
        add_ln<<<NTOK / 8, blk>>>(t, h2, ln3_g + lnOff, ln3_b + lnOff, x);
    }

    // --- vocab projection ---
    cvt_split<<<(NTOK * DEMB) / 1024, blk>>>(x, ah, al);
    cvt_trans<<<dim3(NVOCAB / 32, DEMB / 32), tblk>>>(Wout, bth, btl, DEMB, NVOCAB);
    gemm_cp<<<dim3(NTOK / 128, NVOCAB / 128), blk, GEMM_SMEM>>>(
        ah, al, bth, btl, bout, out, NVOCAB, DEMB, 0);
}

// round 9
// speedup vs baseline: 1.2552x; 1.2552x over previous
#include <cuda_runtime.h>
#include <cuda_bf16.h>
#include <cuda_fp16.h>
#include <math.h>
#include <stdint.h>

#define NB 2
#define SEQ 1024
#define NTOK (NB * SEQ)          // 2048
#define DEMB 1024
#define NHEAD 16
#define DH 64
#define DFF 4096
#define NVOCAB 32000
#define NLAYER 6

// -------- scratch (device globals; no allocation allowed) --------
__device__ float g_x [NTOK * DEMB];
__device__ float g_h1[NTOK * DEMB];
__device__ float g_h2[NTOK * DEMB];
__device__ float g_t [NTOK * DEMB];
__device__ float g_q [NTOK * DEMB];
__device__ float g_k [NTOK * DEMB];
__device__ float g_v [NTOK * DEMB];
__device__ float g_ff[NTOK * DFF];
// split-fp16 staging (uint16 = raw fp16 bits)
__device__ uint16_t g_ah [NTOK * DFF];             // A hi (max 2048x4096)
__device__ uint16_t g_al [NTOK * DFF];             // A lo
__device__ uint16_t g_bth[(size_t)NVOCAB * DEMB];  // B^T hi (max 32000x1024)

// ---------------- split-bf16 helper (flash attention only) ----------------
__device__ __forceinline__ void split2(float x0, float x1, uint32_t& hi, uint32_t& lo) {
    uint32_t u0 = __float_as_uint(x0), u1 = __float_as_uint(x1);
    hi = __byte_perm(u0, u1, 0x7632);
    float l0 = x0 - __uint_as_float(u0 & 0xffff0000u);
    float l1 = x1 - __uint_as_float(u1 & 0xffff0000u);
    asm("cvt.rn.bf16x2.f32 %0, %1, %2;" : "=r"(lo) : "f"(l1), "f"(l0));
}

// ---------------- split-fp16 helper: x = hi(fp16 RN) + lo(fp16), |lo|<=2^-12|x| ----------------
__device__ __forceinline__ void split2h(float x0, float x1, uint32_t& hi, uint32_t& lo) {
    __half h0 = __float2half_rn(x0), h1 = __float2half_rn(x1);
    float r0 = x0 - __half2float(h0);
    float r1 = x1 - __half2float(h1);
    __half l0 = __float2half_rn(r0), l1 = __float2half_rn(r1);
    hi = (uint32_t)(*(uint16_t*)&h0) | ((uint32_t)(*(uint16_t*)&h1) << 16);
    lo = (uint32_t)(*(uint16_t*)&l0) | ((uint32_t)(*(uint16_t*)&l1) << 16);
}

// bf16 MMA, fp32 acc (flash attention)
#define MMA(acc, a0, a1, a2, a3, b0, b1)                                        \
    asm("mma.sync.aligned.m16n8k16.row.col.f32.bf16.bf16.f32 "                  \
        "{%0,%1,%2,%3}, {%4,%5,%6,%7}, {%8,%9}, {%0,%1,%2,%3};"                 \
        : "+f"((acc)[0]), "+f"((acc)[1]), "+f"((acc)[2]), "+f"((acc)[3])        \
        : "r"(a0), "r"(a1), "r"(a2), "r"(a3), "r"(b0), "r"(b1))

// fp16 MMA, fp32 acc (GEMM passes)
#define MMAF(acc, a0, a1, a2, a3, b0, b1)                                       \
    asm("mma.sync.aligned.m16n8k16.row.col.f32.f16.f16.f32 "                    \
        "{%0,%1,%2,%3}, {%4,%5,%6,%7}, {%8,%9}, {%0,%1,%2,%3};"                 \
        : "+f"((acc)[0]), "+f"((acc)[1]), "+f"((acc)[2]), "+f"((acc)[3])        \
        : "r"(a0), "r"(a1), "r"(a2), "r"(a3), "r"(b0), "r"(b1))

#define CP_ASYNC16(dst, src) \
    asm volatile("cp.async.cg.shared.global [%0], [%1], 16;" :: "r"(dst), "l"(src))
#define CP_COMMIT() asm volatile("cp.async.commit_group;")
#define CP_WAIT(n)  asm volatile("cp.async.wait_group %0;" :: "n"(n))

__device__ __forceinline__ uint32_t smem_u32(const void* p) {
    uint32_t a;
    asm("{ .reg .u64 t; cvta.to.shared.u64 t, %1; cvt.u32.u64 %0, t; }" : "=r"(a) : "l"(p));
    return a;
}

// ---------------- elementwise fp32 -> split-fp16 (hi/lo) ----------------
__global__ __launch_bounds__(256) void cvt_split(const float* __restrict__ in,
                                                 uint16_t* __restrict__ hi,
                                                 uint16_t* __restrict__ lo) {
    int i4 = (blockIdx.x * 256 + threadIdx.x) * 4;
    float4 v = *(const float4*)(in + i4);
    uint32_t h0, l0, h1, l1;
    split2h(v.x, v.y, h0, l0);
    split2h(v.z, v.w, h1, l1);
    *(uint32_t*)(hi + i4) = h0; *(uint32_t*)(hi + i4 + 2) = h1;
    *(uint32_t*)(lo + i4) = l0; *(uint32_t*)(lo + i4 + 2) = l1;
}

// ---------------- transpose + fp16 hi only: in[K][N] -> hiT [N][K] ----------------
__global__ __launch_bounds__(256) void cvt_trans(const float* __restrict__ in,
                                                 uint16_t* __restrict__ hiT,
                                                 int K, int N) {
    __shared__ float t[32][33];
    int n0 = blockIdx.x * 32, k0 = blockIdx.y * 32;
    int tx = threadIdx.x & 31, ty = threadIdx.x >> 5;   // 32x8
#pragma unroll
    for (int i = 0; i < 32; i += 8)
        t[ty + i][tx] = in[(size_t)(k0 + ty + i) * N + n0 + tx];
    __syncthreads();
#pragma unroll
    for (int i = 0; i < 32; i += 8) {
        float x = t[tx][ty + i];                         // k = k0+tx, n = n0+ty+i
        __half h = __float2half_rn(x);
        hiT[(size_t)(n0 + ty + i) * K + k0 + tx] = *(uint16_t*)&h;
    }
}

// ============ cp.async pipelined 2-pass split-fp16 HMMA GEMM ============
// C = (A_hi + A_lo) @ B_hi^T + bias;  dropped term A_hi@B_lo ~ 2^-12 relative.
// Both passes fp32-accumulate into the SAME accumulator. grid=(M/128,N/128), 2 CTAs/SM.
#define STRIDE 20                         // words per smem row (32 k + pad)
#define TILE_B (128 * STRIDE * 4)         // 10240 bytes per tile
#define BUF_B  (3 * TILE_B)               // Ah, Al, Bh = 30720 bytes
#define GEMM_SMEM (2 * BUF_B)             // 61440

__global__ __launch_bounds__(256, 2) void gemm_cp(const uint16_t* __restrict__ Ahg,
                                                  const uint16_t* __restrict__ Alg,
                                                  const uint16_t* __restrict__ Bth,
                                                  const float* __restrict__ bias,
                                                  float* __restrict__ C,
                                                  int N, int K, int relu) {
    extern __shared__ uint32_t sh[];
    uint32_t sb = smem_u32(sh);
    int tid = threadIdx.x, wid = tid >> 5, lane = tid & 31;
    int bm = blockIdx.x * 128, bn = blockIdx.y * 128;
    int wm = (wid >> 2) * 64, wn = (wid & 3) * 32;
    int r = lane >> 2, c = lane & 3;

#define ISSUE(kt, buf)                                                          \
    {                                                                           \
        int k0i = (kt) << 5;                                                    \
        _Pragma("unroll")                                                       \
        for (int p = 0; p < 2; p++) {                                           \
            int idx = tid + p * 256;                                            \
            int row = idx >> 2, q = idx & 3;                                    \
            size_t ao = (size_t)(bm + row) * K + k0i + q * 8;                   \
            size_t bo = (size_t)(bn + row) * K + k0i + q * 8;                   \
            uint32_t d = sb + (buf) * BUF_B + row * (STRIDE * 4) + q * 16;      \
            CP_ASYNC16(d,              Ahg + ao);                               \
            CP_ASYNC16(d + TILE_B,     Alg + ao);                               \
            CP_ASYNC16(d + 2 * TILE_B, Bth + bo);                               \
        }                                                                       \
        CP_COMMIT();                                                            \
    }

    float acc[4][4][4] = {};

    int KT = K >> 5;
    ISSUE(0, 0);
    ISSUE(1, 1);

    for (int kt = 0; kt < KT; kt++) {
        if (kt + 1 < KT) { CP_WAIT(1); } else { CP_WAIT(0); }
        __syncthreads();
        uint32_t* Ah = sh + (kt & 1) * (BUF_B / 4);
        uint32_t* Al = Ah + 2560;
        uint32_t* Bh = Al + 2560;
#pragma unroll
        for (int s = 0; s < 2; s++) {
            uint32_t bh[4][2];
#pragma unroll
            for (int j = 0; j < 4; j++) {
                int o = (wn + 8 * j + r) * STRIDE + s * 8 + c;
                bh[j][0] = Bh[o]; bh[j][1] = Bh[o + 4];
            }
#pragma unroll
            for (int i = 0; i < 4; i++) {
                int o0 = (wm + 16 * i + r) * STRIDE + s * 8 + c;
                int o1 = o0 + 8 * STRIDE;
                uint32_t ah0 = Ah[o0], ah1 = Ah[o1], ah2 = Ah[o0 + 4], ah3 = Ah[o1 + 4];
                uint32_t al0 = Al[o0], al1 = Al[o1], al2 = Al[o0 + 4], al3 = Al[o1 + 4];
#pragma unroll
                for (int j = 0; j < 4; j++) {
                    MMAF(acc[i][j], ah0, ah1, ah2, ah3, bh[j][0], bh[j][1]);   // hi*hi
                    MMAF(acc[i][j], al0, al1, al2, al3, bh[j][0], bh[j][1]);   // lo*hi
                }
            }
        }
        if (kt + 2 < KT) {
            __syncthreads();               // all compute(kt) done before overwriting its buffer
            ISSUE(kt + 2, kt & 1);
        }
    }

#pragma unroll
    for (int i = 0; i < 4; i++) {
#pragma unroll
        for (int j = 0; j < 4; j++) {
            int col = bn + wn + 8 * j + 2 * c;
            int row0 = bm + wm + 16 * i + r;
            float b0 = bias[col], b1 = bias[col + 1];
            float v0 = acc[i][j][0] + b0, v1 = acc[i][j][1] + b1;
            float v2 = acc[i][j][2] + b0, v3 = acc[i][j][3] + b1;
            if (relu) {
                v0 = fmaxf(v0, 0.0f); v1 = fmaxf(v1, 0.0f);
                v2 = fmaxf(v2, 0.0f); v3 = fmaxf(v3, 0.0f);
            }
            *(float2*)(C + (size_t)row0 * N + col) = make_float2(v0, v1);
            *(float2*)(C + (size_t)(row0 + 8) * N + col) = make_float2(v2, v3);
        }
    }
}

// ============ fused flash attention (split-bf16 HMMA, online softmax, 1e-19 mask quirk) ============
#define FA_SMEM_WORDS (4608 + 4608 + 4352 + 4352)
#define FA_SMEM_BYTES (FA_SMEM_WORDS * 4)
__global__ __launch_bounds__(256) void flash_attn(const float* __restrict__ Qg,
                                                  const float* __restrict__ Kg,
                                                  const float* __restrict__ Vg,
                                                  float* __restrict__ Og, int causal) {
    extern __shared__ uint32_t sm[];
    uint32_t* Kh = sm;
    uint32_t* Kl = sm + 4608;
    uint32_t* Vh = sm + 9216;
    uint32_t* Vl = sm + 13568;
    int tid = threadIdx.x, wid = tid >> 5, lane = tid & 31;
    int r = lane >> 2, c = lane & 3;
    int b = blockIdx.y >> 4, h = blockIdx.y & 15;
    const float* Qb = Qg + (size_t)b * SEQ * DEMB + h * DH;
    const float* Kb = Kg + (size_t)b * SEQ * DEMB + h * DH;
    const float* Vb = Vg + (size_t)b * SEQ * DEMB + h * DH;
    int q0 = blockIdx.x * 128;
    int grow = q0 + wid * 16 + r;

    uint32_t qh[4][4], ql[4][4];
#pragma unroll
    for (int s = 0; s < 4; s++) {
        const float* q0p = Qb + (size_t)grow * DEMB + s * 16;
        const float* q1p = q0p + 8 * DEMB;
        float2 v0 = *(const float2*)(q0p + 2 * c);
        float2 v1 = *(const float2*)(q1p + 2 * c);
        float2 v2 = *(const float2*)(q0p + 2 * c + 8);
        float2 v3 = *(const float2*)(q1p + 2 * c + 8);
        split2(v0.x, v0.y, qh[s][0], ql[s][0]);
        split2(v1.x, v1.y, qh[s][1], ql[s][1]);
        split2(v2.x, v2.y, qh[s][2], ql[s][2]);
        split2(v3.x, v3.y, qh[s][3], ql[s][3]);
    }

    float oacc[8][4] = {};
    float m0 = -1e30f, m1 = -1e30f, l0 = 0.0f, l1 = 0.0f;

    for (int kt = 0; kt < SEQ / 128; kt++) {
        int k0 = kt * 128;
        __syncthreads();
#pragma unroll
        for (int p = 0; p < 16; p++) {
            int idx = tid + p * 256;
            int row = idx >> 5, kp = idx & 31;
            float2 kv = *(const float2*)(Kb + (size_t)(k0 + row) * DEMB + kp * 2);
            uint32_t hh, ll; split2(kv.x, kv.y, hh, ll);
            Kh[row * 36 + kp] = hh; Kl[row * 36 + kp] = ll;
        }
#pragma unroll
        for (int p = 0; p < 16; p++) {
            int idx = tid + p * 256;
            int d = idx & 63, kp = idx >> 6;
            float x0 = Vb[(size_t)(k0 + kp * 2) * DEMB + d];
            float x1 = Vb[(size_t)(k0 + kp * 2 + 1) * DEMB + d];
            uint32_t hh, ll; split2(x0, x1, hh, ll);
            Vh[d * 68 + kp] = hh; Vl[d * 68 + kp] = ll;
        }
        __syncthreads();

        float sacc[16][4];
#pragma unroll
        for (int j = 0; j < 16; j++) { sacc[j][0] = sacc[j][1] = sacc[j][2] = sacc[j][3] = 0.0f; }
#pragma unroll
        for (int j = 0; j < 16; j++) {
#pragma unroll
            for (int s = 0; s < 4; s++) {
                int o = (8 * j + r) * 36 + 8 * s + c;
                uint32_t kh0 = Kh[o], kh1 = Kh[o + 4];
                uint32_t kl0 = Kl[o], kl1 = Kl[o + 4];
                MMA(sacc[j], qh[s][0], qh[s][1], qh[s][2], qh[s][3], kh0, kh1);
                MMA(sacc[j], qh[s][0], qh[s][1], qh[s][2], qh[s][3], kl0, kl1);
                MMA(sacc[j], ql[s][0], ql[s][1], ql[s][2], ql[s][3], kh0, kh1);
            }
        }
        float tm0 = -1e30f, tm1 = -1e30f;
#pragma unroll
        for (int j = 0; j < 16; j++) {
            int col = k0 + 8 * j + 2 * c;
            float v0 = sacc[j][0] * 0.125f, v1 = sacc[j][1] * 0.125f;
            float v2 = sacc[j][2] * 0.125f, v3 = sacc[j][3] * 0.125f;
            if (causal) {
                if (col     > grow)     v0 = 1e-19f;
                if (col + 1 > grow)     v1 = 1e-19f;
                if (col     > grow + 8) v2 = 1e-19f;
                if (col + 1 > grow + 8) v3 = 1e-19f;
            }
            sacc[j][0] = v0; sacc[j][1] = v1; sacc[j][2] = v2; sacc[j][3] = v3;
            tm0 = fmaxf(tm0, fmaxf(v0, v1));
            tm1 = fmaxf(tm1, fmaxf(v2, v3));
        }
        tm0 = fmaxf(tm0, __shfl_xor_sync(0xffffffffu, tm0, 1));
        tm0 = fmaxf(tm0, __shfl_xor_sync(0xffffffffu, tm0, 2));
        tm1 = fmaxf(tm1, __shfl_xor_sync(0xffffffffu, tm1, 1));
        tm1 = fmaxf(tm1, __shfl_xor_sync(0xffffffffu, tm1, 2));
        float mn0 = fmaxf(m0, tm0), mn1 = fmaxf(m1, tm1);
        float sc0 = __expf(m0 - mn0), sc1 = __expf(m1 - mn1);
        m0 = mn0; m1 = mn1;
        float rs0 = 0.0f, rs1 = 0.0f;
#pragma unroll
        for (int j = 0; j < 16; j++) {
            float p0 = __expf(sacc[j][0] - m0), p1 = __expf(sacc[j][1] - m0);
            float p2 = __expf(sacc[j][2] - m1), p3 = __expf(sacc[j][3] - m1);
            sacc[j][0] = p0; sacc[j][1] = p1; sacc[j][2] = p2; sacc[j][3] = p3;
            rs0 += p0 + p1; rs1 += p2 + p3;
        }
        rs0 += __shfl_xor_sync(0xffffffffu, rs0, 1);
        rs0 += __shfl_xor_sync(0xffffffffu, rs0, 2);
        rs1 += __shfl_xor_sync(0xffffffffu, rs1, 1);
        rs1 += __shfl_xor_sync(0xffffffffu, rs1, 2);
        l0 = l0 * sc0 + rs0; l1 = l1 * sc1 + rs1;
#pragma unroll
        for (int j2 = 0; j2 < 8; j2++) {
            oacc[j2][0] *= sc0; oacc[j2][1] *= sc0;
            oacc[j2][2] *= sc1; oacc[j2][3] *= sc1;
        }
#pragma unroll
        for (int s2 = 0; s2 < 8; s2++) {
            uint32_t a0h, a0l, a1h, a1l, a2h, a2l, a3h, a3l;
            split2(sacc[2 * s2][0],     sacc[2 * s2][1],     a0h, a0l);
            split2(sacc[2 * s2][2],     sacc[2 * s2][3],     a1h, a1l);
            split2(sacc[2 * s2 + 1][0], sacc[2 * s2 + 1][1], a2h, a2l);
            split2(sacc[2 * s2 + 1][2], sacc[2 * s2 + 1][3], a3h, a3l);
#pragma unroll
            for (int j2 = 0; j2 < 8; j2++) {
                int o = (8 * j2 + r) * 68 + 8 * s2 + c;
                uint32_t vh0 = Vh[o], vh1 = Vh[o + 4];
                uint32_t vl0 = Vl[o], vl1 = Vl[o + 4];
                MMA(oacc[j2], a0h, a1h, a2h, a3h, vh0, vh1);
                MMA(oacc[j2], a0h, a1h, a2h, a3h, vl0, vl1);
                MMA(oacc[j2], a0l, a1l, a2l, a3l, vh0, vh1);
            }
        }
    }
    float i0 = 1.0f / l0, i1 = 1.0f / l1;
#pragma unroll
    for (int j2 = 0; j2 < 8; j2++) {
        float* op = Og + (size_t)(b * SEQ + grow) * DEMB + h * DH + 8 * j2 + 2 * c;
        *(float2*)op = make_float2(oacc[j2][0] * i0, oacc[j2][1] * i0);
        *(float2*)(op + 8 * DEMB) = make_float2(oacc[j2][2] * i1, oacc[j2][3] * i1);
    }
}

// ---------------- embedding + positional encoding ----------------
__global__ __launch_bounds__(256) void embed_kernel(const int* __restrict__ ids,
                                                    const float* __restrict__ emb,
                                                    float* __restrict__ X) {
    int t = blockIdx.x;
    int pos = t & (SEQ - 1);
    int id = ids[t];
    int d0 = threadIdx.x * 4;
    float4 e4 = *(const float4*)(emb + (size_t)id * DEMB + d0);
    float ev[4] = {e4.x, e4.y, e4.z, e4.w};
    float ov[4];
#pragma unroll
    for (int j = 0; j < 4; j++) {
        int d = d0 + j;
        float ang = (float)pos * powf(10000.0f, -2.0f * (float)d / (float)DEMB);
        float pe = ((d & 1) == 0) ? sinf(ang) : cosf(ang);
        ov[j] = ev[j] * 32.0f + pe;
    }
    *(float4*)(X + (size_t)t * DEMB + d0) = make_float4(ov[0], ov[1], ov[2], ov[3]);
}

// ---------------- fused q/k/v per-head projection (grid.z selects) ----------------
__global__ __launch_bounds__(256) void proj_head3(
        const float* __restrict__ X0, const float* __restrict__ X1, const float* __restrict__ X2,
        const float* __restrict__ W0, const float* __restrict__ W1, const float* __restrict__ W2,
        float* __restrict__ O0, float* __restrict__ O1, float* __restrict__ O2) {
    const float* X; const float* W; float* O;
    if (blockIdx.z == 0)      { X = X0; W = W0; O = O0; }
    else if (blockIdx.z == 1) { X = X1; W = W1; O = O1; }
    else                      { X = X2; W = W2; O = O2; }
    __shared__ float Xs[64][64];
    __shared__ float Ws[64][64];
    int tid = threadIdx.x;
    int h = blockIdx.y;
    int t0 = blockIdx.x * 64;
#pragma unroll
    for (int r = 0; r < 4; r++) {
        int idx = tid + r * 256;
        int a = idx >> 4;
        int c4 = (idx & 15) << 2;
        float4 xv = *(const float4*)(X + (size_t)(t0 + a) * DEMB + h * DH + c4);
        Xs[c4 + 0][a] = xv.x; Xs[c4 + 1][a] = xv.y; Xs[c4 + 2][a] = xv.z; Xs[c4 + 3][a] = xv.w;
        float4 wv = *(const float4*)(W + a * DH + c4);
        *(float4*)&Ws[a][c4] = wv;
    }
    __syncthreads();
    int tx = tid & 15, ty = tid >> 4;
    float acc[4][4] = {};
#pragma unroll
    for (int d = 0; d < 64; d++) {
        float4 a4 = *(float4*)&Xs[d][ty * 4];
        float4 w4 = *(float4*)&Ws[d][tx * 4];
        float av[4] = {a4.x, a4.y, a4.z, a4.w};
        float wv[4] = {w4.x, w4.y, w4.z, w4.w};
#pragma unroll
        for (int i = 0; i < 4; i++)
#pragma unroll
            for (int j = 0; j < 4; j++) acc[i][j] = fmaf(av[i], wv[j], acc[i][j]);
    }
#pragma unroll
    for (int i = 0; i < 4; i++) {
        float4 o = make_float4(acc[i][0], acc[i][1], acc[i][2], acc[i][3]);
        *(float4*)(O + (size_t)(t0 + ty * 4 + i) * DEMB + h * DH + tx * 4) = o;
    }
}

// ---------------- residual add + layernorm: one warp per row, shuffle-only ----------------
__global__ __launch_bounds__(256) void add_ln(const float* __restrict__ A, const float* __restrict__ B,
                                              const float* __restrict__ g, const float* __restrict__ be,
                                              float* __restrict__ O) {
    int lane = threadIdx.x & 31, wid = threadIdx.x >> 5;
    int row = blockIdx.x * 8 + wid;
    size_t base = (size_t)row * DEMB;
    float4 v[8];
    float s1 = 0.0f, s2 = 0.0f;
#pragma unroll
    for (int p = 0; p < 8; p++) {
        float4 a = ((const float4*)(A + base))[lane + p * 32];
        float4 b = ((const float4*)(B + base))[lane + p * 32];
        float4 t = make_float4(a.x + b.x, a.y + b.y, a.z + b.z, a.w + b.w);
        v[p] = t;
        s1 += t.x + t.y + t.z + t.w;
        s2 += t.x * t.x + t.y * t.y + t.z * t.z + t.w * t.w;
    }
#pragma unroll
    for (int o = 16; o; o >>= 1) {
        s1 += __shfl_xor_sync(0xffffffffu, s1, o);
        s2 += __shfl_xor_sync(0xffffffffu, s2, o);
    }
    float mu = s1 * (1.0f / DEMB);
    float var = s2 * (1.0f / DEMB) - mu * mu;
    float w = rsqrtf(var + 1e-5f);
#pragma unroll
    for (int p = 0; p < 8; p++) {
        float4 gg = ((const float4*)g)[lane + p * 32];
        float4 bb = ((const float4*)be)[lane + p * 32];
        float4 t = v[p];
        float4 o;
        o.x = (t.x - mu) * w * gg.x + bb.x;
        o.y = (t.y - mu) * w * gg.y + bb.y;
        o.z = (t.z - mu) * w * gg.z + bb.z;
        o.w = (t.w - mu) * w * gg.w + bb.w;
        ((float4*)(O + base))[lane + p * 32] = o;
    }
}

// ---------------- host orchestration ----------------
extern "C" void kernel_launch(void* const* d_in, const int* in_sizes, int n_in,
                              void* d_out, int out_size) {
    const int*   ids   = (const int*)  d_in[0];
    const float* enc_k = (const float*)d_in[1];
    const float* enc_v = (const float*)d_in[2];
    const float* emb   = (const float*)d_in[3];
    const float* Wq_m  = (const float*)d_in[4];
    const float* Wk_m  = (const float*)d_in[5];
    const float* Wv_m  = (const float*)d_in[6];
    const float* Wq_c  = (const float*)d_in[7];
    const float* Wk_c  = (const float*)d_in[8];
    const float* Wv_c  = (const float*)d_in[9];
    const float* ln1_g = (const float*)d_in[10];
    const float* ln1_b = (const float*)d_in[11];
    const float* ln2_g = (const float*)d_in[12];
    const float* ln2_b = (const float*)d_in[13];
    const float* ln3_g = (const float*)d_in[14];
    const float* ln3_b = (const float*)d_in[15];
    const float* W1    = (const float*)d_in[16];
    const float* b1    = (const float*)d_in[17];
    const float* W2    = (const float*)d_in[18];
    const float* b2    = (const float*)d_in[19];
    const float* Wout  = (const float*)d_in[20];
    const float* bout  = (const float*)d_in[21];
    float* out = (float*)d_out;

    float *x, *h1, *h2, *t, *q, *k, *v, *ff;
    uint16_t *ah, *al, *bth;
    cudaGetSymbolAddress((void**)&x,  g_x);
    cudaGetSymbolAddress((void**)&h1, g_h1);
    cudaGetSymbolAddress((void**)&h2, g_h2);
    cudaGetSymbolAddress((void**)&t,  g_t);
    cudaGetSymbolAddress((void**)&q,  g_q);
    cudaGetSymbolAddress((void**)&k,  g_k);
    cudaGetSymbolAddress((void**)&v,  g_v);
    cudaGetSymbolAddress((void**)&ff, g_ff);
    cudaGetSymbolAddress((void**)&ah,  g_ah);
    cudaGetSymbolAddress((void**)&al,  g_al);
    cudaGetSymbolAddress((void**)&bth, g_bth);

    cudaFuncSetAttribute(flash_attn, cudaFuncAttributeMaxDynamicSharedMemorySize, FA_SMEM_BYTES);
    cudaFuncSetAttribute(gemm_cp,   cudaFuncAttributeMaxDynamicSharedMemorySize, GEMM_SMEM);

    dim3 blk(256);
    dim3 projGrid(NTOK / 64, NHEAD, 3);
    dim3 faGrid(SEQ / 128, NB * NHEAD);
    dim3 tblk(256);

    embed_kernel<<<NTOK, blk>>>(ids, emb, x);

    for (int l = 0; l < NLAYER; l++) {
        size_t wOff  = (size_t)l * DH * DH;
        size_t lnOff = (size_t)l * DEMB;
        // --- masked self-attention ---
        proj_head3<<<projGrid, blk>>>(x, x, x, Wq_m + wOff, Wk_m + wOff, Wv_m + wOff, q, k, v);
        flash_attn<<<faGrid, blk, FA_SMEM_BYTES>>>(q, k, v, t, 1);
        add_ln<<<NTOK / 8, blk>>>(t, x, ln1_g + lnOff, ln1_b + lnOff, h1);
        // --- cross-attention ---
        proj_head3<<<projGrid, blk>>>(h1, enc_k, enc_v, Wq_c + wOff, Wk_c + wOff, Wv_c + wOff, q, k, v);
        flash_attn<<<faGrid, blk, FA_SMEM_BYTES>>>(q, k, v, t, 0);
        add_ln<<<NTOK / 8, blk>>>(t, h1, ln2_g + lnOff, ln2_b + lnOff, h2);
        // --- FFN (2-pass cp.async split-fp16 HMMA, 2 CTAs/SM) ---
        cvt_split<<<(NTOK * DEMB) / 1024, blk>>>(h2, ah, al);
        cvt_trans<<<dim3(DFF / 32, DEMB / 32), tblk>>>(W1 + (size_t)l * DEMB * DFF, bth, DEMB, DFF);
        gemm_cp<<<dim3(NTOK / 128, DFF / 128), blk, GEMM_SMEM>>>(
            ah, al, bth, b1 + (size_t)l * DFF, ff, DFF, DEMB, 1);
        cvt_split<<<(NTOK * DFF) / 1024, blk>>>(ff, ah, al);
        cvt_trans<<<dim3(DEMB / 32, DFF / 32), tblk>>>(W2 + (size_t)l * DFF * DEMB, bth, DFF, DEMB);
        gemm_cp<<<dim3(NTOK / 128, DEMB / 128), blk, GEMM_SMEM>>>(
            ah, al, bth, b2 + lnOff, t, DEMB, DFF, 0);
        add_ln<<<NTOK / 8, blk>>>(t, h2, ln3_g + lnOff, ln3_b + lnOff, x);
    }

    // --- vocab projection ---
    cvt_split<<<(NTOK * DEMB) / 1024, blk>>>(x, ah, al);
    cvt_trans<<<dim3(NVOCAB / 32, DEMB / 32), tblk>>>(Wout, bth, DEMB, NVOCAB);
    gemm_cp<<<dim3(NTOK / 128, NVOCAB / 128), blk, GEMM_SMEM>>>(
        ah, al, bth, bout, out, NVOCAB, DEMB, 0);
}

// round 10
// speedup vs baseline: 1.2573x; 1.0017x over previous
#include <cuda_runtime.h>
#include <cuda_bf16.h>
#include <cuda_fp16.h>
#include <math.h>
#include <stdint.h>

#define NB 2
#define SEQ 1024
#define NTOK (NB * SEQ)          // 2048
#define DEMB 1024
#define NHEAD 16
#define DH 64
#define DFF 4096
#define NVOCAB 32000
#define NLAYER 6

// -------- scratch (device globals; no allocation allowed) --------
__device__ float g_x [NTOK * DEMB];
__device__ float g_h1[NTOK * DEMB];
__device__ float g_h2[NTOK * DEMB];
__device__ float g_t [NTOK * DEMB];
__device__ float g_q [NTOK * DEMB];
__device__ float g_k [NTOK * DEMB];
__device__ float g_v [NTOK * DEMB];
// split-fp16 staging (uint16 = raw fp16 bits)
__device__ uint16_t g_ah [NTOK * DEMB];            // activation hi (h2 / x)
__device__ uint16_t g_al [NTOK * DEMB];            // activation lo
__device__ uint16_t g_fh [NTOK * DFF];             // ff hi
__device__ uint16_t g_fl [NTOK * DFF];             // ff lo
__device__ uint16_t g_bth[(size_t)NVOCAB * DEMB];  // B^T hi (max 32000x1024)

// ---------------- split-bf16 helper (flash attention only) ----------------
__device__ __forceinline__ void split2(float x0, float x1, uint32_t& hi, uint32_t& lo) {
    uint32_t u0 = __float_as_uint(x0), u1 = __float_as_uint(x1);
    hi = __byte_perm(u0, u1, 0x7632);
    float l0 = x0 - __uint_as_float(u0 & 0xffff0000u);
    float l1 = x1 - __uint_as_float(u1 & 0xffff0000u);
    asm("cvt.rn.bf16x2.f32 %0, %1, %2;" : "=r"(lo) : "f"(l1), "f"(l0));
}

// ---------------- split-fp16 helper: x = hi(fp16 RN) + lo(fp16), |lo|<=2^-12|x| ----------------
__device__ __forceinline__ void split2h(float x0, float x1, uint32_t& hi, uint32_t& lo) {
    __half h0 = __float2half_rn(x0), h1 = __float2half_rn(x1);
    float r0 = x0 - __half2float(h0);
    float r1 = x1 - __half2float(h1);
    __half l0 = __float2half_rn(r0), l1 = __float2half_rn(r1);
    hi = (uint32_t)(*(uint16_t*)&h0) | ((uint32_t)(*(uint16_t*)&h1) << 16);
    lo = (uint32_t)(*(uint16_t*)&l0) | ((uint32_t)(*(uint16_t*)&l1) << 16);
}

// bf16 MMA, fp32 acc (flash attention)
#define MMA(acc, a0, a1, a2, a3, b0, b1)                                        \
    asm("mma.sync.aligned.m16n8k16.row.col.f32.bf16.bf16.f32 "                  \
        "{%0,%1,%2,%3}, {%4,%5,%6,%7}, {%8,%9}, {%0,%1,%2,%3};"                 \
        : "+f"((acc)[0]), "+f"((acc)[1]), "+f"((acc)[2]), "+f"((acc)[3])        \
        : "r"(a0), "r"(a1), "r"(a2), "r"(a3), "r"(b0), "r"(b1))

// fp16 MMA, fp32 acc (GEMM passes)
#define MMAF(acc, a0, a1, a2, a3, b0, b1)                                       \
    asm("mma.sync.aligned.m16n8k16.row.col.f32.f16.f16.f32 "                    \
        "{%0,%1,%2,%3}, {%4,%5,%6,%7}, {%8,%9}, {%0,%1,%2,%3};"                 \
        : "+f"((acc)[0]), "+f"((acc)[1]), "+f"((acc)[2]), "+f"((acc)[3])        \
        : "r"(a0), "r"(a1), "r"(a2), "r"(a3), "r"(b0), "r"(b1))

#define CP_ASYNC16(dst, src) \
    asm volatile("cp.async.cg.shared.global [%0], [%1], 16;" :: "r"(dst), "l"(src))
#define CP_COMMIT() asm volatile("cp.async.commit_group;")
#define CP_WAIT(n)  asm volatile("cp.async.wait_group %0;" :: "n"(n))

__device__ __forceinline__ uint32_t smem_u32(const void* p) {
    uint32_t a;
    asm("{ .reg .u64 t; cvta.to.shared.u64 t, %1; cvt.u32.u64 %0, t; }" : "=r"(a) : "l"(p));
    return a;
}

// ---------------- transpose + fp16 hi only: in[K][N] -> hiT [N][K] ----------------
__global__ __launch_bounds__(256) void cvt_trans(const float* __restrict__ in,
                                                 uint16_t* __restrict__ hiT,
                                                 int K, int N) {
    __shared__ float t[32][33];
    int n0 = blockIdx.x * 32, k0 = blockIdx.y * 32;
    int tx = threadIdx.x & 31, ty = threadIdx.x >> 5;   // 32x8
#pragma unroll
    for (int i = 0; i < 32; i += 8)
        t[ty + i][tx] = in[(size_t)(k0 + ty + i) * N + n0 + tx];
    __syncthreads();
#pragma unroll
    for (int i = 0; i < 32; i += 8) {
        float x = t[tx][ty + i];                         // k = k0+tx, n = n0+ty+i
        __half h = __float2half_rn(x);
        hiT[(size_t)(n0 + ty + i) * K + k0 + tx] = *(uint16_t*)&h;
    }
}

// ============ cp.async pipelined 2-pass split-fp16 HMMA GEMM ============
// C = (A_hi + A_lo) @ B_hi^T + bias;  dropped term A_hi@B_lo ~ 2^-12 relative.
// outs: if Oh != null, write relu'd result as split fp16 (Oh/Ol); else f32 to C.
#define STRIDE 20                         // words per smem row (32 k + pad)
#define TILE_B (128 * STRIDE * 4)         // 10240 bytes per tile
#define BUF_B  (3 * TILE_B)               // Ah, Al, Bh = 30720 bytes
#define GEMM_SMEM (2 * BUF_B)             // 61440

__global__ __launch_bounds__(256, 2) void gemm_cp(const uint16_t* __restrict__ Ahg,
                                                  const uint16_t* __restrict__ Alg,
                                                  const uint16_t* __restrict__ Bth,
                                                  const float* __restrict__ bias,
                                                  float* __restrict__ C,
                                                  uint16_t* __restrict__ Oh,
                                                  uint16_t* __restrict__ Ol,
                                                  int N, int K, int relu) {
    extern __shared__ uint32_t sh[];
    uint32_t sb = smem_u32(sh);
    int tid = threadIdx.x, wid = tid >> 5, lane = tid & 31;
    int bm = blockIdx.x * 128, bn = blockIdx.y * 128;
    int wm = (wid >> 2) * 64, wn = (wid & 3) * 32;
    int r = lane >> 2, c = lane & 3;

#define ISSUE(kt, buf)                                                          \
    {                                                                           \
        int k0i = (kt) << 5;                                                    \
        _Pragma("unroll")                                                       \
        for (int p = 0; p < 2; p++) {                                           \
            int idx = tid + p * 256;                                            \
            int row = idx >> 2, q = idx & 3;                                    \
            size_t ao = (size_t)(bm + row) * K + k0i + q * 8;                   \
            size_t bo = (size_t)(bn + row) * K + k0i + q * 8;                   \
            uint32_t d = sb + (buf) * BUF_B + row * (STRIDE * 4) + q * 16;      \
            CP_ASYNC16(d,              Ahg + ao);                               \
            CP_ASYNC16(d + TILE_B,     Alg + ao);                               \
            CP_ASYNC16(d + 2 * TILE_B, Bth + bo);                               \
        }                                                                       \
        CP_COMMIT();                                                            \
    }

    float acc[4][4][4] = {};

    int KT = K >> 5;
    ISSUE(0, 0);
    ISSUE(1, 1);

    for (int kt = 0; kt < KT; kt++) {
        if (kt + 1 < KT) { CP_WAIT(1); } else { CP_WAIT(0); }
        __syncthreads();
        uint32_t* Ah = sh + (kt & 1) * (BUF_B / 4);
        uint32_t* Al = Ah + 2560;
        uint32_t* Bh = Al + 2560;
#pragma unroll
        for (int s = 0; s < 2; s++) {
            uint32_t bh[4][2];
#pragma unroll
            for (int j = 0; j < 4; j++) {
                int o = (wn + 8 * j + r) * STRIDE + s * 8 + c;
                bh[j][0] = Bh[o]; bh[j][1] = Bh[o + 4];
            }
#pragma unroll
            for (int i = 0; i < 4; i++) {
                int o0 = (wm + 16 * i + r) * STRIDE + s * 8 + c;
                int o1 = o0 + 8 * STRIDE;
                uint32_t ah0 = Ah[o0], ah1 = Ah[o1], ah2 = Ah[o0 + 4], ah3 = Ah[o1 + 4];
                uint32_t al0 = Al[o0], al1 = Al[o1], al2 = Al[o0 + 4], al3 = Al[o1 + 4];
#pragma unroll
                for (int j = 0; j < 4; j++) {
                    MMAF(acc[i][j], ah0, ah1, ah2, ah3, bh[j][0], bh[j][1]);   // hi*hi
                    MMAF(acc[i][j], al0, al1, al2, al3, bh[j][0], bh[j][1]);   // lo*hi
                }
            }
        }
        if (kt + 2 < KT) {
            __syncthreads();               // all compute(kt) done before overwriting its buffer
            ISSUE(kt + 2, kt & 1);
        }
    }

#pragma unroll
    for (int i = 0; i < 4; i++) {
#pragma unroll
        for (int j = 0; j < 4; j++) {
            int col = bn + wn + 8 * j + 2 * c;
            int row0 = bm + wm + 16 * i + r;
            float b0 = bias[col], b1 = bias[col + 1];
            float v0 = acc[i][j][0] + b0, v1 = acc[i][j][1] + b1;
            float v2 = acc[i][j][2] + b0, v3 = acc[i][j][3] + b1;
            if (relu) {
                v0 = fmaxf(v0, 0.0f); v1 = fmaxf(v1, 0.0f);
                v2 = fmaxf(v2, 0.0f); v3 = fmaxf(v3, 0.0f);
            }
            if (Oh) {
                uint32_t h0, l0, h1, l1;
                split2h(v0, v1, h0, l0);
                split2h(v2, v3, h1, l1);
                size_t o0 = (size_t)row0 * N + col;
                size_t o1 = (size_t)(row0 + 8) * N + col;
                *(uint32_t*)(Oh + o0) = h0; *(uint32_t*)(Ol + o0) = l0;
                *(uint32_t*)(Oh + o1) = h1; *(uint32_t*)(Ol + o1) = l1;
            } else {
                *(float2*)(C + (size_t)row0 * N + col) = make_float2(v0, v1);
                *(float2*)(C + (size_t)(row0 + 8) * N + col) = make_float2(v2, v3);
            }
        }
    }
}

// ============ fused flash attention (split-bf16 HMMA, online softmax, 1e-19 mask quirk) ============
#define FA_SMEM_WORDS (4608 + 4608 + 4352 + 4352)
#define FA_SMEM_BYTES (FA_SMEM_WORDS * 4)
__global__ __launch_bounds__(256) void flash_attn(const float* __restrict__ Qg,
                                                  const float* __restrict__ Kg,
                                                  const float* __restrict__ Vg,
                                                  float* __restrict__ Og, int causal) {
    extern __shared__ uint32_t sm[];
    uint32_t* Kh = sm;
    uint32_t* Kl = sm + 4608;
    uint32_t* Vh = sm + 9216;
    uint32_t* Vl = sm + 13568;
    int tid = threadIdx.x, wid = tid >> 5, lane = tid & 31;
    int r = lane >> 2, c = lane & 3;
    int b = blockIdx.y >> 4, h = blockIdx.y & 15;
    const float* Qb = Qg + (size_t)b * SEQ * DEMB + h * DH;
    const float* Kb = Kg + (size_t)b * SEQ * DEMB + h * DH;
    const float* Vb = Vg + (size_t)b * SEQ * DEMB + h * DH;
    int q0 = blockIdx.x * 128;
    int grow = q0 + wid * 16 + r;

    uint32_t qh[4][4], ql[4][4];
#pragma unroll
    for (int s = 0; s < 4; s++) {
        const float* q0p = Qb + (size_t)grow * DEMB + s * 16;
        const float* q1p = q0p + 8 * DEMB;
        float2 v0 = *(const float2*)(q0p + 2 * c);
        float2 v1 = *(const float2*)(q1p + 2 * c);
        float2 v2 = *(const float2*)(q0p + 2 * c + 8);
        float2 v3 = *(const float2*)(q1p + 2 * c + 8);
        split2(v0.x, v0.y, qh[s][0], ql[s][0]);
        split2(v1.x, v1.y, qh[s][1], ql[s][1]);
        split2(v2.x, v2.y, qh[s][2], ql[s][2]);
        split2(v3.x, v3.y, qh[s][3], ql[s][3]);
    }

    float oacc[8][4] = {};
    float m0 = -1e30f, m1 = -1e30f, l0 = 0.0f, l1 = 0.0f;

    for (int kt = 0; kt < SEQ / 128; kt++) {
        int k0 = kt * 128;
        __syncthreads();
#pragma unroll
        for (int p = 0; p < 16; p++) {
            int idx = tid + p * 256;
            int row = idx >> 5, kp = idx & 31;
            float2 kv = *(const float2*)(Kb + (size_t)(k0 + row) * DEMB + kp * 2);
            uint32_t hh, ll; split2(kv.x, kv.y, hh, ll);
            Kh[row * 36 + kp] = hh; Kl[row * 36 + kp] = ll;
        }
#pragma unroll
        for (int p = 0; p < 16; p++) {
            int idx = tid + p * 256;
            int d = idx & 63, kp = idx >> 6;
            float x0 = Vb[(size_t)(k0 + kp * 2) * DEMB + d];
            float x1 = Vb[(size_t)(k0 + kp * 2 + 1) * DEMB + d];
            uint32_t hh, ll; split2(x0, x1, hh, ll);
            Vh[d * 68 + kp] = hh; Vl[d * 68 + kp] = ll;
        }
        __syncthreads();

        float sacc[16][4];
#pragma unroll
        for (int j = 0; j < 16; j++) { sacc[j][0] = sacc[j][1] = sacc[j][2] = sacc[j][3] = 0.0f; }
#pragma unroll
        for (int j = 0; j < 16; j++) {
#pragma unroll
            for (int s = 0; s < 4; s++) {
                int o = (8 * j + r) * 36 + 8 * s + c;
                uint32_t kh0 = Kh[o], kh1 = Kh[o + 4];
                uint32_t kl0 = Kl[o], kl1 = Kl[o + 4];
                MMA(sacc[j], qh[s][0], qh[s][1], qh[s][2], qh[s][3], kh0, kh1);
                MMA(sacc[j], qh[s][0], qh[s][1], qh[s][2], qh[s][3], kl0, kl1);
                MMA(sacc[j], ql[s][0], ql[s][1], ql[s][2], ql[s][3], kh0, kh1);
            }
        }
        float tm0 = -1e30f, tm1 = -1e30f;
#pragma unroll
        for (int j = 0; j < 16; j++) {
            int col = k0 + 8 * j + 2 * c;
            float v0 = sacc[j][0] * 0.125f, v1 = sacc[j][1] * 0.125f;
            float v2 = sacc[j][2] * 0.125f, v3 = sacc[j][3] * 0.125f;
            if (causal) {
                if (col     > grow)     v0 = 1e-19f;
                if (col + 1 > grow)     v1 = 1e-19f;
                if (col     > grow + 8) v2 = 1e-19f;
                if (col + 1 > grow + 8) v3 = 1e-19f;
            }
            sacc[j][0] = v0; sacc[j][1] = v1; sacc[j][2] = v2; sacc[j][3] = v3;
            tm0 = fmaxf(tm0, fmaxf(v0, v1));
            tm1 = fmaxf(tm1, fmaxf(v2, v3));
        }
        tm0 = fmaxf(tm0, __shfl_xor_sync(0xffffffffu, tm0, 1));
        tm0 = fmaxf(tm0, __shfl_xor_sync(0xffffffffu, tm0, 2));
        tm1 = fmaxf(tm1, __shfl_xor_sync(0xffffffffu, tm1, 1));
        tm1 = fmaxf(tm1, __shfl_xor_sync(0xffffffffu, tm1, 2));
        float mn0 = fmaxf(m0, tm0), mn1 = fmaxf(m1, tm1);
        float sc0 = __expf(m0 - mn0), sc1 = __expf(m1 - mn1);
        m0 = mn0; m1 = mn1;
        float rs0 = 0.0f, rs1 = 0.0f;
#pragma unroll
        for (int j = 0; j < 16; j++) {
            float p0 = __expf(sacc[j][0] - m0), p1 = __expf(sacc[j][1] - m0);
            float p2 = __expf(sacc[j][2] - m1), p3 = __expf(sacc[j][3] - m1);
            sacc[j][0] = p0; sacc[j][1] = p1; sacc[j][2] = p2; sacc[j][3] = p3;
            rs0 += p0 + p1; rs1 += p2 + p3;
        }
        rs0 += __shfl_xor_sync(0xffffffffu, rs0, 1);
        rs0 += __shfl_xor_sync(0xffffffffu, rs0, 2);
        rs1 += __shfl_xor_sync(0xffffffffu, rs1, 1);
        rs1 += __shfl_xor_sync(0xffffffffu, rs1, 2);
        l0 = l0 * sc0 + rs0; l1 = l1 * sc1 + rs1;
#pragma unroll
        for (int j2 = 0; j2 < 8; j2++) {
            oacc[j2][0] *= sc0; oacc[j2][1] *= sc0;
            oacc[j2][2] *= sc1; oacc[j2][3] *= sc1;
        }
#pragma unroll
        for (int s2 = 0; s2 < 8; s2++) {
            uint32_t a0h, a0l, a1h, a1l, a2h, a2l, a3h, a3l;
            split2(sacc[2 * s2][0],     sacc[2 * s2][1],     a0h, a0l);
            split2(sacc[2 * s2][2],     sacc[2 * s2][3],     a1h, a1l);
            split2(sacc[2 * s2 + 1][0], sacc[2 * s2 + 1][1], a2h, a2l);
            split2(sacc[2 * s2 + 1][2], sacc[2 * s2 + 1][3], a3h, a3l);
#pragma unroll
            for (int j2 = 0; j2 < 8; j2++) {
                int o = (8 * j2 + r) * 68 + 8 * s2 + c;
                uint32_t vh0 = Vh[o], vh1 = Vh[o + 4];
                uint32_t vl0 = Vl[o], vl1 = Vl[o + 4];
                MMA(oacc[j2], a0h, a1h, a2h, a3h, vh0, vh1);
                MMA(oacc[j2], a0h, a1h, a2h, a3h, vl0, vl1);
                MMA(oacc[j2], a0l, a1l, a2l, a3l, vh0, vh1);
            }
        }
    }
    float i0 = 1.0f / l0, i1 = 1.0f / l1;
#pragma unroll
    for (int j2 = 0; j2 < 8; j2++) {
        float* op = Og + (size_t)(b * SEQ + grow) * DEMB + h * DH + 8 * j2 + 2 * c;
        *(float2*)op = make_float2(oacc[j2][0] * i0, oacc[j2][1] * i0);
        *(float2*)(op + 8 * DEMB) = make_float2(oacc[j2][2] * i1, oacc[j2][3] * i1);
    }
}

// ---------------- embedding + positional encoding ----------------
__global__ __launch_bounds__(256) void embed_kernel(const int* __restrict__ ids,
                                                    const float* __restrict__ emb,
                                                    float* __restrict__ X) {
    int t = blockIdx.x;
    int pos = t & (SEQ - 1);
    int id = ids[t];
    int d0 = threadIdx.x * 4;
    float4 e4 = *(const float4*)(emb + (size_t)id * DEMB + d0);
    float ev[4] = {e4.x, e4.y, e4.z, e4.w};
    float ov[4];
#pragma unroll
    for (int j = 0; j < 4; j++) {
        int d = d0 + j;
        float ang = (float)pos * powf(10000.0f, -2.0f * (float)d / (float)DEMB);
        float pe = ((d & 1) == 0) ? sinf(ang) : cosf(ang);
        ov[j] = ev[j] * 32.0f + pe;
    }
    *(float4*)(X + (size_t)t * DEMB + d0) = make_float4(ov[0], ov[1], ov[2], ov[3]);
}

// ---------------- fused q/k/v per-head projection (grid.z selects) ----------------
__global__ __launch_bounds__(256) void proj_head3(
        const float* __restrict__ X0, const float* __restrict__ X1, const float* __restrict__ X2,
        const float* __restrict__ W0, const float* __restrict__ W1, const float* __restrict__ W2,
        float* __restrict__ O0, float* __restrict__ O1, float* __restrict__ O2) {
    const float* X; const float* W; float* O;
    if (blockIdx.z == 0)      { X = X0; W = W0; O = O0; }
    else if (blockIdx.z == 1) { X = X1; W = W1; O = O1; }
    else                      { X = X2; W = W2; O = O2; }
    __shared__ float Xs[64][64];
    __shared__ float Ws[64][64];
    int tid = threadIdx.x;
    int h = blockIdx.y;
    int t0 = blockIdx.x * 64;
#pragma unroll
    for (int r = 0; r < 4; r++) {
        int idx = tid + r * 256;
        int a = idx >> 4;
        int c4 = (idx & 15) << 2;
        float4 xv = *(const float4*)(X + (size_t)(t0 + a) * DEMB + h * DH + c4);
        Xs[c4 + 0][a] = xv.x; Xs[c4 + 1][a] = xv.y; Xs[c4 + 2][a] = xv.z; Xs[c4 + 3][a] = xv.w;
        float4 wv = *(const float4*)(W + a * DH + c4);
        *(float4*)&Ws[a][c4] = wv;
    }
    __syncthreads();
    int tx = tid & 15, ty = tid >> 4;
    float acc[4][4] = {};
#pragma unroll
    for (int d = 0; d < 64; d++) {
        float4 a4 = *(float4*)&Xs[d][ty * 4];
        float4 w4 = *(float4*)&Ws[d][tx * 4];
        float av[4] = {a4.x, a4.y, a4.z, a4.w};
        float wv[4] = {w4.x, w4.y, w4.z, w4.w};
#pragma unroll
        for (int i = 0; i < 4; i++)
#pragma unroll
            for (int j = 0; j < 4; j++) acc[i][j] = fmaf(av[i], wv[j], acc[i][j]);
    }
#pragma unroll
    for (int i = 0; i < 4; i++) {
        float4 o = make_float4(acc[i][0], acc[i][1], acc[i][2], acc[i][3]);
        *(float4*)(O + (size_t)(t0 + ty * 4 + i) * DEMB + h * DH + tx * 4) = o;
    }
}

// ---------------- residual add + layernorm (+ optional split-fp16 emit) ----------------
__global__ __launch_bounds__(256) void add_ln(const float* __restrict__ A, const float* __restrict__ B,
                                              const float* __restrict__ g, const float* __restrict__ be,
                                              float* __restrict__ O,
                                              uint16_t* __restrict__ Oh, uint16_t* __restrict__ Ol) {
    int lane = threadIdx.x & 31, wid = threadIdx.x >> 5;
    int row = blockIdx.x * 8 + wid;
    size_t base = (size_t)row * DEMB;
    float4 v[8];
    float s1 = 0.0f, s2 = 0.0f;
#pragma unroll
    for (int p = 0; p < 8; p++) {
        float4 a = ((const float4*)(A + base))[lane + p * 32];
        float4 b = ((const float4*)(B + base))[lane + p * 32];
        float4 t = make_float4(a.x + b.x, a.y + b.y, a.z + b.z, a.w + b.w);
        v[p] = t;
        s1 += t.x + t.y + t.z + t.w;
        s2 += t.x * t.x + t.y * t.y + t.z * t.z + t.w * t.w;
    }
#pragma unroll
    for (int o = 16; o; o >>= 1) {
        s1 += __shfl_xor_sync(0xffffffffu, s1, o);
        s2 += __shfl_xor_sync(0xffffffffu, s2, o);
    }
    float mu = s1 * (1.0f / DEMB);
    float var = s2 * (1.0f / DEMB) - mu * mu;
    float w = rsqrtf(var + 1e-5f);
#pragma unroll
    for (int p = 0; p < 8; p++) {
        float4 gg = ((const float4*)g)[lane + p * 32];
        float4 bb = ((const float4*)be)[lane + p * 32];
        float4 t = v[p];
        float4 o;
        o.x = (t.x - mu) * w * gg.x + bb.x;
        o.y = (t.y - mu) * w * gg.y + bb.y;
        o.z = (t.z - mu) * w * gg.z + bb.z;
        o.w = (t.w - mu) * w * gg.w + bb.w;
        ((float4*)(O + base))[lane + p * 32] = o;
        if (Oh) {
            uint32_t h0, l0, h1, l1;
            split2h(o.x, o.y, h0, l0);
            split2h(o.z, o.w, h1, l1);
            size_t idx = base + (size_t)(lane + p * 32) * 4;
            *(uint32_t*)(Oh + idx) = h0; *(uint32_t*)(Oh + idx + 2) = h1;
            *(uint32_t*)(Ol + idx) = l0; *(uint32_t*)(Ol + idx + 2) = l1;
        }
    }
}

// ---------------- host orchestration ----------------
extern "C" void kernel_launch(void* const* d_in, const int* in_sizes, int n_in,
                              void* d_out, int out_size) {
    const int*   ids   = (const int*)  d_in[0];
    const float* enc_k = (const float*)d_in[1];
    const float* enc_v = (const float*)d_in[2];
    const float* emb   = (const float*)d_in[3];
    const float* Wq_m  = (const float*)d_in[4];
    const float* Wk_m  = (const float*)d_in[5];
    const float* Wv_m  = (const float*)d_in[6];
    const float* Wq_c  = (const float*)d_in[7];
    const float* Wk_c  = (const float*)d_in[8];
    const float* Wv_c  = (const float*)d_in[9];
    const float* ln1_g = (const float*)d_in[10];
    const float* ln1_b = (const float*)d_in[11];
    const float* ln2_g = (const float*)d_in[12];
    const float* ln2_b = (const float*)d_in[13];
    const float* ln3_g = (const float*)d_in[14];
    const float* ln3_b = (const float*)d_in[15];
    const float* W1    = (const float*)d_in[16];
    const float* b1    = (const float*)d_in[17];
    const float* W2    = (const float*)d_in[18];
    const float* b2    = (const float*)d_in[19];
    const float* Wout  = (const float*)d_in[20];
    const float* bout  = (const float*)d_in[21];
    float* out = (float*)d_out;

    float *x, *h1, *h2, *t, *q, *k, *v;
    uint16_t *ah, *al, *fh, *fl, *bth;
    cudaGetSymbolAddress((void**)&x,  g_x);
    cudaGetSymbolAddress((void**)&h1, g_h1);
    cudaGetSymbolAddress((void**)&h2, g_h2);
    cudaGetSymbolAddress((void**)&t,  g_t);
    cudaGetSymbolAddress((void**)&q,  g_q);
    cudaGetSymbolAddress((void**)&k,  g_k);
    cudaGetSymbolAddress((void**)&v,  g_v);
    cudaGetSymbolAddress((void**)&ah,  g_ah);
    cudaGetSymbolAddress((void**)&al,  g_al);
    cudaGetSymbolAddress((void**)&fh,  g_fh);
    cudaGetSymbolAddress((void**)&fl,  g_fl);
    cudaGetSymbolAddress((void**)&bth, g_bth);

    cudaFuncSetAttribute(flash_attn, cudaFuncAttributeMaxDynamicSharedMemorySize, FA_SMEM_BYTES);
    cudaFuncSetAttribute(gemm_cp,   cudaFuncAttributeMaxDynamicSharedMemorySize, GEMM_SMEM);

    dim3 blk(256);
    dim3 projGrid(NTOK / 64, NHEAD, 3);
    dim3 faGrid(SEQ / 128, NB * NHEAD);
    dim3 tblk(256);

    embed_kernel<<<NTOK, blk>>>(ids, emb, x);

    for (int l = 0; l < NLAYER; l++) {
        size_t wOff  = (size_t)l * DH * DH;
        size_t lnOff = (size_t)l * DEMB;
        // --- masked self-attention ---
        proj_head3<<<projGrid, blk>>>(x, x, x, Wq_m + wOff, Wk_m + wOff, Wv_m + wOff, q, k, v);
        flash_attn<<<faGrid, blk, FA_SMEM_BYTES>>>(q, k, v, t, 1);
        add_ln<<<NTOK / 8, blk>>>(t, x, ln1_g + lnOff, ln1_b + lnOff, h1,
                                  (uint16_t*)nullptr, (uint16_t*)nullptr);
        // --- cross-attention ---
        proj_head3<<<projGrid, blk>>>(h1, enc_k, enc_v, Wq_c + wOff, Wk_c + wOff, Wv_c + wOff, q, k, v);
        flash_attn<<<faGrid, blk, FA_SMEM_BYTES>>>(q, k, v, t, 0);
        add_ln<<<NTOK / 8, blk>>>(t, h1, ln2_g + lnOff, ln2_b + lnOff, h2, ah, al);   // emit h2 split
        // --- FFN (2-pass cp.async split-fp16 HMMA, fused split I/O) ---
        cvt_trans<<<dim3(DFF / 32, DEMB / 32), tblk>>>(W1 + (size_t)l * DEMB * DFF, bth, DEMB, DFF);
        gemm_cp<<<dim3(NTOK / 128, DFF / 128), blk, GEMM_SMEM>>>(
            ah, al, bth, b1 + (size_t)l * DFF, (float*)nullptr, fh, fl, DFF, DEMB, 1); // ff -> split
        cvt_trans<<<dim3(DEMB / 32, DFF / 32), tblk>>>(W2 + (size_t)l * DFF * DEMB, bth, DFF, DEMB);
        gemm_cp<<<dim3(NTOK / 128, DEMB / 128), blk, GEMM_SMEM>>>(
            fh, fl, bth, b2 + lnOff, t, (uint16_t*)nullptr, (uint16_t*)nullptr, DEMB, DFF, 0);
        add_ln<<<NTOK / 8, blk>>>(t, h2, ln3_g + lnOff, ln3_b + lnOff, x, ah, al);    // emit x split
    }

    // --- vocab projection (x split already emitted by last add_ln) ---
    cvt_trans<<<dim3(NVOCAB / 32, DEMB / 32), tblk>>>(Wout, bth, DEMB, NVOCAB);
    gemm_cp<<<dim3(NTOK / 128, NVOCAB / 128), blk, GEMM_SMEM>>>(
        ah, al, bth, bout, out, (uint16_t*)nullptr, (uint16_t*)nullptr, NVOCAB, DEMB, 0);
}

// round 12
// speedup vs baseline: 1.2795x; 1.0176x over previous
#include <cuda_runtime.h>
#include <cuda_bf16.h>
#include <cuda_fp16.h>
#include <math.h>
#include <stdint.h>

#define NB 2
#define SEQ 1024
#define NTOK (NB * SEQ)          // 2048
#define DEMB 1024
#define NHEAD 16
#define DH 64
#define DFF 4096
#define NVOCAB 32000
#define NLAYER 6

// -------- scratch (device globals; no allocation allowed) --------
__device__ float g_x [NTOK * DEMB];
__device__ float g_h1[NTOK * DEMB];
__device__ float g_h2[NTOK * DEMB];
__device__ float g_t [NTOK * DEMB];
__device__ float g_q [NTOK * DEMB];
__device__ float g_k [NTOK * DEMB];
__device__ float g_v [NTOK * DEMB];
// split-fp16 staging (uint16 = raw fp16 bits)
__device__ uint16_t g_ah [NTOK * DEMB];            // activation hi (h2 / x)
__device__ uint16_t g_al [NTOK * DEMB];            // activation lo
__device__ uint16_t g_fh [NTOK * DFF];             // ff hi
__device__ uint16_t g_fl [NTOK * DFF];             // ff lo
__device__ uint16_t g_bth[(size_t)NVOCAB * DEMB];  // B^T hi (max 32000x1024)

// ---------------- split-bf16 helper (flash attention only) ----------------
__device__ __forceinline__ void split2(float x0, float x1, uint32_t& hi, uint32_t& lo) {
    uint32_t u0 = __float_as_uint(x0), u1 = __float_as_uint(x1);
    hi = __byte_perm(u0, u1, 0x7632);
    float l0 = x0 - __uint_as_float(u0 & 0xffff0000u);
    float l1 = x1 - __uint_as_float(u1 & 0xffff0000u);
    asm("cvt.rn.bf16x2.f32 %0, %1, %2;" : "=r"(lo) : "f"(l1), "f"(l0));
}

// ---------------- split-fp16 helper: x = hi(fp16 RN) + lo(fp16), |lo|<=2^-12|x| ----------------
__device__ __forceinline__ void split2h(float x0, float x1, uint32_t& hi, uint32_t& lo) {
    __half h0 = __float2half_rn(x0), h1 = __float2half_rn(x1);
    float r0 = x0 - __half2float(h0);
    float r1 = x1 - __half2float(h1);
    __half l0 = __float2half_rn(r0), l1 = __float2half_rn(r1);
    hi = (uint32_t)(*(uint16_t*)&h0) | ((uint32_t)(*(uint16_t*)&h1) << 16);
    lo = (uint32_t)(*(uint16_t*)&l0) | ((uint32_t)(*(uint16_t*)&l1) << 16);
}

// bf16 MMA, fp32 acc (flash attention)
#define MMA(acc, a0, a1, a2, a3, b0, b1)                                        \
    asm("mma.sync.aligned.m16n8k16.row.col.f32.bf16.bf16.f32 "                  \
        "{%0,%1,%2,%3}, {%4,%5,%6,%7}, {%8,%9}, {%0,%1,%2,%3};"                 \
        : "+f"((acc)[0]), "+f"((acc)[1]), "+f"((acc)[2]), "+f"((acc)[3])        \
        : "r"(a0), "r"(a1), "r"(a2), "r"(a3), "r"(b0), "r"(b1))

// fp16 MMA, fp32 acc (GEMM passes)
#define MMAF(acc, a0, a1, a2, a3, b0, b1)                                       \
    asm("mma.sync.aligned.m16n8k16.row.col.f32.f16.f16.f32 "                    \
        "{%0,%1,%2,%3}, {%4,%5,%6,%7}, {%8,%9}, {%0,%1,%2,%3};"                 \
        : "+f"((acc)[0]), "+f"((acc)[1]), "+f"((acc)[2]), "+f"((acc)[3])        \
        : "r"(a0), "r"(a1), "r"(a2), "r"(a3), "r"(b0), "r"(b1))

// warp-collective 4-matrix fragment load
#define LDMX4(r0, r1, r2, r3, addr)                                             \
    asm volatile("ldmatrix.sync.aligned.m8n8.x4.shared.b16 {%0,%1,%2,%3}, [%4];"\
        : "=r"(r0), "=r"(r1), "=r"(r2), "=r"(r3) : "r"(addr))

#define CP_ASYNC16(dst, src) \
    asm volatile("cp.async.cg.shared.global [%0], [%1], 16;" :: "r"(dst), "l"(src))
#define CP_COMMIT() asm volatile("cp.async.commit_group;")
#define CP_WAIT(n)  asm volatile("cp.async.wait_group %0;" :: "n"(n))

__device__ __forceinline__ uint32_t smem_u32(const void* p) {
    uint32_t a;
    asm("{ .reg .u64 t; cvta.to.shared.u64 t, %1; cvt.u32.u64 %0, t; }" : "=r"(a) : "l"(p));
    return a;
}

// ---------------- transpose + fp16 hi only: in[K][N] -> hiT [N][K] ----------------
__global__ __launch_bounds__(256) void cvt_trans(const float* __restrict__ in,
                                                 uint16_t* __restrict__ hiT,
                                                 int K, int N) {
    __shared__ float t[32][33];
    int n0 = blockIdx.x * 32, k0 = blockIdx.y * 32;
    int tx = threadIdx.x & 31, ty = threadIdx.x >> 5;   // 32x8
#pragma unroll
    for (int i = 0; i < 32; i += 8)
        t[ty + i][tx] = in[(size_t)(k0 + ty + i) * N + n0 + tx];
    __syncthreads();
#pragma unroll
    for (int i = 0; i < 32; i += 8) {
        float x = t[tx][ty + i];                         // k = k0+tx, n = n0+ty+i
        __half h = __float2half_rn(x);
        hiT[(size_t)(n0 + ty + i) * K + k0 + tx] = *(uint16_t*)&h;
    }
}

// ============ cp.async pipelined 2-pass split-fp16 HMMA GEMM (ldmatrix frags) ============
// C = (A_hi + A_lo) @ B_hi^T + bias;  dropped term A_hi@B_lo ~ 2^-12 relative.
#define STRIDE 20                         // words per smem row (32 k + pad)
#define TILE_B (128 * STRIDE * 4)         // 10240 bytes per tile
#define BUF_B  (3 * TILE_B)               // Ah, Al, Bh = 30720 bytes
#define GEMM_SMEM (2 * BUF_B)             // 61440

__global__ __launch_bounds__(256, 2) void gemm_cp(const uint16_t* __restrict__ Ahg,
                                                  const uint16_t* __restrict__ Alg,
                                                  const uint16_t* __restrict__ Bth,
                                                  const float* __restrict__ bias,
                                                  float* __restrict__ C,
                                                  uint16_t* __restrict__ Oh,
                                                  uint16_t* __restrict__ Ol,
                                                  int N, int K, int relu) {
    extern __shared__ uint32_t sh[];
    uint32_t sb = smem_u32(sh);
    int tid = threadIdx.x, wid = tid >> 5, lane = tid & 31;
    int bm = blockIdx.x * 128, bn = blockIdx.y * 128;
    int wm = (wid >> 2) * 64, wn = (wid & 3) * 32;
    int r = lane >> 2, c = lane & 3;
    int q = lane >> 3, tt = lane & 7;     // ldmatrix lane roles

    // per-lane ldmatrix byte offsets (within a buffer)
    // A x4: m0=(rows 0-7,k0-7) m1=(rows 8-15,k0-7) m2=(rows 0-7,k8-15) m3=(rows 8-15,k8-15)
    uint32_t aoff = ((uint32_t)(wm + tt + 8 * (q & 1)) * STRIDE + 4 * (q >> 1)) * 4;
    // B x4 over j-pair: m0=(j,k0-7) m1=(j,k8-15) m2=(j+1,k0-7) m3=(j+1,k8-15)
    uint32_t boff = 2 * TILE_B + ((uint32_t)(wn + 8 * (q >> 1) + tt) * STRIDE + 4 * (q & 1)) * 4;

#define ISSUE(kt, buf)                                                          \
    {                                                                           \
        int k0i = (kt) << 5;                                                    \
        _Pragma("unroll")                                                       \
        for (int p = 0; p < 2; p++) {                                           \
            int idx = tid + p * 256;                                            \
            int row = idx >> 2, qq = idx & 3;                                   \
            size_t ao = (size_t)(bm + row) * K + k0i + qq * 8;                  \
            size_t bo = (size_t)(bn + row) * K + k0i + qq * 8;                  \
            uint32_t d = sb + (buf) * BUF_B + row * (STRIDE * 4) + qq * 16;     \
            CP_ASYNC16(d,              Ahg + ao);                               \
            CP_ASYNC16(d + TILE_B,     Alg + ao);                               \
            CP_ASYNC16(d + 2 * TILE_B, Bth + bo);                               \
        }                                                                       \
        CP_COMMIT();                                                            \
    }

    float acc[4][4][4] = {};

    int KT = K >> 5;
    ISSUE(0, 0);
    ISSUE(1, 1);

    for (int kt = 0; kt < KT; kt++) {
        if (kt + 1 < KT) { CP_WAIT(1); } else { CP_WAIT(0); }
        __syncthreads();
        uint32_t bufb = sb + (kt & 1) * BUF_B;
#pragma unroll
        for (int s = 0; s < 2; s++) {
            uint32_t bh[4][2];
#pragma unroll
            for (int p = 0; p < 2; p++) {
                uint32_t addr = bufb + boff + s * 32 + p * (16 * STRIDE * 4);
                LDMX4(bh[2 * p][0], bh[2 * p][1], bh[2 * p + 1][0], bh[2 * p + 1][1], addr);
            }
#pragma unroll
            for (int i = 0; i < 4; i++) {
                uint32_t addrA = bufb + aoff + i * (16 * STRIDE * 4) + s * 32;
                uint32_t ah0, ah1, ah2, ah3, al0, al1, al2, al3;
                LDMX4(ah0, ah1, ah2, ah3, addrA);
                LDMX4(al0, al1, al2, al3, addrA + TILE_B);
#pragma unroll
                for (int j = 0; j < 4; j++) {
                    MMAF(acc[i][j], ah0, ah1, ah2, ah3, bh[j][0], bh[j][1]);   // hi*hi
                    MMAF(acc[i][j], al0, al1, al2, al3, bh[j][0], bh[j][1]);   // lo*hi
                }
            }
        }
        if (kt + 2 < KT) {
            __syncthreads();               // all compute(kt) done before overwriting its buffer
            ISSUE(kt + 2, kt & 1);
        }
    }

#pragma unroll
    for (int i = 0; i < 4; i++) {
#pragma unroll
        for (int j = 0; j < 4; j++) {
            int col = bn + wn + 8 * j + 2 * c;
            int row0 = bm + wm + 16 * i + r;
            float b0 = bias[col], b1 = bias[col + 1];
            float v0 = acc[i][j][0] + b0, v1 = acc[i][j][1] + b1;
            float v2 = acc[i][j][2] + b0, v3 = acc[i][j][3] + b1;
            if (relu) {
                v0 = fmaxf(v0, 0.0f); v1 = fmaxf(v1, 0.0f);
                v2 = fmaxf(v2, 0.0f); v3 = fmaxf(v3, 0.0f);
            }
            if (Oh) {
                uint32_t h0, l0, h1, l1;
                split2h(v0, v1, h0, l0);
                split2h(v2, v3, h1, l1);
                size_t o0 = (size_t)row0 * N + col;
                size_t o1 = (size_t)(row0 + 8) * N + col;
                *(uint32_t*)(Oh + o0) = h0; *(uint32_t*)(Ol + o0) = l0;
                *(uint32_t*)(Oh + o1) = h1; *(uint32_t*)(Ol + o1) = l1;
            } else {
                *(float2*)(C + (size_t)row0 * N + col) = make_float2(v0, v1);
                *(float2*)(C + (size_t)(row0 + 8) * N + col) = make_float2(v2, v3);
            }
        }
    }
}

// ============ fused flash attention (split-bf16 HMMA, online softmax, 1e-19 mask quirk) ============
#define FA_SMEM_WORDS (4608 + 4608 + 4352 + 4352)
#define FA_SMEM_BYTES (FA_SMEM_WORDS * 4)
__global__ __launch_bounds__(256) void flash_attn(const float* __restrict__ Qg,
                                                  const float* __restrict__ Kg,
                                                  const float* __restrict__ Vg,
                                                  float* __restrict__ Og, int causal) {
    extern __shared__ uint32_t sm[];
    uint32_t* Kh = sm;
    uint32_t* Kl = sm + 4608;
    uint32_t* Vh = sm + 9216;
    uint32_t* Vl = sm + 13568;
    int tid = threadIdx.x, wid = tid >> 5, lane = tid & 31;
    int r = lane >> 2, c = lane & 3;
    int b = blockIdx.y >> 4, h = blockIdx.y & 15;
    const float* Qb = Qg + (size_t)b * SEQ * DEMB + h * DH;
    const float* Kb = Kg + (size_t)b * SEQ * DEMB + h * DH;
    const float* Vb = Vg + (size_t)b * SEQ * DEMB + h * DH;
    int q0 = blockIdx.x * 128;
    int grow = q0 + wid * 16 + r;

    uint32_t qh[4][4], ql[4][4];
#pragma unroll
    for (int s = 0; s < 4; s++) {
        const float* q0p = Qb + (size_t)grow * DEMB + s * 16;
        const float* q1p = q0p + 8 * DEMB;
        float2 v0 = *(const float2*)(q0p + 2 * c);
        float2 v1 = *(const float2*)(q1p + 2 * c);
        float2 v2 = *(const float2*)(q0p + 2 * c + 8);
        float2 v3 = *(const float2*)(q1p + 2 * c + 8);
        split2(v0.x, v0.y, qh[s][0], ql[s][0]);
        split2(v1.x, v1.y, qh[s][1], ql[s][1]);
        split2(v2.x, v2.y, qh[s][2], ql[s][2]);
        split2(v3.x, v3.y, qh[s][3], ql[s][3]);
    }

    float oacc[8][4] = {};
    float m0 = -1e30f, m1 = -1e30f, l0 = 0.0f, l1 = 0.0f;

    for (int kt = 0; kt < SEQ / 128; kt++) {
        int k0 = kt * 128;
        __syncthreads();
#pragma unroll
        for (int p = 0; p < 16; p++) {
            int idx = tid + p * 256;
            int row = idx >> 5, kp = idx & 31;
            float2 kv = *(const float2*)(Kb + (size_t)(k0 + row) * DEMB + kp * 2);
            uint32_t hh, ll; split2(kv.x, kv.y, hh, ll);
            Kh[row * 36 + kp] = hh; Kl[row * 36 + kp] = ll;
        }
#pragma unroll
        for (int p = 0; p < 16; p++) {
            int idx = tid + p * 256;
            int d = idx & 63, kp = idx >> 6;
            float x0 = Vb[(size_t)(k0 + kp * 2) * DEMB + d];
            float x1 = Vb[(size_t)(k0 + kp * 2 + 1) * DEMB + d];
            uint32_t hh, ll; split2(x0, x1, hh, ll);
            Vh[d * 68 + kp] = hh; Vl[d * 68 + kp] = ll;
        }
        __syncthreads();

        float sacc[16][4];
#pragma unroll
        for (int j = 0; j < 16; j++) { sacc[j][0] = sacc[j][1] = sacc[j][2] = sacc[j][3] = 0.0f; }
#pragma unroll
        for (int j = 0; j < 16; j++) {
#pragma unroll
            for (int s = 0; s < 4; s++) {
                int o = (8 * j + r) * 36 + 8 * s + c;
                uint32_t kh0 = Kh[o], kh1 = Kh[o + 4];
                uint32_t kl0 = Kl[o], kl1 = Kl[o + 4];
                MMA(sacc[j], qh[s][0], qh[s][1], qh[s][2], qh[s][3], kh0, kh1);
                MMA(sacc[j], qh[s][0], qh[s][1], qh[s][2], qh[s][3], kl0, kl1);
                MMA(sacc[j], ql[s][0], ql[s][1], ql[s][2], ql[s][3], kh0, kh1);
            }
        }
        float tm0 = -1e30f, tm1 = -1e30f;
#pragma unroll
        for (int j = 0; j < 16; j++) {
            int col = k0 + 8 * j + 2 * c;
            float v0 = sacc[j][0] * 0.125f, v1 = sacc[j][1] * 0.125f;
            float v2 = sacc[j][2] * 0.125f, v3 = sacc[j][3] * 0.125f;
            if (causal) {
                if (col     > grow)     v0 = 1e-19f;
                if (col + 1 > grow)     v1 = 1e-19f;
                if (col     > grow + 8) v2 = 1e-19f;
                if (col + 1 > grow + 8) v3 = 1e-19f;
            }
            sacc[j][0] = v0; sacc[j][1] = v1; sacc[j][2] = v2; sacc[j][3] = v3;
            tm0 = fmaxf(tm0, fmaxf(v0, v1));
            tm1 = fmaxf(tm1, fmaxf(v2, v3));
        }
        tm0 = fmaxf(tm0, __shfl_xor_sync(0xffffffffu, tm0, 1));
        tm0 = fmaxf(tm0, __shfl_xor_sync(0xffffffffu, tm0, 2));
        tm1 = fmaxf(tm1, __shfl_xor_sync(0xffffffffu, tm1, 1));
        tm1 = fmaxf(tm1, __shfl_xor_sync(0xffffffffu, tm1, 2));
        float mn0 = fmaxf(m0, tm0), mn1 = fmaxf(m1, tm1);
        float sc0 = __expf(m0 - mn0), sc1 = __expf(m1 - mn1);
        m0 = mn0; m1 = mn1;
        float rs0 = 0.0f, rs1 = 0.0f;
#pragma unroll
        for (int j = 0; j < 16; j++) {
            float p0 = __expf(sacc[j][0] - m0), p1 = __expf(sacc[j][1] - m0);
            float p2 = __expf(sacc[j][2] - m1), p3 = __expf(sacc[j][3] - m1);
            sacc[j][0] = p0; sacc[j][1] = p1; sacc[j][2] = p2; sacc[j][3] = p3;
            rs0 += p0 + p1; rs1 += p2 + p3;
        }
        rs0 += __shfl_xor_sync(0xffffffffu, rs0, 1);
        rs0 += __shfl_xor_sync(0xffffffffu, rs0, 2);
        rs1 += __shfl_xor_sync(0xffffffffu, rs1, 1);
        rs1 += __shfl_xor_sync(0xffffffffu, rs1, 2);
        l0 = l0 * sc0 + rs0; l1 = l1 * sc1 + rs1;
#pragma unroll
        for (int j2 = 0; j2 < 8; j2++) {
            oacc[j2][0] *= sc0; oacc[j2][1] *= sc0;
            oacc[j2][2] *= sc1; oacc[j2][3] *= sc1;
        }
#pragma unroll
        for (int s2 = 0; s2 < 8; s2++) {
            uint32_t a0h, a0l, a1h, a1l, a2h, a2l, a3h, a3l;
            split2(sacc[2 * s2][0],     sacc[2 * s2][1],     a0h, a0l);
            split2(sacc[2 * s2][2],     sacc[2 * s2][3],     a1h, a1l);
            split2(sacc[2 * s2 + 1][0], sacc[2 * s2 + 1][1], a2h, a2l);
            split2(sacc[2 * s2 + 1][2], sacc[2 * s2 + 1][3], a3h, a3l);
#pragma unroll
            for (int j2 = 0; j2 < 8; j2++) {
                int o = (8 * j2 + r) * 68 + 8 * s2 + c;
                uint32_t vh0 = Vh[o], vh1 = Vh[o + 4];
                uint32_t vl0 = Vl[o], vl1 = Vl[o + 4];
                MMA(oacc[j2], a0h, a1h, a2h, a3h, vh0, vh1);
                MMA(oacc[j2], a0h, a1h, a2h, a3h, vl0, vl1);
                MMA(oacc[j2], a0l, a1l, a2l, a3l, vh0, vh1);
            }
        }
    }
    float i0 = 1.0f / l0, i1 = 1.0f / l1;
#pragma unroll
    for (int j2 = 0; j2 < 8; j2++) {
        float* op = Og + (size_t)(b * SEQ + grow) * DEMB + h * DH + 8 * j2 + 2 * c;
        *(float2*)op = make_float2(oacc[j2][0] * i0, oacc[j2][1] * i0);
        *(float2*)(op + 8 * DEMB) = make_float2(oacc[j2][2] * i1, oacc[j2][3] * i1);
    }
}

// ---------------- embedding + positional encoding ----------------
__global__ __launch_bounds__(256) void embed_kernel(const int* __restrict__ ids,
                                                    const float* __restrict__ emb,
                                                    float* __restrict__ X) {
    int t = blockIdx.x;
    int pos = t & (SEQ - 1);
    int id = ids[t];
    int d0 = threadIdx.x * 4;
    float4 e4 = *(const float4*)(emb + (size_t)id * DEMB + d0);
    float ev[4] = {e4.x, e4.y, e4.z, e4.w};
    float ov[4];
#pragma unroll
    for (int j = 0; j < 4; j++) {
        int d = d0 + j;
        float ang = (float)pos * powf(10000.0f, -2.0f * (float)d / (float)DEMB);
        float pe = ((d & 1) == 0) ? sinf(ang) : cosf(ang);
        ov[j] = ev[j] * 32.0f + pe;
    }
    *(float4*)(X + (size_t)t * DEMB + d0) = make_float4(ov[0], ov[1], ov[2], ov[3]);
}

// ---------------- fused q/k/v per-head projection (grid.z selects) ----------------
__global__ __launch_bounds__(256) void proj_head3(
        const float* __restrict__ X0, const float* __restrict__ X1, const float* __restrict__ X2,
        const float* __restrict__ W0, const float* __restrict__ W1, const float* __restrict__ W2,
        float* __restrict__ O0, float* __restrict__ O1, float* __restrict__ O2) {
    const float* X; const float* W; float* O;
    if (blockIdx.z == 0)      { X = X0; W = W0; O = O0; }
    else if (blockIdx.z == 1) { X = X1; W = W1; O = O1; }
    else                      { X = X2; W = W2; O = O2; }
    __shared__ float Xs[64][64];
    __shared__ float Ws[64][64];
    int tid = threadIdx.x;
    int h = blockIdx.y;
    int t0 = blockIdx.x * 64;
#pragma unroll
    for (int r = 0; r < 4; r++) {
        int idx = tid + r * 256;
        int a = idx >> 4;
        int c4 = (idx & 15) << 2;
        float4 xv = *(const float4*)(X + (size_t)(t0 + a) * DEMB + h * DH + c4);
        Xs[c4 + 0][a] = xv.x; Xs[c4 + 1][a] = xv.y; Xs[c4 + 2][a] = xv.z; Xs[c4 + 3][a] = xv.w;
        float4 wv = *(const float4*)(W + a * DH + c4);
        *(float4*)&Ws[a][c4] = wv;
    }
    __syncthreads();
    int tx = tid & 15, ty = tid >> 4;
    float acc[4][4] = {};
#pragma unroll
    for (int d = 0; d < 64; d++) {
        float4 a4 = *(float4*)&Xs[d][ty * 4];
        float4 w4 = *(float4*)&Ws[d][tx * 4];
        float av[4] = {a4.x, a4.y, a4.z, a4.w};
        float wv[4] = {w4.x, w4.y, w4.z, w4.w};
#pragma unroll
        for (int i = 0; i < 4; i++)
#pragma unroll
            for (int j = 0; j < 4; j++) acc[i][j] = fmaf(av[i], wv[j], acc[i][j]);
    }
#pragma unroll
    for (int i = 0; i < 4; i++) {
        float4 o = make_float4(acc[i][0], acc[i][1], acc[i][2], acc[i][3]);
        *(float4*)(O + (size_t)(t0 + ty * 4 + i) * DEMB + h * DH + tx * 4) = o;
    }
}

// ---------------- residual add + layernorm (+ optional split-fp16 emit) ----------------
__global__ __launch_bounds__(256) void add_ln(const float* __restrict__ A, const float* __restrict__ B,
                                              const float* __restrict__ g, const float* __restrict__ be,
                                              float* __restrict__ O,
                                              uint16_t* __restrict__ Oh, uint16_t* __restrict__ Ol) {
    int lane = threadIdx.x & 31, wid = threadIdx.x >> 5;
    int row = blockIdx.x * 8 + wid;
    size_t base = (size_t)row * DEMB;
    float4 v[8];
    float s1 = 0.0f, s2 = 0.0f;
#pragma unroll
    for (int p = 0; p < 8; p++) {
        float4 a = ((const float4*)(A + base))[lane + p * 32];
        float4 b = ((const float4*)(B + base))[lane + p * 32];
        float4 t = make_float4(a.x + b.x, a.y + b.y, a.z + b.z, a.w + b.w);
        v[p] = t;
        s1 += t.x + t.y + t.z + t.w;
        s2 += t.x * t.x + t.y * t.y + t.z * t.z + t.w * t.w;
    }
#pragma unroll
    for (int o = 16; o; o >>= 1) {
        s1 += __shfl_xor_sync(0xffffffffu, s1, o);
        s2 += __shfl_xor_sync(0xffffffffu, s2, o);
    }
    float mu = s1 * (1.0f / DEMB);
    float var = s2 * (1.0f / DEMB) - mu * mu;
    float w = rsqrtf(var + 1e-5f);
#pragma unroll
    for (int p = 0; p < 8; p++) {
        float4 gg = ((const float4*)g)[lane + p * 32];
        float4 bb = ((const float4*)be)[lane + p * 32];
        float4 t = v[p];
        float4 o;
        o.x = (t.x - mu) * w * gg.x + bb.x;
        o.y = (t.y - mu) * w * gg.y + bb.y;
        o.z = (t.z - mu) * w * gg.z + bb.z;
        o.w = (t.w - mu) * w * gg.w + bb.w;
        ((float4*)(O + base))[lane + p * 32] = o;
        if (Oh) {
            uint32_t h0, l0, h1, l1;
            split2h(o.x, o.y, h0, l0);
            split2h(o.z, o.w, h1, l1);
            size_t idx = base + (size_t)(lane + p * 32) * 4;
            *(uint32_t*)(Oh + idx) = h0; *(uint32_t*)(Oh + idx + 2) = h1;
            *(uint32_t*)(Ol + idx) = l0; *(uint32_t*)(Ol + idx + 2) = l1;
        }
    }
}

// ---------------- host orchestration ----------------
extern "C" void kernel_launch(void* const* d_in, const int* in_sizes, int n_in,
                              void* d_out, int out_size) {
    const int*   ids   = (const int*)  d_in[0];
    const float* enc_k = (const float*)d_in[1];
    const float* enc_v = (const float*)d_in[2];
    const float* emb   = (const float*)d_in[3];
    const float* Wq_m  = (const float*)d_in[4];
    const float* Wk_m  = (const float*)d_in[5];
    const float* Wv_m  = (const float*)d_in[6];
    const float* Wq_c  = (const float*)d_in[7];
    const float* Wk_c  = (const float*)d_in[8];
    const float* Wv_c  = (const float*)d_in[9];
    const float* ln1_g = (const float*)d_in[10];
    const float* ln1_b = (const float*)d_in[11];
    const float* ln2_g = (const float*)d_in[12];
    const float* ln2_b = (const float*)d_in[13];
    const float* ln3_g = (const float*)d_in[14];
    const float* ln3_b = (const float*)d_in[15];
    const float* W1    = (const float*)d_in[16];
    const float* b1    = (const float*)d_in[17];
    const float* W2    = (const float*)d_in[18];
    const float* b2    = (const float*)d_in[19];
    const float* Wout  = (const float*)d_in[20];
    const float* bout  = (const float*)d_in[21];
    float* out = (float*)d_out;

    float *x, *h1, *h2, *t, *q, *k, *v;
    uint16_t *ah, *al, *fh, *fl, *bth;
    cudaGetSymbolAddress((void**)&x,  g_x);
    cudaGetSymbolAddress((void**)&h1, g_h1);
    cudaGetSymbolAddress((void**)&h2, g_h2);
    cudaGetSymbolAddress((void**)&t,  g_t);
    cudaGetSymbolAddress((void**)&q,  g_q);
    cudaGetSymbolAddress((void**)&k,  g_k);
    cudaGetSymbolAddress((void**)&v,  g_v);
    cudaGetSymbolAddress((void**)&ah,  g_ah);
    cudaGetSymbolAddress((void**)&al,  g_al);
    cudaGetSymbolAddress((void**)&fh,  g_fh);
    cudaGetSymbolAddress((void**)&fl,  g_fl);
    cudaGetSymbolAddress((void**)&bth, g_bth);

    cudaFuncSetAttribute(flash_attn, cudaFuncAttributeMaxDynamicSharedMemorySize, FA_SMEM_BYTES);
    cudaFuncSetAttribute(gemm_cp,   cudaFuncAttributeMaxDynamicSharedMemorySize, GEMM_SMEM);

    dim3 blk(256);
    dim3 projGrid(NTOK / 64, NHEAD, 3);
    dim3 faGrid(SEQ / 128, NB * NHEAD);
    dim3 tblk(256);

    embed_kernel<<<NTOK, blk>>>(ids, emb, x);

    for (int l = 0; l < NLAYER; l++) {
        size_t wOff  = (size_t)l * DH * DH;
        size_t lnOff = (size_t)l * DEMB;
        // --- masked self-attention ---
        proj_head3<<<projGrid, blk>>>(x, x, x, Wq_m + wOff, Wk_m + wOff, Wv_m + wOff, q, k, v);
        flash_attn<<<faGrid, blk, FA_SMEM_BYTES>>>(q, k, v, t, 1);
        add_ln<<<NTOK / 8, blk>>>(t, x, ln1_g + lnOff, ln1_b + lnOff, h1,
                                  (uint16_t*)nullptr, (uint16_t*)nullptr);
        // --- cross-attention ---
        proj_head3<<<projGrid, blk>>>(h1, enc_k, enc_v, Wq_c + wOff, Wk_c + wOff, Wv_c + wOff, q, k, v);
        flash_attn<<<faGrid, blk, FA_SMEM_BYTES>>>(q, k, v, t, 0);
        add_ln<<<NTOK / 8, blk>>>(t, h1, ln2_g + lnOff, ln2_b + lnOff, h2, ah, al);   // emit h2 split
        // --- FFN (2-pass cp.async split-fp16 HMMA, ldmatrix frags) ---
        cvt_trans<<<dim3(DFF / 32, DEMB / 32), tblk>>>(W1 + (size_t)l * DEMB * DFF, bth, DEMB, DFF);
        gemm_cp<<<dim3(NTOK / 128, DFF / 128), blk, GEMM_SMEM>>>(
            ah, al, bth, b1 + (size_t)l * DFF, (float*)nullptr, fh, fl, DFF, DEMB, 1); // ff -> split
        cvt_trans<<<dim3(DEMB / 32, DFF / 32), tblk>>>(W2 + (size_t)l * DFF * DEMB, bth, DFF, DEMB);
        gemm_cp<<<dim3(NTOK / 128, DEMB / 128), blk, GEMM_SMEM>>>(
            fh, fl, bth, b2 + lnOff, t, (uint16_t*)nullptr, (uint16_t*)nullptr, DEMB, DFF, 0);
        add_ln<<<NTOK / 8, blk>>>(t, h2, ln3_g + lnOff, ln3_b + lnOff, x, ah, al);    // emit x split
    }

    // --- vocab projection (x split already emitted by last add_ln) ---
    cvt_trans<<<dim3(NVOCAB / 32, DEMB / 32), tblk>>>(Wout, bth, DEMB, NVOCAB);
    gemm_cp<<<dim3(NTOK / 128, NVOCAB / 128), blk, GEMM_SMEM>>>(
        ah, al, bth, bout, out, (uint16_t*)nullptr, (uint16_t*)nullptr, NVOCAB, DEMB, 0);
}

// round 13
// speedup vs baseline: 1.3474x; 1.0531x over previous
#include <cuda_runtime.h>
#include <cuda_bf16.h>
#include <cuda_fp16.h>
#include <math.h>
#include <stdint.h>

#define NB 2
#define SEQ 1024
#define NTOK (NB * SEQ)          // 2048
#define DEMB 1024
#define NHEAD 16
#define DH 64
#define DFF 4096
#define NVOCAB 32000
#define NLAYER 6

// -------- scratch (device globals; no allocation allowed) --------
__device__ float g_x [NTOK * DEMB];
__device__ float g_h1[NTOK * DEMB];
__device__ float g_h2[NTOK * DEMB];
__device__ float g_t [NTOK * DEMB];
__device__ float g_q [NTOK * DEMB];
__device__ float g_k [NTOK * DEMB];
__device__ float g_v [NTOK * DEMB];
// split-fp16 staging (uint16 = raw fp16 bits)
__device__ uint16_t g_ah [NTOK * DEMB];            // activation hi (h2 / x)
__device__ uint16_t g_al [NTOK * DEMB];            // activation lo
__device__ uint16_t g_fh [NTOK * DFF];             // ff hi
__device__ uint16_t g_fl [NTOK * DFF];             // ff lo
__device__ uint16_t g_bth[(size_t)NVOCAB * DEMB];  // B^T hi (max 32000x1024)

// ---------------- split-fp16 helper: x = hi(fp16 RN) + lo(fp16), |lo|<=2^-12|x| ----------------
__device__ __forceinline__ void split2h(float x0, float x1, uint32_t& hi, uint32_t& lo) {
    __half h0 = __float2half_rn(x0), h1 = __float2half_rn(x1);
    float r0 = x0 - __half2float(h0);
    float r1 = x1 - __half2float(h1);
    __half l0 = __float2half_rn(r0), l1 = __float2half_rn(r1);
    hi = (uint32_t)(*(uint16_t*)&h0) | ((uint32_t)(*(uint16_t*)&h1) << 16);
    lo = (uint32_t)(*(uint16_t*)&l0) | ((uint32_t)(*(uint16_t*)&l1) << 16);
}
__device__ __forceinline__ uint32_t pack2h(float x0, float x1) {
    __half2 h = __floats2half2_rn(x0, x1);
    return *(uint32_t*)&h;
}

// fp16 MMA, fp32 acc
#define MMAF(acc, a0, a1, a2, a3, b0, b1)                                       \
    asm("mma.sync.aligned.m16n8k16.row.col.f32.f16.f16.f32 "                    \
        "{%0,%1,%2,%3}, {%4,%5,%6,%7}, {%8,%9}, {%0,%1,%2,%3};"                 \
        : "+f"((acc)[0]), "+f"((acc)[1]), "+f"((acc)[2]), "+f"((acc)[3])        \
        : "r"(a0), "r"(a1), "r"(a2), "r"(a3), "r"(b0), "r"(b1))

// warp-collective 4-matrix fragment load
#define LDMX4(r0, r1, r2, r3, addr)                                             \
    asm volatile("ldmatrix.sync.aligned.m8n8.x4.shared.b16 {%0,%1,%2,%3}, [%4];"\
        : "=r"(r0), "=r"(r1), "=r"(r2), "=r"(r3) : "r"(addr))

#define CP_ASYNC16(dst, src) \
    asm volatile("cp.async.cg.shared.global [%0], [%1], 16;" :: "r"(dst), "l"(src))
#define CP_COMMIT() asm volatile("cp.async.commit_group;")
#define CP_WAIT(n)  asm volatile("cp.async.wait_group %0;" :: "n"(n))

__device__ __forceinline__ uint32_t smem_u32(const void* p) {
    uint32_t a;
    asm("{ .reg .u64 t; cvta.to.shared.u64 t, %1; cvt.u32.u64 %0, t; }" : "=r"(a) : "l"(p));
    return a;
}

// ---------------- transpose + fp16 hi only: in[K][N] -> hiT [N][K] ----------------
__global__ __launch_bounds__(256) void cvt_trans(const float* __restrict__ in,
                                                 uint16_t* __restrict__ hiT,
                                                 int K, int N) {
    __shared__ float t[32][33];
    int n0 = blockIdx.x * 32, k0 = blockIdx.y * 32;
    int tx = threadIdx.x & 31, ty = threadIdx.x >> 5;   // 32x8
#pragma unroll
    for (int i = 0; i < 32; i += 8)
        t[ty + i][tx] = in[(size_t)(k0 + ty + i) * N + n0 + tx];
    __syncthreads();
#pragma unroll
    for (int i = 0; i < 32; i += 8) {
        float x = t[tx][ty + i];                         // k = k0+tx, n = n0+ty+i
        __half h = __float2half_rn(x);
        hiT[(size_t)(n0 + ty + i) * K + k0 + tx] = *(uint16_t*)&h;
    }
}

// ============ cp.async pipelined 2-pass split-fp16 HMMA GEMM (ldmatrix frags) ============
// C = (A_hi + A_lo) @ B_hi^T + bias;  dropped term A_hi@B_lo ~ 2^-12 relative.
#define STRIDE 20                         // words per smem row (32 k + pad)
#define TILE_B (128 * STRIDE * 4)         // 10240 bytes per tile
#define BUF_B  (3 * TILE_B)               // Ah, Al, Bh = 30720 bytes
#define GEMM_SMEM (2 * BUF_B)             // 61440

__global__ __launch_bounds__(256, 2) void gemm_cp(const uint16_t* __restrict__ Ahg,
                                                  const uint16_t* __restrict__ Alg,
                                                  const uint16_t* __restrict__ Bth,
                                                  const float* __restrict__ bias,
                                                  float* __restrict__ C,
                                                  uint16_t* __restrict__ Oh,
                                                  uint16_t* __restrict__ Ol,
                                                  int N, int K, int relu) {
    extern __shared__ uint32_t sh[];
    uint32_t sb = smem_u32(sh);
    int tid = threadIdx.x, wid = tid >> 5, lane = tid & 31;
    int bm = blockIdx.x * 128, bn = blockIdx.y * 128;
    int wm = (wid >> 2) * 64, wn = (wid & 3) * 32;
    int r = lane >> 2, c = lane & 3;
    int q = lane >> 3, tt = lane & 7;     // ldmatrix lane roles

    uint32_t aoff = ((uint32_t)(wm + tt + 8 * (q & 1)) * STRIDE + 4 * (q >> 1)) * 4;
    uint32_t boff = 2 * TILE_B + ((uint32_t)(wn + 8 * (q >> 1) + tt) * STRIDE + 4 * (q & 1)) * 4;

#define ISSUE(kt, buf)                                                          \
    {                                                                           \
        int k0i = (kt) << 5;                                                    \
        _Pragma("unroll")                                                       \
        for (int p = 0; p < 2; p++) {                                           \
            int idx = tid + p * 256;                                            \
            int row = idx >> 2, qq = idx & 3;                                   \
            size_t ao = (size_t)(bm + row) * K + k0i + qq * 8;                  \
            size_t bo = (size_t)(bn + row) * K + k0i + qq * 8;                  \
            uint32_t d = sb + (buf) * BUF_B + row * (STRIDE * 4) + qq * 16;     \
            CP_ASYNC16(d,              Ahg + ao);                               \
            CP_ASYNC16(d + TILE_B,     Alg + ao);                               \
            CP_ASYNC16(d + 2 * TILE_B, Bth + bo);                               \
        }                                                                       \
        CP_COMMIT();                                                            \
    }

    float acc[4][4][4] = {};

    int KT = K >> 5;
    ISSUE(0, 0);
    ISSUE(1, 1);

    for (int kt = 0; kt < KT; kt++) {
        if (kt + 1 < KT) { CP_WAIT(1); } else { CP_WAIT(0); }
        __syncthreads();
        uint32_t bufb = sb + (kt & 1) * BUF_B;
#pragma unroll
        for (int s = 0; s < 2; s++) {
            uint32_t bh[4][2];
#pragma unroll
            for (int p = 0; p < 2; p++) {
                uint32_t addr = bufb + boff + s * 32 + p * (16 * STRIDE * 4);
                LDMX4(bh[2 * p][0], bh[2 * p][1], bh[2 * p + 1][0], bh[2 * p + 1][1], addr);
            }
#pragma unroll
            for (int i = 0; i < 4; i++) {
                uint32_t addrA = bufb + aoff + i * (16 * STRIDE * 4) + s * 32;
                uint32_t ah0, ah1, ah2, ah3, al0, al1, al2, al3;
                LDMX4(ah0, ah1, ah2, ah3, addrA);
                LDMX4(al0, al1, al2, al3, addrA + TILE_B);
#pragma unroll
                for (int j = 0; j < 4; j++) {
                    MMAF(acc[i][j], ah0, ah1, ah2, ah3, bh[j][0], bh[j][1]);   // hi*hi
                    MMAF(acc[i][j], al0, al1, al2, al3, bh[j][0], bh[j][1]);   // lo*hi
                }
            }
        }
        if (kt + 2 < KT) {
            __syncthreads();               // all compute(kt) done before overwriting its buffer
            ISSUE(kt + 2, kt & 1);
        }
    }

#pragma unroll
    for (int i = 0; i < 4; i++) {
#pragma unroll
        for (int j = 0; j < 4; j++) {
            int col = bn + wn + 8 * j + 2 * c;
            int row0 = bm + wm + 16 * i + r;
            float b0 = bias[col], b1 = bias[col + 1];
            float v0 = acc[i][j][0] + b0, v1 = acc[i][j][1] + b1;
            float v2 = acc[i][j][2] + b0, v3 = acc[i][j][3] + b1;
            if (relu) {
                v0 = fmaxf(v0, 0.0f); v1 = fmaxf(v1, 0.0f);
                v2 = fmaxf(v2, 0.0f); v3 = fmaxf(v3, 0.0f);
            }
            if (Oh) {
                uint32_t h0, l0, h1, l1;
                split2h(v0, v1, h0, l0);
                split2h(v2, v3, h1, l1);
                size_t o0 = (size_t)row0 * N + col;
                size_t o1 = (size_t)(row0 + 8) * N + col;
                *(uint32_t*)(Oh + o0) = h0; *(uint32_t*)(Ol + o0) = l0;
                *(uint32_t*)(Oh + o1) = h1; *(uint32_t*)(Ol + o1) = l1;
            } else {
                *(float2*)(C + (size_t)row0 * N + col) = make_float2(v0, v1);
                *(float2*)(C + (size_t)(row0 + 8) * N + col) = make_float2(v2, v3);
            }
        }
    }
}

// ============ fused flash attention (2-pass split-fp16 HMMA, online softmax, 1e-19 mask) ============
// K/V tiles store hi only; A-side (Q, P) carries hi+lo. Dropped hi*lo terms ~2^-12.
#define FA_SMEM_WORDS (4608 + 4352)       // Kh[128][36], Vh[64][68]
#define FA_SMEM_BYTES (FA_SMEM_WORDS * 4)
__global__ __launch_bounds__(256) void flash_attn(const float* __restrict__ Qg,
                                                  const float* __restrict__ Kg,
                                                  const float* __restrict__ Vg,
                                                  float* __restrict__ Og, int causal) {
    extern __shared__ uint32_t sm[];
    uint32_t* Kh = sm;
    uint32_t* Vh = sm + 4608;
    int tid = threadIdx.x, wid = tid >> 5, lane = tid & 31;
    int r = lane >> 2, c = lane & 3;
    int b = blockIdx.y >> 4, h = blockIdx.y & 15;
    const float* Qb = Qg + (size_t)b * SEQ * DEMB + h * DH;
    const float* Kb = Kg + (size_t)b * SEQ * DEMB + h * DH;
    const float* Vb = Vg + (size_t)b * SEQ * DEMB + h * DH;
    int q0 = blockIdx.x * 128;
    int grow = q0 + wid * 16 + r;

    uint32_t qh[4][4], ql[4][4];
#pragma unroll
    for (int s = 0; s < 4; s++) {
        const float* q0p = Qb + (size_t)grow * DEMB + s * 16;
        const float* q1p = q0p + 8 * DEMB;
        float2 v0 = *(const float2*)(q0p + 2 * c);
        float2 v1 = *(const float2*)(q1p + 2 * c);
        float2 v2 = *(const float2*)(q0p + 2 * c + 8);
        float2 v3 = *(const float2*)(q1p + 2 * c + 8);
        split2h(v0.x, v0.y, qh[s][0], ql[s][0]);
        split2h(v1.x, v1.y, qh[s][1], ql[s][1]);
        split2h(v2.x, v2.y, qh[s][2], ql[s][2]);
        split2h(v3.x, v3.y, qh[s][3], ql[s][3]);
    }

    float oacc[8][4] = {};
    float m0 = -1e30f, m1 = -1e30f, l0 = 0.0f, l1 = 0.0f;

    for (int kt = 0; kt < SEQ / 128; kt++) {
        int k0 = kt * 128;
        __syncthreads();
        // ---- fill K tile (hi only): [key][kp(d)] ----
#pragma unroll
        for (int p = 0; p < 16; p++) {
            int idx = tid + p * 256;
            int row = idx >> 5, kp = idx & 31;
            float2 kv = *(const float2*)(Kb + (size_t)(k0 + row) * DEMB + kp * 2);
            Kh[row * 36 + kp] = pack2h(kv.x, kv.y);
        }
        // ---- fill V tile (hi only, transposed): [d][kp(key)] ----
#pragma unroll
        for (int p = 0; p < 16; p++) {
            int idx = tid + p * 256;
            int d = idx & 63, kp = idx >> 6;
            float x0 = Vb[(size_t)(k0 + kp * 2) * DEMB + d];
            float x1 = Vb[(size_t)(k0 + kp * 2 + 1) * DEMB + d];
            Vh[d * 68 + kp] = pack2h(x0, x1);
        }
        __syncthreads();

        // ---- S = Q K^T (2-pass split-fp16) ----
        float sacc[16][4];
#pragma unroll
        for (int j = 0; j < 16; j++) { sacc[j][0] = sacc[j][1] = sacc[j][2] = sacc[j][3] = 0.0f; }
#pragma unroll
        for (int j = 0; j < 16; j++) {
#pragma unroll
            for (int s = 0; s < 4; s++) {
                int o = (8 * j + r) * 36 + 8 * s + c;
                uint32_t kh0 = Kh[o], kh1 = Kh[o + 4];
                MMAF(sacc[j], qh[s][0], qh[s][1], qh[s][2], qh[s][3], kh0, kh1);
                MMAF(sacc[j], ql[s][0], ql[s][1], ql[s][2], ql[s][3], kh0, kh1);
            }
        }
        float tm0 = -1e30f, tm1 = -1e30f;
#pragma unroll
        for (int j = 0; j < 16; j++) {
            int col = k0 + 8 * j + 2 * c;
            float v0 = sacc[j][0] * 0.125f, v1 = sacc[j][1] * 0.125f;
            float v2 = sacc[j][2] * 0.125f, v3 = sacc[j][3] * 0.125f;
            if (causal) {
                if (col     > grow)     v0 = 1e-19f;
                if (col + 1 > grow)     v1 = 1e-19f;
                if (col     > grow + 8) v2 = 1e-19f;
                if (col + 1 > grow + 8) v3 = 1e-19f;
            }
            sacc[j][0] = v0; sacc[j][1] = v1; sacc[j][2] = v2; sacc[j][3] = v3;
            tm0 = fmaxf(tm0, fmaxf(v0, v1));
            tm1 = fmaxf(tm1, fmaxf(v2, v3));
        }
        tm0 = fmaxf(tm0, __shfl_xor_sync(0xffffffffu, tm0, 1));
        tm0 = fmaxf(tm0, __shfl_xor_sync(0xffffffffu, tm0, 2));
        tm1 = fmaxf(tm1, __shfl_xor_sync(0xffffffffu, tm1, 1));
        tm1 = fmaxf(tm1, __shfl_xor_sync(0xffffffffu, tm1, 2));
        float mn0 = fmaxf(m0, tm0), mn1 = fmaxf(m1, tm1);
        float sc0 = __expf(m0 - mn0), sc1 = __expf(m1 - mn1);
        m0 = mn0; m1 = mn1;
        float rs0 = 0.0f, rs1 = 0.0f;
#pragma unroll
        for (int j = 0; j < 16; j++) {
            float p0 = __expf(sacc[j][0] - m0), p1 = __expf(sacc[j][1] - m0);
            float p2 = __expf(sacc[j][2] - m1), p3 = __expf(sacc[j][3] - m1);
            sacc[j][0] = p0; sacc[j][1] = p1; sacc[j][2] = p2; sacc[j][3] = p3;
            rs0 += p0 + p1; rs1 += p2 + p3;
        }
        rs0 += __shfl_xor_sync(0xffffffffu, rs0, 1);
        rs0 += __shfl_xor_sync(0xffffffffu, rs0, 2);
        rs1 += __shfl_xor_sync(0xffffffffu, rs1, 1);
        rs1 += __shfl_xor_sync(0xffffffffu, rs1, 2);
        l0 = l0 * sc0 + rs0; l1 = l1 * sc1 + rs1;
#pragma unroll
        for (int j2 = 0; j2 < 8; j2++) {
            oacc[j2][0] *= sc0; oacc[j2][1] *= sc0;
            oacc[j2][2] *= sc1; oacc[j2][3] *= sc1;
        }
        // ---- O += P V (2-pass split-fp16); P frags are thread-local repacks ----
#pragma unroll
        for (int s2 = 0; s2 < 8; s2++) {
            uint32_t a0h, a0l, a1h, a1l, a2h, a2l, a3h, a3l;
            split2h(sacc[2 * s2][0],     sacc[2 * s2][1],     a0h, a0l);
            split2h(sacc[2 * s2][2],     sacc[2 * s2][3],     a1h, a1l);
            split2h(sacc[2 * s2 + 1][0], sacc[2 * s2 + 1][1], a2h, a2l);
            split2h(sacc[2 * s2 + 1][2], sacc[2 * s2 + 1][3], a3h, a3l);
#pragma unroll
            for (int j2 = 0; j2 < 8; j2++) {
                int o = (8 * j2 + r) * 68 + 8 * s2 + c;
                uint32_t vh0 = Vh[o], vh1 = Vh[o + 4];
                MMAF(oacc[j2], a0h, a1h, a2h, a3h, vh0, vh1);
                MMAF(oacc[j2], a0l, a1l, a2l, a3l, vh0, vh1);
            }
        }
    }
    float i0 = 1.0f / l0, i1 = 1.0f / l1;
#pragma unroll
    for (int j2 = 0; j2 < 8; j2++) {
        float* op = Og + (size_t)(b * SEQ + grow) * DEMB + h * DH + 8 * j2 + 2 * c;
        *(float2*)op = make_float2(oacc[j2][0] * i0, oacc[j2][1] * i0);
        *(float2*)(op + 8 * DEMB) = make_float2(oacc[j2][2] * i1, oacc[j2][3] * i1);
    }
}

// ---------------- embedding + positional encoding ----------------
__global__ __launch_bounds__(256) void embed_kernel(const int* __restrict__ ids,
                                                    const float* __restrict__ emb,
                                                    float* __restrict__ X) {
    int t = blockIdx.x;
    int pos = t & (SEQ - 1);
    int id = ids[t];
    int d0 = threadIdx.x * 4;
    float4 e4 = *(const float4*)(emb + (size_t)id * DEMB + d0);
    float ev[4] = {e4.x, e4.y, e4.z, e4.w};
    float ov[4];
#pragma unroll
    for (int j = 0; j < 4; j++) {
        int d = d0 + j;
        float ang = (float)pos * powf(10000.0f, -2.0f * (float)d / (float)DEMB);
        float pe = ((d & 1) == 0) ? sinf(ang) : cosf(ang);
        ov[j] = ev[j] * 32.0f + pe;
    }
    *(float4*)(X + (size_t)t * DEMB + d0) = make_float4(ov[0], ov[1], ov[2], ov[3]);
}

// ---------------- fused q/k/v per-head projection (grid.z selects) ----------------
__global__ __launch_bounds__(256) void proj_head3(
        const float* __restrict__ X0, const float* __restrict__ X1, const float* __restrict__ X2,
        const float* __restrict__ W0, const float* __restrict__ W1, const float* __restrict__ W2,
        float* __restrict__ O0, float* __restrict__ O1, float* __restrict__ O2) {
    const float* X; const float* W; float* O;
    if (blockIdx.z == 0)      { X = X0; W = W0; O = O0; }
    else if (blockIdx.z == 1) { X = X1; W = W1; O = O1; }
    else                      { X = X2; W = W2; O = O2; }
    __shared__ float Xs[64][64];
    __shared__ float Ws[64][64];
    int tid = threadIdx.x;
    int h = blockIdx.y;
    int t0 = blockIdx.x * 64;
#pragma unroll
    for (int r = 0; r < 4; r++) {
        int idx = tid + r * 256;
        int a = idx >> 4;
        int c4 = (idx & 15) << 2;
        float4 xv = *(const float4*)(X + (size_t)(t0 + a) * DEMB + h * DH + c4);
        Xs[c4 + 0][a] = xv.x; Xs[c4 + 1][a] = xv.y; Xs[c4 + 2][a] = xv.z; Xs[c4 + 3][a] = xv.w;
        float4 wv = *(const float4*)(W + a * DH + c4);
        *(float4*)&Ws[a][c4] = wv;
    }
    __syncthreads();
    int tx = tid & 15, ty = tid >> 4;
    float acc[4][4] = {};
#pragma unroll
    for (int d = 0; d < 64; d++) {
        float4 a4 = *(float4*)&Xs[d][ty * 4];
        float4 w4 = *(float4*)&Ws[d][tx * 4];
        float av[4] = {a4.x, a4.y, a4.z, a4.w};
        float wv[4] = {w4.x, w4.y, w4.z, w4.w};
#pragma unroll
        for (int i = 0; i < 4; i++)
#pragma unroll
            for (int j = 0; j < 4; j++) acc[i][j] = fmaf(av[i], wv[j], acc[i][j]);
    }
#pragma unroll
    for (int i = 0; i < 4; i++) {
        float4 o = make_float4(acc[i][0], acc[i][1], acc[i][2], acc[i][3]);
        *(float4*)(O + (size_t)(t0 + ty * 4 + i) * DEMB + h * DH + tx * 4) = o;
    }
}

// ---------------- residual add + layernorm (+ optional split-fp16 emit) ----------------
__global__ __launch_bounds__(256) void add_ln(const float* __restrict__ A, const float* __restrict__ B,
                                              const float* __restrict__ g, const float* __restrict__ be,
                                              float* __restrict__ O,
                                              uint16_t* __restrict__ Oh, uint16_t* __restrict__ Ol) {
    int lane = threadIdx.x & 31, wid = threadIdx.x >> 5;
    int row = blockIdx.x * 8 + wid;
    size_t base = (size_t)row * DEMB;
    float4 v[8];
    float s1 = 0.0f, s2 = 0.0f;
#pragma unroll
    for (int p = 0; p < 8; p++) {
        float4 a = ((const float4*)(A + base))[lane + p * 32];
        float4 b = ((const float4*)(B + base))[lane + p * 32];
        float4 t = make_float4(a.x + b.x, a.y + b.y, a.z + b.z, a.w + b.w);
        v[p] = t;
        s1 += t.x + t.y + t.z + t.w;
        s2 += t.x * t.x + t.y * t.y + t.z * t.z + t.w * t.w;
    }
#pragma unroll
    for (int o = 16; o; o >>= 1) {
        s1 += __shfl_xor_sync(0xffffffffu, s1, o);
        s2 += __shfl_xor_sync(0xffffffffu, s2, o);
    }
    float mu = s1 * (1.0f / DEMB);
    float var = s2 * (1.0f / DEMB) - mu * mu;
    float w = rsqrtf(var + 1e-5f);
#pragma unroll
    for (int p = 0; p < 8; p++) {
        float4 gg = ((const float4*)g)[lane + p * 32];
        float4 bb = ((const float4*)be)[lane + p * 32];
        float4 t = v[p];
        float4 o;
        o.x = (t.x - mu) * w * gg.x + bb.x;
        o.y = (t.y - mu) * w * gg.y + bb.y;
        o.z = (t.z - mu) * w * gg.z + bb.z;
        o.w = (t.w - mu) * w * gg.w + bb.w;
        ((float4*)(O + base))[lane + p * 32] = o;
        if (Oh) {
            uint32_t h0, l0, h1, l1;
            split2h(o.x, o.y, h0, l0);
            split2h(o.z, o.w, h1, l1);
            size_t idx = base + (size_t)(lane + p * 32) * 4;
            *(uint32_t*)(Oh + idx) = h0; *(uint32_t*)(Oh + idx + 2) = h1;
            *(uint32_t*)(Ol + idx) = l0; *(uint32_t*)(Ol + idx + 2) = l1;
        }
    }
}

// ---------------- host orchestration ----------------
extern "C" void kernel_launch(void* const* d_in, const int* in_sizes, int n_in,
                              void* d_out, int out_size) {
    const int*   ids   = (const int*)  d_in[0];
    const float* enc_k = (const float*)d_in[1];
    const float* enc_v = (const float*)d_in[2];
    const float* emb   = (const float*)d_in[3];
    const float* Wq_m  = (const float*)d_in[4];
    const float* Wk_m  = (const float*)d_in[5];
    const float* Wv_m  = (const float*)d_in[6];
    const float* Wq_c  = (const float*)d_in[7];
    const float* Wk_c  = (const float*)d_in[8];
    const float* Wv_c  = (const float*)d_in[9];
    const float* ln1_g = (const float*)d_in[10];
    const float* ln1_b = (const float*)d_in[11];
    const float* ln2_g = (const float*)d_in[12];
    const float* ln2_b = (const float*)d_in[13];
    const float* ln3_g = (const float*)d_in[14];
    const float* ln3_b = (const float*)d_in[15];
    const float* W1    = (const float*)d_in[16];
    const float* b1    = (const float*)d_in[17];
    const float* W2    = (const float*)d_in[18];
    const float* b2    = (const float*)d_in[19];
    const float* Wout  = (const float*)d_in[20];
    const float* bout  = (const float*)d_in[21];
    float* out = (float*)d_out;

    float *x, *h1, *h2, *t, *q, *k, *v;
    uint16_t *ah, *al, *fh, *fl, *bth;
    cudaGetSymbolAddress((void**)&x,  g_x);
    cudaGetSymbolAddress((void**)&h1, g_h1);
    cudaGetSymbolAddress((void**)&h2, g_h2);
    cudaGetSymbolAddress((void**)&t,  g_t);
    cudaGetSymbolAddress((void**)&q,  g_q);
    cudaGetSymbolAddress((void**)&k,  g_k);
    cudaGetSymbolAddress((void**)&v,  g_v);
    cudaGetSymbolAddress((void**)&ah,  g_ah);
    cudaGetSymbolAddress((void**)&al,  g_al);
    cudaGetSymbolAddress((void**)&fh,  g_fh);
    cudaGetSymbolAddress((void**)&fl,  g_fl);
    cudaGetSymbolAddress((void**)&bth, g_bth);

    cudaFuncSetAttribute(flash_attn, cudaFuncAttributeMaxDynamicSharedMemorySize, FA_SMEM_BYTES);
    cudaFuncSetAttribute(gemm_cp,   cudaFuncAttributeMaxDynamicSharedMemorySize, GEMM_SMEM);

    dim3 blk(256);
    dim3 projGrid(NTOK / 64, NHEAD, 3);
    dim3 faGrid(SEQ / 128, NB * NHEAD);
    dim3 tblk(256);

    embed_kernel<<<NTOK, blk>>>(ids, emb, x);

    for (int l = 0; l < NLAYER; l++) {
        size_t wOff  = (size_t)l * DH * DH;
        size_t lnOff = (size_t)l * DEMB;
        // --- masked self-attention ---
        proj_head3<<<projGrid, blk>>>(x, x, x, Wq_m + wOff, Wk_m + wOff, Wv_m + wOff, q, k, v);
        flash_attn<<<faGrid, blk, FA_SMEM_BYTES>>>(q, k, v, t, 1);
        add_ln<<<NTOK / 8, blk>>>(t, x, ln1_g + lnOff, ln1_b + lnOff, h1,
                                  (uint16_t*)nullptr, (uint16_t*)nullptr);
        // --- cross-attention ---
        proj_head3<<<projGrid, blk>>>(h1, enc_k, enc_v, Wq_c + wOff, Wk_c + wOff, Wv_c + wOff, q, k, v);
        flash_attn<<<faGrid, blk, FA_SMEM_BYTES>>>(q, k, v, t, 0);
        add_ln<<<NTOK / 8, blk>>>(t, h1, ln2_g + lnOff, ln2_b + lnOff, h2, ah, al);   // emit h2 split
        // --- FFN (2-pass cp.async split-fp16 HMMA, ldmatrix frags) ---
        cvt_trans<<<dim3(DFF / 32, DEMB / 32), tblk>>>(W1 + (size_t)l * DEMB * DFF, bth, DEMB, DFF);
        gemm_cp<<<dim3(NTOK / 128, DFF / 128), blk, GEMM_SMEM>>>(
            ah, al, bth, b1 + (size_t)l * DFF, (float*)nullptr, fh, fl, DFF, DEMB, 1); // ff -> split
        cvt_trans<<<dim3(DEMB / 32, DFF / 32), tblk>>>(W2 + (size_t)l * DFF * DEMB, bth, DFF, DEMB);
        gemm_cp<<<dim3(NTOK / 128, DEMB / 128), blk, GEMM_SMEM>>>(
            fh, fl, bth, b2 + lnOff, t, (uint16_t*)nullptr, (uint16_t*)nullptr, DEMB, DFF, 0);
        add_ln<<<NTOK / 8, blk>>>(t, h2, ln3_g + lnOff, ln3_b + lnOff, x, ah, al);    // emit x split
    }

    // --- vocab projection (x split already emitted by last add_ln) ---
    cvt_trans<<<dim3(NVOCAB / 32, DEMB / 32), tblk>>>(Wout, bth, DEMB, NVOCAB);
    gemm_cp<<<dim3(NTOK / 128, NVOCAB / 128), blk, GEMM_SMEM>>>(
        ah, al, bth, bout, out, (uint16_t*)nullptr, (uint16_t*)nullptr, NVOCAB, DEMB, 0);
}

// round 14
// speedup vs baseline: 1.4163x; 1.0511x over previous
#include <cuda_runtime.h>
#include <cuda_bf16.h>
#include <cuda_fp16.h>
#include <math.h>
#include <stdint.h>

#define NB 2
#define SEQ 1024
#define NTOK (NB * SEQ)          // 2048
#define DEMB 1024
#define NHEAD 16
#define DH 64
#define DFF 4096
#define NVOCAB 32000
#define NLAYER 6

// -------- scratch (device globals; no allocation allowed) --------
__device__ float g_x [NTOK * DEMB];
__device__ float g_h1[NTOK * DEMB];
__device__ float g_h2[NTOK * DEMB];
__device__ float g_t [NTOK * DEMB];
__device__ float g_q [NTOK * DEMB];
__device__ float g_k [NTOK * DEMB];
__device__ float g_v [NTOK * DEMB];
// split-fp16 staging (uint16 = raw fp16 bits)
__device__ uint16_t g_ah [NTOK * DEMB];            // activation hi (h2 / x)
__device__ uint16_t g_al [NTOK * DEMB];            // activation lo
__device__ uint16_t g_fh [NTOK * DFF];             // ff hi
__device__ uint16_t g_fl [NTOK * DFF];             // ff lo
__device__ uint16_t g_bth[(size_t)NVOCAB * DEMB];  // B^T hi (max 32000x1024)

// ---------------- split-fp16 helper: x = hi(fp16 RN) + lo(fp16), |lo|<=2^-12|x| ----------------
__device__ __forceinline__ void split2h(float x0, float x1, uint32_t& hi, uint32_t& lo) {
    __half h0 = __float2half_rn(x0), h1 = __float2half_rn(x1);
    float r0 = x0 - __half2float(h0);
    float r1 = x1 - __half2float(h1);
    __half l0 = __float2half_rn(r0), l1 = __float2half_rn(r1);
    hi = (uint32_t)(*(uint16_t*)&h0) | ((uint32_t)(*(uint16_t*)&h1) << 16);
    lo = (uint32_t)(*(uint16_t*)&l0) | ((uint32_t)(*(uint16_t*)&l1) << 16);
}
__device__ __forceinline__ uint32_t pack2h(float x0, float x1) {
    __half2 h = __floats2half2_rn(x0, x1);
    return *(uint32_t*)&h;
}

// fp16 MMA, fp32 acc
#define MMAF(acc, a0, a1, a2, a3, b0, b1)                                       \
    asm("mma.sync.aligned.m16n8k16.row.col.f32.f16.f16.f32 "                    \
        "{%0,%1,%2,%3}, {%4,%5,%6,%7}, {%8,%9}, {%0,%1,%2,%3};"                 \
        : "+f"((acc)[0]), "+f"((acc)[1]), "+f"((acc)[2]), "+f"((acc)[3])        \
        : "r"(a0), "r"(a1), "r"(a2), "r"(a3), "r"(b0), "r"(b1))

// warp-collective 4-matrix fragment load
#define LDMX4(r0, r1, r2, r3, addr)                                             \
    asm volatile("ldmatrix.sync.aligned.m8n8.x4.shared.b16 {%0,%1,%2,%3}, [%4];"\
        : "=r"(r0), "=r"(r1), "=r"(r2), "=r"(r3) : "r"(addr))

#define CP_ASYNC16(dst, src) \
    asm volatile("cp.async.cg.shared.global [%0], [%1], 16;" :: "r"(dst), "l"(src))
#define CP_COMMIT() asm volatile("cp.async.commit_group;")
#define CP_WAIT(n)  asm volatile("cp.async.wait_group %0;" :: "n"(n))

__device__ __forceinline__ uint32_t smem_u32(const void* p) {
    uint32_t a;
    asm("{ .reg .u64 t; cvta.to.shared.u64 t, %1; cvt.u32.u64 %0, t; }" : "=r"(a) : "l"(p));
    return a;
}

// ---------------- transpose + fp16 hi only: in[K][N] -> hiT [N][K] ----------------
__global__ __launch_bounds__(256) void cvt_trans(const float* __restrict__ in,
                                                 uint16_t* __restrict__ hiT,
                                                 int K, int N) {
    __shared__ float t[32][33];
    int n0 = blockIdx.x * 32, k0 = blockIdx.y * 32;
    int tx = threadIdx.x & 31, ty = threadIdx.x >> 5;   // 32x8
#pragma unroll
    for (int i = 0; i < 32; i += 8)
        t[ty + i][tx] = in[(size_t)(k0 + ty + i) * N + n0 + tx];
    __syncthreads();
#pragma unroll
    for (int i = 0; i < 32; i += 8) {
        float x = t[tx][ty + i];                         // k = k0+tx, n = n0+ty+i
        __half h = __float2half_rn(x);
        hiT[(size_t)(n0 + ty + i) * K + k0 + tx] = *(uint16_t*)&h;
    }
}

// ============ 3-stage cp.async pipelined 2-pass split-fp16 HMMA GEMM (ldmatrix) ============
// C = (A_hi + A_lo) @ B_hi^T + bias;  dropped term A_hi@B_lo ~ 2^-12 relative.
// ONE __syncthreads per K-chunk: issue(kt+2) targets buf used by compute(kt-1),
// which the top-of-loop sync has already ordered past for all warps.
#define STRIDE 20                         // words per smem row (32 k + pad)
#define TILE_B (128 * STRIDE * 4)         // 10240 bytes per tile
#define BUF_B  (3 * TILE_B)               // Ah, Al, Bh = 30720 bytes
#define GEMM_SMEM (3 * BUF_B)             // 92160 (3 stages)

__global__ __launch_bounds__(256, 2) void gemm_cp(const uint16_t* __restrict__ Ahg,
                                                  const uint16_t* __restrict__ Alg,
                                                  const uint16_t* __restrict__ Bth,
                                                  const float* __restrict__ bias,
                                                  float* __restrict__ C,
                                                  uint16_t* __restrict__ Oh,
                                                  uint16_t* __restrict__ Ol,
                                                  int N, int K, int relu) {
    extern __shared__ uint32_t sh[];
    uint32_t sb = smem_u32(sh);
    int tid = threadIdx.x, wid = tid >> 5, lane = tid & 31;
    int bm = blockIdx.x * 128, bn = blockIdx.y * 128;
    int wm = (wid >> 2) * 64, wn = (wid & 3) * 32;
    int r = lane >> 2, c = lane & 3;
    int q = lane >> 3, tt = lane & 7;     // ldmatrix lane roles

    uint32_t aoff = ((uint32_t)(wm + tt + 8 * (q & 1)) * STRIDE + 4 * (q >> 1)) * 4;
    uint32_t boff = 2 * TILE_B + ((uint32_t)(wn + 8 * (q >> 1) + tt) * STRIDE + 4 * (q & 1)) * 4;

#define ISSUE(kt, buf)                                                          \
    {                                                                           \
        int k0i = (kt) << 5;                                                    \
        _Pragma("unroll")                                                       \
        for (int p = 0; p < 2; p++) {                                           \
            int idx = tid + p * 256;                                            \
            int row = idx >> 2, qq = idx & 3;                                   \
            size_t ao = (size_t)(bm + row) * K + k0i + qq * 8;                  \
            size_t bo = (size_t)(bn + row) * K + k0i + qq * 8;                  \
            uint32_t d = sb + (buf) * BUF_B + row * (STRIDE * 4) + qq * 16;     \
            CP_ASYNC16(d,              Ahg + ao);                               \
            CP_ASYNC16(d + TILE_B,     Alg + ao);                               \
            CP_ASYNC16(d + 2 * TILE_B, Bth + bo);                               \
        }                                                                       \
        CP_COMMIT();                                                            \
    }

    float acc[4][4][4] = {};

    int KT = K >> 5;                      // always >= 32 here
    ISSUE(0, 0);
    ISSUE(1, 1);

    int bufc = 0;                         // kt % 3
    int bufn = 2;                         // (kt+2) % 3
    for (int kt = 0; kt < KT; kt++) {
        if (kt + 1 < KT) { CP_WAIT(1); } else { CP_WAIT(0); }
        __syncthreads();
        if (kt + 2 < KT) ISSUE(kt + 2, bufn);
        uint32_t bufb = sb + bufc * BUF_B;
        bufc = (bufc == 2) ? 0 : bufc + 1;
        bufn = (bufn == 2) ? 0 : bufn + 1;
#pragma unroll
        for (int s = 0; s < 2; s++) {
            uint32_t bh[4][2];
#pragma unroll
            for (int p = 0; p < 2; p++) {
                uint32_t addr = bufb + boff + s * 32 + p * (16 * STRIDE * 4);
                LDMX4(bh[2 * p][0], bh[2 * p][1], bh[2 * p + 1][0], bh[2 * p + 1][1], addr);
            }
#pragma unroll
            for (int i = 0; i < 4; i++) {
                uint32_t addrA = bufb + aoff + i * (16 * STRIDE * 4) + s * 32;
                uint32_t ah0, ah1, ah2, ah3, al0, al1, al2, al3;
                LDMX4(ah0, ah1, ah2, ah3, addrA);
                LDMX4(al0, al1, al2, al3, addrA + TILE_B);
#pragma unroll
                for (int j = 0; j < 4; j++) {
                    MMAF(acc[i][j], ah0, ah1, ah2, ah3, bh[j][0], bh[j][1]);   // hi*hi
                    MMAF(acc[i][j], al0, al1, al2, al3, bh[j][0], bh[j][1]);   // lo*hi
                }
            }
        }
    }

#pragma unroll
    for (int i = 0; i < 4; i++) {
#pragma unroll
        for (int j = 0; j < 4; j++) {
            int col = bn + wn + 8 * j + 2 * c;
            int row0 = bm + wm + 16 * i + r;
            float b0 = bias[col], b1 = bias[col + 1];
            float v0 = acc[i][j][0] + b0, v1 = acc[i][j][1] + b1;
            float v2 = acc[i][j][2] + b0, v3 = acc[i][j][3] + b1;
            if (relu) {
                v0 = fmaxf(v0, 0.0f); v1 = fmaxf(v1, 0.0f);
                v2 = fmaxf(v2, 0.0f); v3 = fmaxf(v3, 0.0f);
            }
            if (Oh) {
                uint32_t h0, l0, h1, l1;
                split2h(v0, v1, h0, l0);
                split2h(v2, v3, h1, l1);
                size_t o0 = (size_t)row0 * N + col;
                size_t o1 = (size_t)(row0 + 8) * N + col;
                *(uint32_t*)(Oh + o0) = h0; *(uint32_t*)(Ol + o0) = l0;
                *(uint32_t*)(Oh + o1) = h1; *(uint32_t*)(Ol + o1) = l1;
            } else {
                *(float2*)(C + (size_t)row0 * N + col) = make_float2(v0, v1);
                *(float2*)(C + (size_t)(row0 + 8) * N + col) = make_float2(v2, v3);
            }
        }
    }
}

// ============ fused flash attention (2-pass split-fp16 HMMA, online softmax, 1e-19 mask) ============
#define FA_SMEM_WORDS (4608 + 4352)       // Kh[128][36], Vh[64][68]
#define FA_SMEM_BYTES (FA_SMEM_WORDS * 4)
__global__ __launch_bounds__(256) void flash_attn(const float* __restrict__ Qg,
                                                  const float* __restrict__ Kg,
                                                  const float* __restrict__ Vg,
                                                  float* __restrict__ Og, int causal) {
    extern __shared__ uint32_t sm[];
    uint32_t* Kh = sm;
    uint32_t* Vh = sm + 4608;
    int tid = threadIdx.x, wid = tid >> 5, lane = tid & 31;
    int r = lane >> 2, c = lane & 3;
    int b = blockIdx.y >> 4, h = blockIdx.y & 15;
    const float* Qb = Qg + (size_t)b * SEQ * DEMB + h * DH;
    const float* Kb = Kg + (size_t)b * SEQ * DEMB + h * DH;
    const float* Vb = Vg + (size_t)b * SEQ * DEMB + h * DH;
    int q0 = blockIdx.x * 128;
    int grow = q0 + wid * 16 + r;

    uint32_t qh[4][4], ql[4][4];
#pragma unroll
    for (int s = 0; s < 4; s++) {
        const float* q0p = Qb + (size_t)grow * DEMB + s * 16;
        const float* q1p = q0p + 8 * DEMB;
        float2 v0 = *(const float2*)(q0p + 2 * c);
        float2 v1 = *(const float2*)(q1p + 2 * c);
        float2 v2 = *(const float2*)(q0p + 2 * c + 8);
        float2 v3 = *(const float2*)(q1p + 2 * c + 8);
        split2h(v0.x, v0.y, qh[s][0], ql[s][0]);
        split2h(v1.x, v1.y, qh[s][1], ql[s][1]);
        split2h(v2.x, v2.y, qh[s][2], ql[s][2]);
        split2h(v3.x, v3.y, qh[s][3], ql[s][3]);
    }

    float oacc[8][4] = {};
    float m0 = -1e30f, m1 = -1e30f, l0 = 0.0f, l1 = 0.0f;

    for (int kt = 0; kt < SEQ / 128; kt++) {
        int k0 = kt * 128;
        __syncthreads();
#pragma unroll
        for (int p = 0; p < 16; p++) {
            int idx = tid + p * 256;
            int row = idx >> 5, kp = idx & 31;
            float2 kv = *(const float2*)(Kb + (size_t)(k0 + row) * DEMB + kp * 2);
            Kh[row * 36 + kp] = pack2h(kv.x, kv.y);
        }
#pragma unroll
        for (int p = 0; p < 16; p++) {
            int idx = tid + p * 256;
            int d = idx & 63, kp = idx >> 6;
            float x0 = Vb[(size_t)(k0 + kp * 2) * DEMB + d];
            float x1 = Vb[(size_t)(k0 + kp * 2 + 1) * DEMB + d];
            Vh[d * 68 + kp] = pack2h(x0, x1);
        }
        __syncthreads();

        float sacc[16][4];
#pragma unroll
        for (int j = 0; j < 16; j++) { sacc[j][0] = sacc[j][1] = sacc[j][2] = sacc[j][3] = 0.0f; }
#pragma unroll
        for (int j = 0; j < 16; j++) {
#pragma unroll
            for (int s = 0; s < 4; s++) {
                int o = (8 * j + r) * 36 + 8 * s + c;
                uint32_t kh0 = Kh[o], kh1 = Kh[o + 4];
                MMAF(sacc[j], qh[s][0], qh[s][1], qh[s][2], qh[s][3], kh0, kh1);
                MMAF(sacc[j], ql[s][0], ql[s][1], ql[s][2], ql[s][3], kh0, kh1);
            }
        }
        float tm0 = -1e30f, tm1 = -1e30f;
#pragma unroll
        for (int j = 0; j < 16; j++) {
            int col = k0 + 8 * j + 2 * c;
            float v0 = sacc[j][0] * 0.125f, v1 = sacc[j][1] * 0.125f;
            float v2 = sacc[j][2] * 0.125f, v3 = sacc[j][3] * 0.125f;
            if (causal) {
                if (col     > grow)     v0 = 1e-19f;
                if (col + 1 > grow)     v1 = 1e-19f;
                if (col     > grow + 8) v2 = 1e-19f;
                if (col + 1 > grow + 8) v3 = 1e-19f;
            }
            sacc[j][0] = v0; sacc[j][1] = v1; sacc[j][2] = v2; sacc[j][3] = v3;
            tm0 = fmaxf(tm0, fmaxf(v0, v1));
            tm1 = fmaxf(tm1, fmaxf(v2, v3));
        }
        tm0 = fmaxf(tm0, __shfl_xor_sync(0xffffffffu, tm0, 1));
        tm0 = fmaxf(tm0, __shfl_xor_sync(0xffffffffu, tm0, 2));
        tm1 = fmaxf(tm1, __shfl_xor_sync(0xffffffffu, tm1, 1));
        tm1 = fmaxf(tm1, __shfl_xor_sync(0xffffffffu, tm1, 2));
        float mn0 = fmaxf(m0, tm0), mn1 = fmaxf(m1, tm1);
        float sc0 = __expf(m0 - mn0), sc1 = __expf(m1 - mn1);
        m0 = mn0; m1 = mn1;
        float rs0 = 0.0f, rs1 = 0.0f;
#pragma unroll
        for (int j = 0; j < 16; j++) {
            float p0 = __expf(sacc[j][0] - m0), p1 = __expf(sacc[j][1] - m0);
            float p2 = __expf(sacc[j][2] - m1), p3 = __expf(sacc[j][3] - m1);
            sacc[j][0] = p0; sacc[j][1] = p1; sacc[j][2] = p2; sacc[j][3] = p3;
            rs0 += p0 + p1; rs1 += p2 + p3;
        }
        rs0 += __shfl_xor_sync(0xffffffffu, rs0, 1);
        rs0 += __shfl_xor_sync(0xffffffffu, rs0, 2);
        rs1 += __shfl_xor_sync(0xffffffffu, rs1, 1);
        rs1 += __shfl_xor_sync(0xffffffffu, rs1, 2);
        l0 = l0 * sc0 + rs0; l1 = l1 * sc1 + rs1;
#pragma unroll
        for (int j2 = 0; j2 < 8; j2++) {
            oacc[j2][0] *= sc0; oacc[j2][1] *= sc0;
            oacc[j2][2] *= sc1; oacc[j2][3] *= sc1;
        }
#pragma unroll
        for (int s2 = 0; s2 < 8; s2++) {
            uint32_t a0h, a0l, a1h, a1l, a2h, a2l, a3h, a3l;
            split2h(sacc[2 * s2][0],     sacc[2 * s2][1],     a0h, a0l);
            split2h(sacc[2 * s2][2],     sacc[2 * s2][3],     a1h, a1l);
            split2h(sacc[2 * s2 + 1][0], sacc[2 * s2 + 1][1], a2h, a2l);
            split2h(sacc[2 * s2 + 1][2], sacc[2 * s2 + 1][3], a3h, a3l);
#pragma unroll
            for (int j2 = 0; j2 < 8; j2++) {
                int o = (8 * j2 + r) * 68 + 8 * s2 + c;
                uint32_t vh0 = Vh[o], vh1 = Vh[o + 4];
                MMAF(oacc[j2], a0h, a1h, a2h, a3h, vh0, vh1);
                MMAF(oacc[j2], a0l, a1l, a2l, a3l, vh0, vh1);
            }
        }
    }
    float i0 = 1.0f / l0, i1 = 1.0f / l1;
#pragma unroll
    for (int j2 = 0; j2 < 8; j2++) {
        float* op = Og + (size_t)(b * SEQ + grow) * DEMB + h * DH + 8 * j2 + 2 * c;
        *(float2*)op = make_float2(oacc[j2][0] * i0, oacc[j2][1] * i0);
        *(float2*)(op + 8 * DEMB) = make_float2(oacc[j2][2] * i1, oacc[j2][3] * i1);
    }
}

// ---------------- embedding + positional encoding ----------------
__global__ __launch_bounds__(256) void embed_kernel(const int* __restrict__ ids,
                                                    const float* __restrict__ emb,
                                                    float* __restrict__ X) {
    int t = blockIdx.x;
    int pos = t & (SEQ - 1);
    int id = ids[t];
    int d0 = threadIdx.x * 4;
    float4 e4 = *(const float4*)(emb + (size_t)id * DEMB + d0);
    float ev[4] = {e4.x, e4.y, e4.z, e4.w};
    float ov[4];
#pragma unroll
    for (int j = 0; j < 4; j++) {
        int d = d0 + j;
        float ang = (float)pos * powf(10000.0f, -2.0f * (float)d / (float)DEMB);
        float pe = ((d & 1) == 0) ? sinf(ang) : cosf(ang);
        ov[j] = ev[j] * 32.0f + pe;
    }
    *(float4*)(X + (size_t)t * DEMB + d0) = make_float4(ov[0], ov[1], ov[2], ov[3]);
}

// ---------------- fused q/k/v per-head projection: 128 tokens x 1 head per block ----------------
__global__ __launch_bounds__(256) void proj_head3(
        const float* __restrict__ X0, const float* __restrict__ X1, const float* __restrict__ X2,
        const float* __restrict__ W0, const float* __restrict__ W1, const float* __restrict__ W2,
        float* __restrict__ O0, float* __restrict__ O1, float* __restrict__ O2) {
    const float* X; const float* W; float* O;
    if (blockIdx.z == 0)      { X = X0; W = W0; O = O0; }
    else if (blockIdx.z == 1) { X = X1; W = W1; O = O1; }
    else                      { X = X2; W = W2; O = O2; }
    __shared__ float Xs[64][132];   // [d][token], pad 4 (row 528B, 16B-aligned)
    __shared__ float Ws[64][64];    // [d][e]
    int tid = threadIdx.x;
    int h = blockIdx.y;
    int t0 = blockIdx.x * 128;
    // fill Ws (64x64)
#pragma unroll
    for (int r2 = 0; r2 < 4; r2++) {
        int idx = tid + r2 * 256;
        int a = idx >> 4;
        int c4 = (idx & 15) << 2;
        *(float4*)&Ws[a][c4] = *(const float4*)(W + a * DH + c4);
    }
    // fill Xs transposed (128 tokens x 64 dims)
#pragma unroll
    for (int r2 = 0; r2 < 8; r2++) {
        int idx = tid + r2 * 256;
        int a = idx >> 4;                  // token 0..127
        int c4 = (idx & 15) << 2;          // dim 0..60
        float4 xv = *(const float4*)(X + (size_t)(t0 + a) * DEMB + h * DH + c4);
        Xs[c4 + 0][a] = xv.x; Xs[c4 + 1][a] = xv.y; Xs[c4 + 2][a] = xv.z; Xs[c4 + 3][a] = xv.w;
    }
    __syncthreads();
    int tx = tid & 15, ty = tid >> 4;      // tx: 4-dim group; ty: 8-token group
    float acc[8][4] = {};
#pragma unroll
    for (int d = 0; d < 64; d++) {
        float4 w4 = *(float4*)&Ws[d][tx * 4];
        float4 a0 = *(float4*)&Xs[d][ty * 8];
        float4 a1 = *(float4*)&Xs[d][ty * 8 + 4];
        float av[8] = {a0.x, a0.y, a0.z, a0.w, a1.x, a1.y, a1.z, a1.w};
        float wv[4] = {w4.x, w4.y, w4.z, w4.w};
#pragma unroll
        for (int i = 0; i < 8; i++)
#pragma unroll
            for (int j = 0; j < 4; j++) acc[i][j] = fmaf(av[i], wv[j], acc[i][j]);
    }
#pragma unroll
    for (int i = 0; i < 8; i++) {
        float4 o = make_float4(acc[i][0], acc[i][1], acc[i][2], acc[i][3]);
        *(float4*)(O + (size_t)(t0 + ty * 8 + i) * DEMB + h * DH + tx * 4) = o;
    }
}

// ---------------- residual add + layernorm (+ optional split-fp16 emit) ----------------
__global__ __launch_bounds__(256) void add_ln(const float* __restrict__ A, const float* __restrict__ B,
                                              const float* __restrict__ g, const float* __restrict__ be,
                                              float* __restrict__ O,
                                              uint16_t* __restrict__ Oh, uint16_t* __restrict__ Ol) {
    int lane = threadIdx.x & 31, wid = threadIdx.x >> 5;
    int row = blockIdx.x * 8 + wid;
    size_t base = (size_t)row * DEMB;
    float4 v[8];
    float s1 = 0.0f, s2 = 0.0f;
#pragma unroll
    for (int p = 0; p < 8; p++) {
        float4 a = ((const float4*)(A + base))[lane + p * 32];
        float4 b = ((const float4*)(B + base))[lane + p * 32];
        float4 t = make_float4(a.x + b.x, a.y + b.y, a.z + b.z, a.w + b.w);
        v[p] = t;
        s1 += t.x + t.y + t.z + t.w;
        s2 += t.x * t.x + t.y * t.y + t.z * t.z + t.w * t.w;
    }
#pragma unroll
    for (int o = 16; o; o >>= 1) {
        s1 += __shfl_xor_sync(0xffffffffu, s1, o);
        s2 += __shfl_xor_sync(0xffffffffu, s2, o);
    }
    float mu = s1 * (1.0f / DEMB);
    float var = s2 * (1.0f / DEMB) - mu * mu;
    float w = rsqrtf(var + 1e-5f);
#pragma unroll
    for (int p = 0; p < 8; p++) {
        float4 gg = ((const float4*)g)[lane + p * 32];
        float4 bb = ((const float4*)be)[lane + p * 32];
        float4 t = v[p];
        float4 o;
        o.x = (t.x - mu) * w * gg.x + bb.x;
        o.y = (t.y - mu) * w * gg.y + bb.y;
        o.z = (t.z - mu) * w * gg.z + bb.z;
        o.w = (t.w - mu) * w * gg.w + bb.w;
        ((float4*)(O + base))[lane + p * 32] = o;
        if (Oh) {
            uint32_t h0, l0, h1, l1;
            split2h(o.x, o.y, h0, l0);
            split2h(o.z, o.w, h1, l1);
            size_t idx = base + (size_t)(lane + p * 32) * 4;
            *(uint32_t*)(Oh + idx) = h0; *(uint32_t*)(Oh + idx + 2) = h1;
            *(uint32_t*)(Ol + idx) = l0; *(uint32_t*)(Ol + idx + 2) = l1;
        }
    }
}

// ---------------- host orchestration ----------------
extern "C" void kernel_launch(void* const* d_in, const int* in_sizes, int n_in,
                              void* d_out, int out_size) {
    const int*   ids   = (const int*)  d_in[0];
    const float* enc_k = (const float*)d_in[1];
    const float* enc_v = (const float*)d_in[2];
    const float* emb   = (const float*)d_in[3];
    const float* Wq_m  = (const float*)d_in[4];
    const float* Wk_m  = (const float*)d_in[5];
    const float* Wv_m  = (const float*)d_in[6];
    const float* Wq_c  = (const float*)d_in[7];
    const float* Wk_c  = (const float*)d_in[8];
    const float* Wv_c  = (const float*)d_in[9];
    const float* ln1_g = (const float*)d_in[10];
    const float* ln1_b = (const float*)d_in[11];
    const float* ln2_g = (const float*)d_in[12];
    const float* ln2_b = (const float*)d_in[13];
    const float* ln3_g = (const float*)d_in[14];
    const float* ln3_b = (const float*)d_in[15];
    const float* W1    = (const float*)d_in[16];
    const float* b1    = (const float*)d_in[17];
    const float* W2    = (const float*)d_in[18];
    const float* b2    = (const float*)d_in[19];
    const float* Wout  = (const float*)d_in[20];
    const float* bout  = (const float*)d_in[21];
    float* out = (float*)d_out;

    float *x, *h1, *h2, *t, *q, *k, *v;
    uint16_t *ah, *al, *fh, *fl, *bth;
    cudaGetSymbolAddress((void**)&x,  g_x);
    cudaGetSymbolAddress((void**)&h1, g_h1);
    cudaGetSymbolAddress((void**)&h2, g_h2);
    cudaGetSymbolAddress((void**)&t,  g_t);
    cudaGetSymbolAddress((void**)&q,  g_q);
    cudaGetSymbolAddress((void**)&k,  g_k);
    cudaGetSymbolAddress((void**)&v,  g_v);
    cudaGetSymbolAddress((void**)&ah,  g_ah);
    cudaGetSymbolAddress((void**)&al,  g_al);
    cudaGetSymbolAddress((void**)&fh,  g_fh);
    cudaGetSymbolAddress((void**)&fl,  g_fl);
    cudaGetSymbolAddress((void**)&bth, g_bth);

    cudaFuncSetAttribute(flash_attn, cudaFuncAttributeMaxDynamicSharedMemorySize, FA_SMEM_BYTES);
    cudaFuncSetAttribute(gemm_cp,   cudaFuncAttributeMaxDynamicSharedMemorySize, GEMM_SMEM);

    dim3 blk(256);
    dim3 projGrid(NTOK / 128, NHEAD, 3);
    dim3 faGrid(SEQ / 128, NB * NHEAD);
    dim3 tblk(256);

    embed_kernel<<<NTOK, blk>>>(ids, emb, x);

    for (int l = 0; l < NLAYER; l++) {
        size_t wOff  = (size_t)l * DH * DH;
        size_t lnOff = (size_t)l * DEMB;
        // --- masked self-attention ---
        proj_head3<<<projGrid, blk>>>(x, x, x, Wq_m + wOff, Wk_m + wOff, Wv_m + wOff, q, k, v);
        flash_attn<<<faGrid, blk, FA_SMEM_BYTES>>>(q, k, v, t, 1);
        add_ln<<<NTOK / 8, blk>>>(t, x, ln1_g + lnOff, ln1_b + lnOff, h1,
                                  (uint16_t*)nullptr, (uint16_t*)nullptr);
        // --- cross-attention ---
        proj_head3<<<projGrid, blk>>>(h1, enc_k, enc_v, Wq_c + wOff, Wk_c + wOff, Wv_c + wOff, q, k, v);
        flash_attn<<<faGrid, blk, FA_SMEM_BYTES>>>(q, k, v, t, 0);
        add_ln<<<NTOK / 8, blk>>>(t, h1, ln2_g + lnOff, ln2_b + lnOff, h2, ah, al);   // emit h2 split
        // --- FFN (2-pass cp.async split-fp16 HMMA, 3-stage pipeline) ---
        cvt_trans<<<dim3(DFF / 32, DEMB / 32), tblk>>>(W1 + (size_t)l * DEMB * DFF, bth, DEMB, DFF);
        gemm_cp<<<dim3(NTOK / 128, DFF / 128), blk, GEMM_SMEM>>>(
            ah, al, bth, b1 + (size_t)l * DFF, (float*)nullptr, fh, fl, DFF, DEMB, 1); // ff -> split
        cvt_trans<<<dim3(DEMB / 32, DFF / 32), tblk>>>(W2 + (size_t)l * DFF * DEMB, bth, DFF, DEMB);
        gemm_cp<<<dim3(NTOK / 128, DEMB / 128), blk, GEMM_SMEM>>>(
            fh, fl, bth, b2 + lnOff, t, (uint16_t*)nullptr, (uint16_t*)nullptr, DEMB, DFF, 0);
        add_ln<<<NTOK / 8, blk>>>(t, h2, ln3_g + lnOff, ln3_b + lnOff, x, ah, al);    // emit x split
    }

    // --- vocab projection (x split already emitted by last add_ln) ---
    cvt_trans<<<dim3(NVOCAB / 32, DEMB / 32), tblk>>>(Wout, bth, DEMB, NVOCAB);
    gemm_cp<<<dim3(NTOK / 128, NVOCAB / 128), blk, GEMM_SMEM>>>(
        ah, al, bth, bout, out, (uint16_t*)nullptr, (uint16_t*)nullptr, NVOCAB, DEMB, 0);
}

// round 16
// speedup vs baseline: 1.4764x; 1.0425x over previous
#include <cuda_runtime.h>
#include <cuda_bf16.h>
#include <cuda_fp16.h>
#include <math.h>
#include <stdint.h>

#define NB 2
#define SEQ 1024
#define NTOK (NB * SEQ)          // 2048
#define DEMB 1024
#define NHEAD 16
#define DH 64
#define DFF 4096
#define NVOCAB 32000
#define NLAYER 6

// -------- scratch (device globals; no allocation allowed) --------
__device__ float g_x [NTOK * DEMB];
__device__ float g_h1[NTOK * DEMB];
__device__ float g_h2[NTOK * DEMB];
__device__ float g_t [NTOK * DEMB];
// attention operands in fp16 (emitted by proj)
__device__ uint16_t g_qh [NTOK * DEMB];            // Q hi   [tok][h*64+d]
__device__ uint16_t g_ql [NTOK * DEMB];            // Q lo
__device__ uint16_t g_kh [NTOK * DEMB];            // K hi   [tok][h*64+d]
__device__ uint16_t g_vt [DEMB * NTOK];            // V hi transposed [h*64+d][tok]
// split-fp16 staging for GEMMs
__device__ uint16_t g_ah [NTOK * DEMB];            // activation hi (h2 / x)
__device__ uint16_t g_al [NTOK * DEMB];            // activation lo
__device__ uint16_t g_fh [NTOK * DFF];             // ff hi
__device__ uint16_t g_fl [NTOK * DFF];             // ff lo
__device__ uint16_t g_bth[(size_t)NVOCAB * DEMB];  // B^T hi (max 32000x1024)

// ---------------- split-fp16 helper: x = hi(fp16 RN) + lo(fp16), |lo|<=2^-12|x| ----------------
__device__ __forceinline__ void split2h(float x0, float x1, uint32_t& hi, uint32_t& lo) {
    __half h0 = __float2half_rn(x0), h1 = __float2half_rn(x1);
    float r0 = x0 - __half2float(h0);
    float r1 = x1 - __half2float(h1);
    __half l0 = __float2half_rn(r0), l1 = __float2half_rn(r1);
    hi = (uint32_t)(*(uint16_t*)&h0) | ((uint32_t)(*(uint16_t*)&h1) << 16);
    lo = (uint32_t)(*(uint16_t*)&l0) | ((uint32_t)(*(uint16_t*)&l1) << 16);
}
__device__ __forceinline__ uint32_t pack2h(float x0, float x1) {
    __half2 h = __floats2half2_rn(x0, x1);
    return *(uint32_t*)&h;
}

// fp16 MMA, fp32 acc
#define MMAF(acc, a0, a1, a2, a3, b0, b1)                                       \
    asm("mma.sync.aligned.m16n8k16.row.col.f32.f16.f16.f32 "                    \
        "{%0,%1,%2,%3}, {%4,%5,%6,%7}, {%8,%9}, {%0,%1,%2,%3};"                 \
        : "+f"((acc)[0]), "+f"((acc)[1]), "+f"((acc)[2]), "+f"((acc)[3])        \
        : "r"(a0), "r"(a1), "r"(a2), "r"(a3), "r"(b0), "r"(b1))

// warp-collective 4-matrix fragment load
#define LDMX4(r0, r1, r2, r3, addr)                                             \
    asm volatile("ldmatrix.sync.aligned.m8n8.x4.shared.b16 {%0,%1,%2,%3}, [%4];"\
        : "=r"(r0), "=r"(r1), "=r"(r2), "=r"(r3) : "r"(addr))

#define CP_ASYNC16(dst, src) \
    asm volatile("cp.async.cg.shared.global [%0], [%1], 16;" :: "r"(dst), "l"(src))
#define CP_COMMIT() asm volatile("cp.async.commit_group;")
#define CP_WAIT(n)  asm volatile("cp.async.wait_group %0;" :: "n"(n))

__device__ __forceinline__ uint32_t smem_u32(const void* p) {
    uint32_t a;
    asm("{ .reg .u64 t; cvta.to.shared.u64 t, %1; cvt.u32.u64 %0, t; }" : "=r"(a) : "l"(p));
    return a;
}

// ---------------- transpose + fp16 hi only: in[K][N] -> hiT [N][K] (u32 stores) ----------------
__global__ __launch_bounds__(256) void cvt_trans(const float* __restrict__ in,
                                                 uint16_t* __restrict__ hiT,
                                                 int K, int N) {
    __shared__ float t[32][33];
    int n0 = blockIdx.x * 32, k0 = blockIdx.y * 32;
    int tx = threadIdx.x & 31, ty = threadIdx.x >> 5;   // 32x8
#pragma unroll
    for (int i = 0; i < 32; i += 8)
        t[ty + i][tx] = in[(size_t)(k0 + ty + i) * N + n0 + tx];
    __syncthreads();
    int kp = threadIdx.x & 15;          // k-pair 0..15
    int nb = threadIdx.x >> 4;          // n 0..15
#pragma unroll
    for (int i2 = 0; i2 < 2; i2++) {
        int n = nb + 16 * i2;
        uint32_t w = pack2h(t[2 * kp][n], t[2 * kp + 1][n]);
        *(uint32_t*)(hiT + (size_t)(n0 + n) * K + k0 + 2 * kp) = w;
    }
}

// ============ 3-stage cp.async pipelined 2-pass split-fp16 HMMA GEMM (ldmatrix) ============
#define STRIDE 20                         // words per smem row (32 k + pad)
#define TILE_B (128 * STRIDE * 4)         // 10240 bytes per tile
#define BUF_B  (3 * TILE_B)               // Ah, Al, Bh = 30720 bytes
#define GEMM_SMEM (3 * BUF_B)             // 92160 (3 stages)

__global__ __launch_bounds__(256, 2) void gemm_cp(const uint16_t* __restrict__ Ahg,
                                                  const uint16_t* __restrict__ Alg,
                                                  const uint16_t* __restrict__ Bth,
                                                  const float* __restrict__ bias,
                                                  float* __restrict__ C,
                                                  uint16_t* __restrict__ Oh,
                                                  uint16_t* __restrict__ Ol,
                                                  int N, int K, int relu) {
    extern __shared__ uint32_t sh[];
    uint32_t sb = smem_u32(sh);
    int tid = threadIdx.x, wid = tid >> 5, lane = tid & 31;
    int bm = blockIdx.x * 128, bn = blockIdx.y * 128;
    int wm = (wid >> 2) * 64, wn = (wid & 3) * 32;
    int r = lane >> 2, c = lane & 3;
    int q = lane >> 3, tt = lane & 7;     // ldmatrix lane roles

    uint32_t aoff = ((uint32_t)(wm + tt + 8 * (q & 1)) * STRIDE + 4 * (q >> 1)) * 4;
    uint32_t boff = 2 * TILE_B + ((uint32_t)(wn + 8 * (q >> 1) + tt) * STRIDE + 4 * (q & 1)) * 4;

#define ISSUE(kt, buf)                                                          \
    {                                                                           \
        int k0i = (kt) << 5;                                                    \
        _Pragma("unroll")                                                       \
        for (int p = 0; p < 2; p++) {                                           \
            int idx = tid + p * 256;                                            \
            int row = idx >> 2, qq = idx & 3;                                   \
            size_t ao = (size_t)(bm + row) * K + k0i + qq * 8;                  \
            size_t bo = (size_t)(bn + row) * K + k0i + qq * 8;                  \
            uint32_t d = sb + (buf) * BUF_B + row * (STRIDE * 4) + qq * 16;     \
            CP_ASYNC16(d,              Ahg + ao);                               \
            CP_ASYNC16(d + TILE_B,     Alg + ao);                               \
            CP_ASYNC16(d + 2 * TILE_B, Bth + bo);                               \
        }                                                                       \
        CP_COMMIT();                                                            \
    }

    float acc[4][4][4] = {};

    int KT = K >> 5;
    ISSUE(0, 0);
    ISSUE(1, 1);

    int bufc = 0, bufn = 2;
    for (int kt = 0; kt < KT; kt++) {
        if (kt + 1 < KT) { CP_WAIT(1); } else { CP_WAIT(0); }
        __syncthreads();
        if (kt + 2 < KT) ISSUE(kt + 2, bufn);
        uint32_t bufb = sb + bufc * BUF_B;
        bufc = (bufc == 2) ? 0 : bufc + 1;
        bufn = (bufn == 2) ? 0 : bufn + 1;
#pragma unroll
        for (int s = 0; s < 2; s++) {
            uint32_t bh[4][2];
#pragma unroll
            for (int p = 0; p < 2; p++) {
                uint32_t addr = bufb + boff + s * 32 + p * (16 * STRIDE * 4);
                LDMX4(bh[2 * p][0], bh[2 * p][1], bh[2 * p + 1][0], bh[2 * p + 1][1], addr);
            }
#pragma unroll
            for (int i = 0; i < 4; i++) {
                uint32_t addrA = bufb + aoff + i * (16 * STRIDE * 4) + s * 32;
                uint32_t ah0, ah1, ah2, ah3, al0, al1, al2, al3;
                LDMX4(ah0, ah1, ah2, ah3, addrA);
                LDMX4(al0, al1, al2, al3, addrA + TILE_B);
#pragma unroll
                for (int j = 0; j < 4; j++) {
                    MMAF(acc[i][j], ah0, ah1, ah2, ah3, bh[j][0], bh[j][1]);   // hi*hi
                    MMAF(acc[i][j], al0, al1, al2, al3, bh[j][0], bh[j][1]);   // lo*hi
                }
            }
        }
    }

#pragma unroll
    for (int i = 0; i < 4; i++) {
#pragma unroll
        for (int j = 0; j < 4; j++) {
            int col = bn + wn + 8 * j + 2 * c;
            int row0 = bm + wm + 16 * i + r;
            float b0 = bias[col], b1 = bias[col + 1];
            float v0 = acc[i][j][0] + b0, v1 = acc[i][j][1] + b1;
            float v2 = acc[i][j][2] + b0, v3 = acc[i][j][3] + b1;
            if (relu) {
                v0 = fmaxf(v0, 0.0f); v1 = fmaxf(v1, 0.0f);
                v2 = fmaxf(v2, 0.0f); v3 = fmaxf(v3, 0.0f);
            }
            if (Oh) {
                uint32_t h0, l0, h1, l1;
                split2h(v0, v1, h0, l0);
                split2h(v2, v3, h1, l1);
                size_t o0 = (size_t)row0 * N + col;
                size_t o1 = (size_t)(row0 + 8) * N + col;
                *(uint32_t*)(Oh + o0) = h0; *(uint32_t*)(Ol + o0) = l0;
                *(uint32_t*)(Oh + o1) = h1; *(uint32_t*)(Ol + o1) = l1;
            } else {
                *(float2*)(C + (size_t)row0 * N + col) = make_float2(v0, v1);
                *(float2*)(C + (size_t)(row0 + 8) * N + col) = make_float2(v2, v3);
            }
        }
    }
}

// ============ flash attention: cp.async 3-stage K/V pipeline, 2-pass split-fp16 ============
// K tile smem [key][d-pair] stride 36 words; V tile [d][tok-pair] stride 68 words.
#define FA_KB  (128 * 36 * 4)             // 18432 B
#define FA_VB  (64 * 68 * 4)              // 17408 B
#define FA_STAGE (FA_KB + FA_VB)          // 35840 B
#define FA_SMEM_BYTES (3 * FA_STAGE)      // 107520 B
__global__ __launch_bounds__(256) void flash_attn(const uint16_t* __restrict__ Qhg,
                                                  const uint16_t* __restrict__ Qlg,
                                                  const uint16_t* __restrict__ Khg,
                                                  const uint16_t* __restrict__ Vtg,
                                                  float* __restrict__ Og, int causal) {
    extern __shared__ uint32_t sm[];
    uint32_t sb = smem_u32(sm);
    int tid = threadIdx.x, wid = tid >> 5, lane = tid & 31;
    int r = lane >> 2, c = lane & 3;
    int b = blockIdx.y >> 4, h = blockIdx.y & 15;
    int bq = b * SEQ;
    int hOff = h * DH;
    int q0 = blockIdx.x * 128;
    int grow = q0 + wid * 16 + r;

#define ISSUE_FA(kt, buf)                                                       \
    {                                                                           \
        int k0i = (kt) * 128;                                                   \
        _Pragma("unroll")                                                       \
        for (int p = 0; p < 4; p++) {                                           \
            int idx = tid + p * 256;                                            \
            int row = idx >> 3, qq = idx & 7;                                   \
            CP_ASYNC16(sb + (buf) * FA_STAGE + row * 144 + qq * 16,             \
                       Khg + (size_t)(bq + k0i + row) * DEMB + hOff + qq * 8);  \
        }                                                                       \
        _Pragma("unroll")                                                       \
        for (int p = 0; p < 4; p++) {                                           \
            int idx = tid + p * 256;                                            \
            int row = idx >> 4, qq = idx & 15;                                  \
            CP_ASYNC16(sb + (buf) * FA_STAGE + FA_KB + row * 272 + qq * 16,     \
                       Vtg + (size_t)(hOff + row) * NTOK + bq + k0i + qq * 8);  \
        }                                                                       \
        CP_COMMIT();                                                            \
    }

    // Q fragments from pre-split fp16 (NOTE: includes batch offset bq)
    uint32_t qh[4][4], ql[4][4];
#pragma unroll
    for (int s = 0; s < 4; s++) {
        const uint16_t* qp = Qhg + (size_t)(bq + grow) * DEMB + hOff + s * 16;
        const uint16_t* lp = Qlg + (size_t)(bq + grow) * DEMB + hOff + s * 16;
        qh[s][0] = *(const uint32_t*)(qp + 2 * c);
        qh[s][1] = *(const uint32_t*)(qp + 8 * DEMB + 2 * c);
        qh[s][2] = *(const uint32_t*)(qp + 2 * c + 8);
        qh[s][3] = *(const uint32_t*)(qp + 8 * DEMB + 2 * c + 8);
        ql[s][0] = *(const uint32_t*)(lp + 2 * c);
        ql[s][1] = *(const uint32_t*)(lp + 8 * DEMB + 2 * c);
        ql[s][2] = *(const uint32_t*)(lp + 2 * c + 8);
        ql[s][3] = *(const uint32_t*)(lp + 8 * DEMB + 2 * c + 8);
    }

    float oacc[8][4] = {};
    float m0 = -1e30f, m1 = -1e30f, l0 = 0.0f, l1 = 0.0f;

    ISSUE_FA(0, 0);
    ISSUE_FA(1, 1);
    int bufc = 0, bufn = 2;

    for (int kt = 0; kt < SEQ / 128; kt++) {
        int k0 = kt * 128;
        if (kt + 1 < SEQ / 128) { CP_WAIT(1); } else { CP_WAIT(0); }
        __syncthreads();
        if (kt + 2 < SEQ / 128) ISSUE_FA(kt + 2, bufn);
        uint32_t* Kh = sm + bufc * (FA_STAGE / 4);
        uint32_t* Vh = Kh + (FA_KB / 4);
        bufc = (bufc == 2) ? 0 : bufc + 1;
        bufn = (bufn == 2) ? 0 : bufn + 1;

        // ---- S = Q K^T (2-pass split-fp16) ----
        float sacc[16][4];
#pragma unroll
        for (int j = 0; j < 16; j++) { sacc[j][0] = sacc[j][1] = sacc[j][2] = sacc[j][3] = 0.0f; }
#pragma unroll
        for (int j = 0; j < 16; j++) {
#pragma unroll
            for (int s = 0; s < 4; s++) {
                int o = (8 * j + r) * 36 + 8 * s + c;
                uint32_t kh0 = Kh[o], kh1 = Kh[o + 4];
                MMAF(sacc[j], qh[s][0], qh[s][1], qh[s][2], qh[s][3], kh0, kh1);
                MMAF(sacc[j], ql[s][0], ql[s][1], ql[s][2], ql[s][3], kh0, kh1);
            }
        }
        float tm0 = -1e30f, tm1 = -1e30f;
#pragma unroll
        for (int j = 0; j < 16; j++) {
            int col = k0 + 8 * j + 2 * c;
            float v0 = sacc[j][0] * 0.125f, v1 = sacc[j][1] * 0.125f;
            float v2 = sacc[j][2] * 0.125f, v3 = sacc[j][3] * 0.125f;
            if (causal) {
                if (col     > grow)     v0 = 1e-19f;
                if (col + 1 > grow)     v1 = 1e-19f;
                if (col     > grow + 8) v2 = 1e-19f;
                if (col + 1 > grow + 8) v3 = 1e-19f;
            }
            sacc[j][0] = v0; sacc[j][1] = v1; sacc[j][2] = v2; sacc[j][3] = v3;
            tm0 = fmaxf(tm0, fmaxf(v0, v1));
            tm1 = fmaxf(tm1, fmaxf(v2, v3));
        }
        tm0 = fmaxf(tm0, __shfl_xor_sync(0xffffffffu, tm0, 1));
        tm0 = fmaxf(tm0, __shfl_xor_sync(0xffffffffu, tm0, 2));
        tm1 = fmaxf(tm1, __shfl_xor_sync(0xffffffffu, tm1, 1));
        tm1 = fmaxf(tm1, __shfl_xor_sync(0xffffffffu, tm1, 2));
        float mn0 = fmaxf(m0, tm0), mn1 = fmaxf(m1, tm1);
        float sc0 = __expf(m0 - mn0), sc1 = __expf(m1 - mn1);
        m0 = mn0; m1 = mn1;
        float rs0 = 0.0f, rs1 = 0.0f;
#pragma unroll
        for (int j = 0; j < 16; j++) {
            float p0 = __expf(sacc[j][0] - m0), p1 = __expf(sacc[j][1] - m0);
            float p2 = __expf(sacc[j][2] - m1), p3 = __expf(sacc[j][3] - m1);
            sacc[j][0] = p0; sacc[j][1] = p1; sacc[j][2] = p2; sacc[j][3] = p3;
            rs0 += p0 + p1; rs1 += p2 + p3;
        }
        rs0 += __shfl_xor_sync(0xffffffffu, rs0, 1);
        rs0 += __shfl_xor_sync(0xffffffffu, rs0, 2);
        rs1 += __shfl_xor_sync(0xffffffffu, rs1, 1);
        rs1 += __shfl_xor_sync(0xffffffffu, rs1, 2);
        l0 = l0 * sc0 + rs0; l1 = l1 * sc1 + rs1;
#pragma unroll
        for (int j2 = 0; j2 < 8; j2++) {
            oacc[j2][0] *= sc0; oacc[j2][1] *= sc0;
            oacc[j2][2] *= sc1; oacc[j2][3] *= sc1;
        }
        // ---- O += P V (2-pass split-fp16); P frags are thread-local repacks ----
#pragma unroll
        for (int s2 = 0; s2 < 8; s2++) {
            uint32_t a0h, a0l, a1h, a1l, a2h, a2l, a3h, a3l;
            split2h(sacc[2 * s2][0],     sacc[2 * s2][1],     a0h, a0l);
            split2h(sacc[2 * s2][2],     sacc[2 * s2][3],     a1h, a1l);
            split2h(sacc[2 * s2 + 1][0], sacc[2 * s2 + 1][1], a2h, a2l);
            split2h(sacc[2 * s2 + 1][2], sacc[2 * s2 + 1][3], a3h, a3l);
#pragma unroll
            for (int j2 = 0; j2 < 8; j2++) {
                int o = (8 * j2 + r) * 68 + 8 * s2 + c;
                uint32_t vh0 = Vh[o], vh1 = Vh[o + 4];
                MMAF(oacc[j2], a0h, a1h, a2h, a3h, vh0, vh1);
                MMAF(oacc[j2], a0l, a1l, a2l, a3l, vh0, vh1);
            }
        }
    }
    float i0 = 1.0f / l0, i1 = 1.0f / l1;
#pragma unroll
    for (int j2 = 0; j2 < 8; j2++) {
        float* op = Og + (size_t)(bq + grow) * DEMB + hOff + 8 * j2 + 2 * c;
        *(float2*)op = make_float2(oacc[j2][0] * i0, oacc[j2][1] * i0);
        *(float2*)(op + 8 * DEMB) = make_float2(oacc[j2][2] * i1, oacc[j2][3] * i1);
    }
}

// ---------------- embedding + positional encoding ----------------
__global__ __launch_bounds__(256) void embed_kernel(const int* __restrict__ ids,
                                                    const float* __restrict__ emb,
                                                    float* __restrict__ X) {
    int t = blockIdx.x;
    int pos = t & (SEQ - 1);
    int id = ids[t];
    int d0 = threadIdx.x * 4;
    float4 e4 = *(const float4*)(emb + (size_t)id * DEMB + d0);
    float ev[4] = {e4.x, e4.y, e4.z, e4.w};
    float ov[4];
#pragma unroll
    for (int j = 0; j < 4; j++) {
        int d = d0 + j;
        float ang = (float)pos * powf(10000.0f, -2.0f * (float)d / (float)DEMB);
        float pe = ((d & 1) == 0) ? sinf(ang) : cosf(ang);
        ov[j] = ev[j] * 32.0f + pe;
    }
    *(float4*)(X + (size_t)t * DEMB + d0) = make_float4(ov[0], ov[1], ov[2], ov[3]);
}

// -------- fused q/k/v per-head projection: 128 tokens x 1 head per block, fp16 outputs --------
// z=0: Q -> split hi/lo [tok][hd]; z=1: K -> hi [tok][hd]; z=2: V -> hi transposed [hd][tok]
__global__ __launch_bounds__(256) void proj_head3(
        const float* __restrict__ X0, const float* __restrict__ X1, const float* __restrict__ X2,
        const float* __restrict__ W0, const float* __restrict__ W1, const float* __restrict__ W2,
        uint16_t* __restrict__ Qh, uint16_t* __restrict__ Ql,
        uint16_t* __restrict__ Kho, uint16_t* __restrict__ Vt) {
    const float* X; const float* W;
    if (blockIdx.z == 0)      { X = X0; W = W0; }
    else if (blockIdx.z == 1) { X = X1; W = W1; }
    else                      { X = X2; W = W2; }
    __shared__ float Xs[64][132];
    __shared__ float Ws[64][64];
    int tid = threadIdx.x;
    int h = blockIdx.y;
    int t0 = blockIdx.x * 128;
#pragma unroll
    for (int r2 = 0; r2 < 4; r2++) {
        int idx = tid + r2 * 256;
        int a = idx >> 4;
        int c4 = (idx & 15) << 2;
        *(float4*)&Ws[a][c4] = *(const float4*)(W + a * DH + c4);
    }
#pragma unroll
    for (int r2 = 0; r2 < 8; r2++) {
        int idx = tid + r2 * 256;
        int a = idx >> 4;
        int c4 = (idx & 15) << 2;
        float4 xv = *(const float4*)(X + (size_t)(t0 + a) * DEMB + h * DH + c4);
        Xs[c4 + 0][a] = xv.x; Xs[c4 + 1][a] = xv.y; Xs[c4 + 2][a] = xv.z; Xs[c4 + 3][a] = xv.w;
    }
    __syncthreads();
    int tx = tid & 15, ty = tid >> 4;
    float acc[8][4] = {};
#pragma unroll
    for (int d = 0; d < 64; d++) {
        float4 w4 = *(float4*)&Ws[d][tx * 4];
        float4 a0 = *(float4*)&Xs[d][ty * 8];
        float4 a1 = *(float4*)&Xs[d][ty * 8 + 4];
        float av[8] = {a0.x, a0.y, a0.z, a0.w, a1.x, a1.y, a1.z, a1.w};
        float wv[4] = {w4.x, w4.y, w4.z, w4.w};
#pragma unroll
        for (int i = 0; i < 8; i++)
#pragma unroll
            for (int j = 0; j < 4; j++) acc[i][j] = fmaf(av[i], wv[j], acc[i][j]);
    }
    int tokb = t0 + ty * 8;
    if (blockIdx.z == 0) {
#pragma unroll
        for (int i = 0; i < 8; i++) {
            uint32_t h0, lo0, h1, lo1;
            split2h(acc[i][0], acc[i][1], h0, lo0);
            split2h(acc[i][2], acc[i][3], h1, lo1);
            size_t base = (size_t)(tokb + i) * DEMB + h * DH + tx * 4;
            *(uint32_t*)(Qh + base) = h0; *(uint32_t*)(Qh + base + 2) = h1;
            *(uint32_t*)(Ql + base) = lo0; *(uint32_t*)(Ql + base + 2) = lo1;
        }
    } else if (blockIdx.z == 1) {
#pragma unroll
        for (int i = 0; i < 8; i++) {
            size_t base = (size_t)(tokb + i) * DEMB + h * DH + tx * 4;
            *(uint32_t*)(Kho + base) = pack2h(acc[i][0], acc[i][1]);
            *(uint32_t*)(Kho + base + 2) = pack2h(acc[i][2], acc[i][3]);
        }
    } else {
#pragma unroll
        for (int j = 0; j < 4; j++) {
            uint4 w;
            w.x = pack2h(acc[0][j], acc[1][j]);
            w.y = pack2h(acc[2][j], acc[3][j]);
            w.z = pack2h(acc[4][j], acc[5][j]);
            w.w = pack2h(acc[6][j], acc[7][j]);
            *(uint4*)(Vt + (size_t)(h * DH + tx * 4 + j) * NTOK + tokb) = w;
        }
    }
}

// ---------------- residual add + layernorm (+ optional split-fp16 emit) ----------------
__global__ __launch_bounds__(256) void add_ln(const float* __restrict__ A, const float* __restrict__ B,
                                              const float* __restrict__ g, const float* __restrict__ be,
                                              float* __restrict__ O,
                                              uint16_t* __restrict__ Oh, uint16_t* __restrict__ Ol) {
    int lane = threadIdx.x & 31, wid = threadIdx.x >> 5;
    int row = blockIdx.x * 8 + wid;
    size_t base = (size_t)row * DEMB;
    float4 v[8];
    float s1 = 0.0f, s2 = 0.0f;
#pragma unroll
    for (int p = 0; p < 8; p++) {
        float4 a = ((const float4*)(A + base))[lane + p * 32];
        float4 b = ((const float4*)(B + base))[lane + p * 32];
        float4 t = make_float4(a.x + b.x, a.y + b.y, a.z + b.z, a.w + b.w);
        v[p] = t;
        s1 += t.x + t.y + t.z + t.w;
        s2 += t.x * t.x + t.y * t.y + t.z * t.z + t.w * t.w;
    }
#pragma unroll
    for (int o = 16; o; o >>= 1) {
        s1 += __shfl_xor_sync(0xffffffffu, s1, o);
        s2 += __shfl_xor_sync(0xffffffffu, s2, o);
    }
    float mu = s1 * (1.0f / DEMB);
    float var = s2 * (1.0f / DEMB) - mu * mu;
    float w = rsqrtf(var + 1e-5f);
#pragma unroll
    for (int p = 0; p < 8; p++) {
        float4 gg = ((const float4*)g)[lane + p * 32];
        float4 bb = ((const float4*)be)[lane + p * 32];
        float4 t = v[p];
        float4 o;
        o.x = (t.x - mu) * w * gg.x + bb.x;
        o.y = (t.y - mu) * w * gg.y + bb.y;
        o.z = (t.z - mu) * w * gg.z + bb.z;
        o.w = (t.w - mu) * w * gg.w + bb.w;
        ((float4*)(O + base))[lane + p * 32] = o;
        if (Oh) {
            uint32_t h0, l0, h1, l1;
            split2h(o.x, o.y, h0, l0);
            split2h(o.z, o.w, h1, l1);
            size_t idx = base + (size_t)(lane + p * 32) * 4;
            *(uint32_t*)(Oh + idx) = h0; *(uint32_t*)(Oh + idx + 2) = h1;
            *(uint32_t*)(Ol + idx) = l0; *(uint32_t*)(Ol + idx + 2) = l1;
        }
    }
}

// ---------------- host orchestration ----------------
extern "C" void kernel_launch(void* const* d_in, const int* in_sizes, int n_in,
                              void* d_out, int out_size) {
    const int*   ids   = (const int*)  d_in[0];
    const float* enc_k = (const float*)d_in[1];
    const float* enc_v = (const float*)d_in[2];
    const float* emb   = (const float*)d_in[3];
    const float* Wq_m  = (const float*)d_in[4];
    const float* Wk_m  = (const float*)d_in[5];
    const float* Wv_m  = (const float*)d_in[6];
    const float* Wq_c  = (const float*)d_in[7];
    const float* Wk_c  = (const float*)d_in[8];
    const float* Wv_c  = (const float*)d_in[9];
    const float* ln1_g = (const float*)d_in[10];
    const float* ln1_b = (const float*)d_in[11];
    const float* ln2_g = (const float*)d_in[12];
    const float* ln2_b = (const float*)d_in[13];
    const float* ln3_g = (const float*)d_in[14];
    const float* ln3_b = (const float*)d_in[15];
    const float* W1    = (const float*)d_in[16];
    const float* b1    = (const float*)d_in[17];
    const float* W2    = (const float*)d_in[18];
    const float* b2    = (const float*)d_in[19];
    const float* Wout  = (const float*)d_in[20];
    const float* bout  = (const float*)d_in[21];
    float* out = (float*)d_out;

    float *x, *h1, *h2, *t;
    uint16_t *qh, *ql, *khg, *vtg, *ah, *al, *fh, *fl, *bth;
    cudaGetSymbolAddress((void**)&x,  g_x);
    cudaGetSymbolAddress((void**)&h1, g_h1);
    cudaGetSymbolAddress((void**)&h2, g_h2);
    cudaGetSymbolAddress((void**)&t,  g_t);
    cudaGetSymbolAddress((void**)&qh,  g_qh);
    cudaGetSymbolAddress((void**)&ql,  g_ql);
    cudaGetSymbolAddress((void**)&khg, g_kh);
    cudaGetSymbolAddress((void**)&vtg, g_vt);
    cudaGetSymbolAddress((void**)&ah,  g_ah);
    cudaGetSymbolAddress((void**)&al,  g_al);
    cudaGetSymbolAddress((void**)&fh,  g_fh);
    cudaGetSymbolAddress((void**)&fl,  g_fl);
    cudaGetSymbolAddress((void**)&bth, g_bth);

    cudaFuncSetAttribute(flash_attn, cudaFuncAttributeMaxDynamicSharedMemorySize, FA_SMEM_BYTES);
    cudaFuncSetAttribute(gemm_cp,   cudaFuncAttributeMaxDynamicSharedMemorySize, GEMM_SMEM);

    dim3 blk(256);
    dim3 projGrid(NTOK / 128, NHEAD, 3);
    dim3 faGrid(SEQ / 128, NB * NHEAD);
    dim3 tblk(256);

    embed_kernel<<<NTOK, blk>>>(ids, emb, x);

    for (int l = 0; l < NLAYER; l++) {
        size_t wOff  = (size_t)l * DH * DH;
        size_t lnOff = (size_t)l * DEMB;
        // --- masked self-attention ---
        proj_head3<<<projGrid, blk>>>(x, x, x, Wq_m + wOff, Wk_m + wOff, Wv_m + wOff,
                                      qh, ql, khg, vtg);
        flash_attn<<<faGrid, blk, FA_SMEM_BYTES>>>(qh, ql, khg, vtg, t, 1);
        add_ln<<<NTOK / 8, blk>>>(t, x, ln1_g + lnOff, ln1_b + lnOff, h1,
                                  (uint16_t*)nullptr, (uint16_t*)nullptr);
        // --- cross-attention ---
        proj_head3<<<projGrid, blk>>>(h1, enc_k, enc_v, Wq_c + wOff, Wk_c + wOff, Wv_c + wOff,
                                      qh, ql, khg, vtg);
        flash_attn<<<faGrid, blk, FA_SMEM_BYTES>>>(qh, ql, khg, vtg, t, 0);
        add_ln<<<NTOK / 8, blk>>>(t, h1, ln2_g + lnOff, ln2_b + lnOff, h2, ah, al);   // emit h2 split
        // --- FFN (2-pass cp.async split-fp16 HMMA, 3-stage pipeline) ---
        cvt_trans<<<dim3(DFF / 32, DEMB / 32), tblk>>>(W1 + (size_t)l * DEMB * DFF, bth, DEMB, DFF);
        gemm_cp<<<dim3(NTOK / 128, DFF / 128), blk, GEMM_SMEM>>>(
            ah, al, bth, b1 + (size_t)l * DFF, (float*)nullptr, fh, fl, DFF, DEMB, 1); // ff -> split
        cvt_trans<<<dim3(DEMB / 32, DFF / 32), tblk>>>(W2 + (size_t)l * DFF * DEMB, bth, DFF, DEMB);
        gemm_cp<<<dim3(NTOK / 128, DEMB / 128), blk, GEMM_SMEM>>>(
            fh, fl, bth, b2 + lnOff, t, (uint16_t*)nullptr, (uint16_t*)nullptr, DEMB, DFF, 0);
        add_ln<<<NTOK / 8, blk>>>(t, h2, ln3_g + lnOff, ln3_b + lnOff, x, ah, al);    // emit x split
    }

    // --- vocab projection (x split already emitted by last add_ln) ---
    cvt_trans<<<dim3(NVOCAB / 32, DEMB / 32), tblk>>>(Wout, bth, DEMB, NVOCAB);
    gemm_cp<<<dim3(NTOK / 128, NVOCAB / 128), blk, GEMM_SMEM>>>(
        ah, al, bth, bout, out, (uint16_t*)nullptr, (uint16_t*)nullptr, NVOCAB, DEMB, 0);
}